// round 11
// baseline (speedup 1.0000x reference)
#include <cuda_runtime.h>
#include <math.h>
#include <stdint.h>

#define QLEN 512
#define BATCH 4
#define DMODEL 1024
#define NLAYER 4
#define NHEAD 16
#define DHEAD 64
#define DINNER 4096
#define MLEN 512
#define KLEN 1024
#define BH (BATCH*NHEAD)

// ---------------- scratch ----------------
__device__ float g_cat[(size_t)KLEN*BATCH*DMODEL];
__device__ float g_heads[(size_t)KLEN*BATCH*3*DMODEL];
__device__ float g_r[(size_t)KLEN*DMODEL];
__device__ float g_ac[(size_t)BH*QLEN*KLEN];
__device__ float g_bd[(size_t)BH*QLEN*KLEN];
__device__ float g_av[(size_t)QLEN*BATCH*DMODEL];
__device__ float g_tmp[(size_t)QLEN*BATCH*DMODEL];
__device__ float g_tmp2[(size_t)QLEN*BATCH*DMODEL];
__device__ float g_h[(size_t)QLEN*BATCH*DMODEL];
__device__ float g_ff[(size_t)QLEN*BATCH*DINNER];
__device__ float g_qu[(size_t)BH*QLEN*DHEAD];
__device__ float g_qv[(size_t)BH*QLEN*DHEAD];
__device__ float g_kc[(size_t)BH*KLEN*DHEAD];
__device__ float g_vc[(size_t)BH*KLEN*DHEAD];
__device__ float g_rkc[(size_t)NHEAD*KLEN*DHEAD];
// tf32-rounded weight copies
__device__ float g_wqkv[(size_t)NLAYER*DMODEL*3072];
__device__ float g_wr[(size_t)NLAYER*DMODEL*DMODEL];
__device__ float g_wo[(size_t)NLAYER*DMODEL*DMODEL];
__device__ float g_w1[(size_t)NLAYER*DMODEL*DINNER];
__device__ float g_w2[(size_t)NLAYER*DINNER*DMODEL];

__device__ __forceinline__ uint32_t f2tf32(float f) {
    uint32_t o;
    asm("cvt.rna.tf32.f32 %0, %1;" : "=r"(o) : "f"(f));
    return o;
}
__device__ __forceinline__ float f2tf32f(float f) {
    uint32_t o = f2tf32(f);
    return __uint_as_float(o);
}

#define MMA_TF32(d, a, b) \
    asm volatile("mma.sync.aligned.m16n8k8.row.col.f32.tf32.tf32.f32 " \
                 "{%0,%1,%2,%3}, {%4,%5,%6,%7}, {%8,%9}, {%0,%1,%2,%3};" \
                 : "+f"(d[0]), "+f"(d[1]), "+f"(d[2]), "+f"(d[3]) \
                 : "r"(a.x), "r"(a.y), "r"(a.z), "r"(a.w), "r"(b.x), "r"(b.y))

__device__ __forceinline__ void cpasync16(uint32_t dst, const void* src) {
    asm volatile("cp.async.cg.shared.global [%0], [%1], 16;" :: "r"(dst), "l"(src));
}
#define CP_COMMIT() asm volatile("cp.async.commit_group;" ::: "memory")
__device__ __forceinline__ uint32_t smem_u32(const void* p) {
    uint32_t a;
    asm("{ .reg .u64 t; cvta.to.shared.u64 t, %1; cvt.u32.u64 %0, t; }" : "=r"(a) : "l"(p));
    return a;
}
#define SW128B(o) ((o) ^ (((o) >> 3) & 0x70))

// gemm4: 3 stages x (A 4096 + B 4096) words
#define G4_STAGE_W 8192
#define G4_SMEM (3 * G4_STAGE_W * 4)

// ======== gemm4: C[M,N]=A[M,K]@B[K,N]. 128 thr, CTA 128x128, warp 64x64 ========
template<int RELU, int HASBIAS, int CVT>
__global__ void __launch_bounds__(128) gemm4(
    const float* __restrict__ A, const float* __restrict__ B,
    const float* __restrict__ bias, float* __restrict__ C0, float* __restrict__ C1,
    int K, int lda, int ldb, int ldc)
{
    extern __shared__ uint32_t dsm[];
    const uint32_t sbase = smem_u32(dsm);
    const int tid = threadIdx.x, lane = tid & 31;
    const int warp = tid >> 5, wm = warp >> 1, wn = warp & 1;
    const int bx = blockIdx.x, by = blockIdx.y, bz = blockIdx.z;

    const int koff = bz * K;
    float* C = bz ? C1 : C0;

    const int a_row0 = tid >> 3, a_ch = tid & 7;
    const float* Ag = A + (size_t)(by * 128 + a_row0) * lda + koff + a_ch * 4;
    const int b_k = tid >> 2, b_nch0 = tid & 3;
    const float* Bg = B + (size_t)(koff + b_k) * ldb + bx * 128 + b_nch0 * 4;

    float acc[4][8][4];
#pragma unroll
    for (int mi = 0; mi < 4; mi++)
#pragma unroll
        for (int ni = 0; ni < 8; ni++)
#pragma unroll
            for (int r = 0; r < 4; r++) acc[mi][ni][r] = 0.f;

    const int lr = lane >> 2, lc = lane & 3;
    const int niter = K >> 5;

#define G4_LOAD(stg, k0) do { \
    uint32_t ab_ = sbase + (stg) * (G4_STAGE_W * 4); \
    _Pragma("unroll") for (int i = 0; i < 8; i++) { \
        uint32_t so_ = SW128B((uint32_t)((a_row0 + 16 * i) * 128 + a_ch * 16)); \
        cpasync16(ab_ + so_, Ag + (size_t)(16 * i) * lda + (k0)); \
    } \
    uint32_t bb_ = ab_ + 4096 * 4; \
    _Pragma("unroll") for (int i = 0; i < 8; i++) { \
        int n_ = (b_nch0 + 4 * i) * 4; \
        uint32_t w_ = (uint32_t)(b_k * 128 + (n_ ^ ((b_k & 3) << 3))); \
        cpasync16(bb_ + w_ * 4, Bg + (size_t)(k0) * ldb + 16 * i); \
    } \
    CP_COMMIT(); \
} while (0)

    G4_LOAD(0, 0);
    if (niter > 1) G4_LOAD(1, 32);

    for (int it = 0; it < niter; it++) {
        if (it + 1 < niter) {
            asm volatile("cp.async.wait_group 1;" ::: "memory");
        } else {
            asm volatile("cp.async.wait_group 0;" ::: "memory");
        }
        __syncthreads();
        if (it + 2 < niter) G4_LOAD((it + 2) % 3, (it + 2) * 32);

        const uint32_t* Abuf = dsm + (it % 3) * G4_STAGE_W;
        const uint32_t* Bbuf = Abuf + 4096;
#pragma unroll
        for (int kk = 0; kk < 4; kk++) {
            uint4 af[4]; uint2 bf[8];
#pragma unroll
            for (int mi = 0; mi < 4; mi++) {
                int row = wm * 64 + mi * 16 + lr;
                int k = kk * 8 + lc;
                af[mi].x = Abuf[SW128B((uint32_t)(row * 128 + k * 4)) >> 2];
                af[mi].y = Abuf[SW128B((uint32_t)((row + 8) * 128 + k * 4)) >> 2];
                af[mi].z = Abuf[SW128B((uint32_t)(row * 128 + (k + 4) * 4)) >> 2];
                af[mi].w = Abuf[SW128B((uint32_t)((row + 8) * 128 + (k + 4) * 4)) >> 2];
            }
#pragma unroll
            for (int ni = 0; ni < 8; ni++) {
                int n = wn * 64 + ni * 8 + lr;
                int kb = kk * 8 + lc;
                int nsw = n ^ (lc << 3);
                bf[ni].x = Bbuf[kb * 128 + nsw];
                bf[ni].y = Bbuf[(kb + 4) * 128 + nsw];
            }
#pragma unroll
            for (int mi = 0; mi < 4; mi++)
#pragma unroll
                for (int ni = 0; ni < 8; ni++) MMA_TF32(acc[mi][ni], af[mi], bf[ni]);
        }
    }
#undef G4_LOAD

    const bool dobias = HASBIAS && (bz == 0);
#pragma unroll
    for (int mi = 0; mi < 4; mi++) {
#pragma unroll
        for (int ni = 0; ni < 8; ni++) {
            int row0 = by * 128 + wm * 64 + mi * 16 + lr;
            int col  = bx * 128 + wn * 64 + ni * 8 + lc * 2;
            float b0 = 0.f, b1 = 0.f;
            if (dobias) { b0 = bias[col]; b1 = bias[col + 1]; }
            float v0 = acc[mi][ni][0] + b0, v1 = acc[mi][ni][1] + b1;
            float v2 = acc[mi][ni][2] + b0, v3 = acc[mi][ni][3] + b1;
            if (RELU) {
                v0 = fmaxf(v0, 0.f); v1 = fmaxf(v1, 0.f);
                v2 = fmaxf(v2, 0.f); v3 = fmaxf(v3, 0.f);
            }
            if (CVT) {
                v0 = f2tf32f(v0); v1 = f2tf32f(v1);
                v2 = f2tf32f(v2); v3 = f2tf32f(v3);
            }
            *(float2*)(C + (size_t)row0 * ldc + col)       = make_float2(v0, v1);
            *(float2*)(C + (size_t)(row0 + 8) * ldc + col) = make_float2(v2, v3);
        }
    }
}

// ======== score2: out[bh,i,j] = sum_d A[i][d]*B[j][d] ========
#define SC_SMEM (4 * 4096 * 4)
template<int MODE>
__global__ void __launch_bounds__(128) score2(
    const float* __restrict__ Qb, const float* __restrict__ Kb,
    float* __restrict__ out)
{
    const int bx = blockIdx.x, by = blockIdx.y, bh = blockIdx.z;
    const int i0 = by * 128, j0 = bx * 128;
    if (MODE == 0) { if (j0 >= i0 + 640) return; }
    else           { if (i0 + j0 < 257) return; }
    const float* A = Qb + (size_t)bh * QLEN * 64 + (size_t)i0 * 64;
    const float* B = Kb + (size_t)(MODE ? (bh & 15) : bh) * KLEN * 64 + (size_t)j0 * 64;

    extern __shared__ uint32_t dsm[];
    const uint32_t sbase = smem_u32(dsm);
    const int tid = threadIdx.x, lane = tid & 31;
    const int warp = tid >> 5, wm = warp >> 1, wn = warp & 1;

    const int a_row0 = tid >> 3, a_ch = tid & 7;
    const float* Ag = A + (size_t)a_row0 * 64 + a_ch * 4;
    const float* Bg = B + (size_t)a_row0 * 64 + a_ch * 4;

    float acc[4][8][4];
#pragma unroll
    for (int mi = 0; mi < 4; mi++)
#pragma unroll
        for (int ni = 0; ni < 8; ni++)
#pragma unroll
            for (int r = 0; r < 4; r++) acc[mi][ni][r] = 0.f;

    const int lr = lane >> 2, lc = lane & 3;

#define SC_LOAD(stg, k0) do { \
    uint32_t ab_ = sbase + (stg) * 32768; \
    uint32_t bb_ = ab_ + 16384; \
    _Pragma("unroll") for (int i = 0; i < 8; i++) { \
        uint32_t so_ = SW128B((uint32_t)((a_row0 + 16 * i) * 128 + a_ch * 16)); \
        cpasync16(ab_ + so_, Ag + (size_t)(16 * i) * 64 + (k0)); \
        cpasync16(bb_ + so_, Bg + (size_t)(16 * i) * 64 + (k0)); \
    } \
    CP_COMMIT(); \
} while (0)

    SC_LOAD(0, 0);
    SC_LOAD(1, 32);

#pragma unroll
    for (int it = 0; it < 2; it++) {
        if (it == 0) asm volatile("cp.async.wait_group 1;" ::: "memory");
        else         asm volatile("cp.async.wait_group 0;" ::: "memory");
        __syncthreads();
        const uint32_t* Abuf = dsm + it * 8192;
        const uint32_t* Bbuf = Abuf + 4096;
#pragma unroll
        for (int kk = 0; kk < 4; kk++) {
            uint4 af[4]; uint2 bf[8];
#pragma unroll
            for (int mi = 0; mi < 4; mi++) {
                int row = wm * 64 + mi * 16 + lr;
                int k = kk * 8 + lc;
                af[mi].x = Abuf[SW128B((uint32_t)(row * 128 + k * 4)) >> 2];
                af[mi].y = Abuf[SW128B((uint32_t)((row + 8) * 128 + k * 4)) >> 2];
                af[mi].z = Abuf[SW128B((uint32_t)(row * 128 + (k + 4) * 4)) >> 2];
                af[mi].w = Abuf[SW128B((uint32_t)((row + 8) * 128 + (k + 4) * 4)) >> 2];
            }
#pragma unroll
            for (int ni = 0; ni < 8; ni++) {
                int n = wn * 64 + ni * 8 + lr;
                int k = kk * 8 + lc;
                bf[ni].x = Bbuf[SW128B((uint32_t)(n * 128 + k * 4)) >> 2];
                bf[ni].y = Bbuf[SW128B((uint32_t)(n * 128 + (k + 4) * 4)) >> 2];
            }
#pragma unroll
            for (int mi = 0; mi < 4; mi++)
#pragma unroll
                for (int ni = 0; ni < 8; ni++) MMA_TF32(acc[mi][ni], af[mi], bf[ni]);
        }
    }
#undef SC_LOAD

    float* ob = out + (size_t)bh * QLEN * KLEN;
#pragma unroll
    for (int mi = 0; mi < 4; mi++)
#pragma unroll
        for (int ni = 0; ni < 8; ni++) {
            int row0 = i0 + wm * 64 + mi * 16 + lr;
            int col  = j0 + wn * 64 + ni * 8 + lc * 2;
            *(float2*)(ob + (size_t)row0 * KLEN + col) =
                make_float2(acc[mi][ni][0], acc[mi][ni][1]);
            *(float2*)(ob + (size_t)(row0 + 8) * KLEN + col) =
                make_float2(acc[mi][ni][2], acc[mi][ni][3]);
        }
}

// ======== flash_av: fused shift+mask+softmax(no-max)+P@V ========
// per (128-query block, bh). p computed in registers directly in A-fragment layout.
#define FV_STAGE_W 2048
#define FV_SMEM (3 * FV_STAGE_W * 4)
__global__ void __launch_bounds__(128) flash_av(
    const float* __restrict__ ac, const float* __restrict__ bd,
    const float* __restrict__ V, float* __restrict__ av)
{
    extern __shared__ uint32_t dsm[];
    const uint32_t sbase = smem_u32(dsm);
    const int iblk = blockIdx.x, bh = blockIdx.y;
    const int b = bh >> 4, n_h = bh & 15;
    const float* acb = ac + (size_t)bh * QLEN * KLEN + (size_t)iblk * 128 * KLEN;
    const float* bdb = bd + (size_t)bh * QLEN * KLEN + (size_t)iblk * 128 * KLEN;
    const float* Vb = V + (size_t)bh * KLEN * 64;
    const int kmax = min(KLEN, iblk * 128 + 640);
    const int niter = kmax >> 5;

    const int tid = threadIdx.x, lane = tid & 31;
    const int warp = tid >> 5, wm = warp >> 1, wn = warp & 1;
    const int lr = lane >> 2, lc = lane & 3;

    // V cp.async mapping (32 k-rows x 64 n per stage)
    const int b_k = tid >> 2, b_nch0 = tid & 3;
    const float* Bg = Vb + (size_t)b_k * 64 + b_nch0 * 4;

#define FV_LOAD(stg, k0) do { \
    uint32_t bb_ = sbase + (stg) * (FV_STAGE_W * 4); \
    _Pragma("unroll") for (int i = 0; i < 4; i++) { \
        int n_ = (b_nch0 + 4 * i) * 4; \
        uint32_t w_ = (uint32_t)(b_k * 64 + (n_ ^ ((b_k & 3) << 3))); \
        cpasync16(bb_ + w_ * 4, Bg + (size_t)(k0) * 64 + 16 * i); \
    } \
    CP_COMMIT(); \
} while (0)

    float acc[4][4][4];
#pragma unroll
    for (int mi = 0; mi < 4; mi++)
#pragma unroll
        for (int ni = 0; ni < 4; ni++)
#pragma unroll
            for (int r = 0; r < 4; r++) acc[mi][ni][r] = 0.f;
    float lsum[4][2];
#pragma unroll
    for (int mi = 0; mi < 4; mi++) { lsum[mi][0] = 0.f; lsum[mi][1] = 0.f; }

    // per-(mi,h) row constants
    int rloc[4][2], jmaxr[4][2], shiftr[4][2];
#pragma unroll
    for (int mi = 0; mi < 4; mi++)
#pragma unroll
        for (int h = 0; h < 2; h++) {
            int rl = wm * 64 + mi * 16 + lr + 8 * h;
            int ig = iblk * 128 + rl;
            rloc[mi][h] = rl;
            jmaxr[mi][h] = ig + 512;        // inclusive
            shiftr[mi][h] = 511 - ig;
        }

    FV_LOAD(0, 0);
    if (niter > 1) FV_LOAD(1, 32);

    for (int it = 0; it < niter; it++) {
        if (it + 1 < niter) {
            asm volatile("cp.async.wait_group 1;" ::: "memory");
        } else {
            asm volatile("cp.async.wait_group 0;" ::: "memory");
        }
        __syncthreads();
        if (it + 2 < niter) FV_LOAD((it + 2) % 3, (it + 2) * 32);

        const uint32_t* Bbuf = dsm + (it % 3) * FV_STAGE_W;
        const int jb = it * 32;
#pragma unroll
        for (int kk = 0; kk < 4; kk++) {
            const int j1 = jb + kk * 8 + lc;
            const int j2 = j1 + 4;
            uint4 af[4];
#pragma unroll
            for (int mi = 0; mi < 4; mi++) {
                float p[2][2];   // [h][jpair]
#pragma unroll
                for (int h = 0; h < 2; h++) {
                    const float* acr = acb + (size_t)rloc[mi][h] * KLEN;
                    const float* bdr = bdb + (size_t)rloc[mi][h] * KLEN;
                    int m1 = j1 + shiftr[mi][h]; if (m1 > 1023) m1 = 1023;
                    int m2 = j2 + shiftr[mi][h]; if (m2 > 1023) m2 = 1023;
                    float s1 = 0.125f * (acr[j1] + bdr[m1]);
                    float s2 = 0.125f * (acr[j2] + bdr[m2]);
                    p[h][0] = (j1 <= jmaxr[mi][h]) ? __expf(s1) : 0.f;
                    p[h][1] = (j2 <= jmaxr[mi][h]) ? __expf(s2) : 0.f;
                    lsum[mi][h] += p[h][0] + p[h][1];
                }
                af[mi].x = f2tf32(p[0][0]);
                af[mi].y = f2tf32(p[1][0]);
                af[mi].z = f2tf32(p[0][1]);
                af[mi].w = f2tf32(p[1][1]);
            }
            uint2 bf[4];
#pragma unroll
            for (int ni = 0; ni < 4; ni++) {
                int n = wn * 32 + ni * 8 + lr;
                int kb = kk * 8 + lc;
                int nsw = n ^ (lc << 3);
                bf[ni].x = Bbuf[kb * 64 + nsw];
                bf[ni].y = Bbuf[(kb + 4) * 64 + nsw];
            }
#pragma unroll
            for (int mi = 0; mi < 4; mi++)
#pragma unroll
                for (int ni = 0; ni < 4; ni++) MMA_TF32(acc[mi][ni], af[mi], bf[ni]);
        }
    }
#undef FV_LOAD

    // reduce row sums across the 4 quad lanes (lc), then scale+store
    float inv[4][2];
#pragma unroll
    for (int mi = 0; mi < 4; mi++)
#pragma unroll
        for (int h = 0; h < 2; h++) {
            float l = lsum[mi][h];
            l += __shfl_xor_sync(0xFFFFFFFF, l, 1);
            l += __shfl_xor_sync(0xFFFFFFFF, l, 2);
            inv[mi][h] = 1.0f / l;
        }

#pragma unroll
    for (int mi = 0; mi < 4; mi++)
#pragma unroll
        for (int ni = 0; ni < 4; ni++) {
            int row0 = iblk * 128 + wm * 64 + mi * 16 + lr;
            int col  = wn * 32 + ni * 8 + lc * 2;
            *(float2*)(av + ((size_t)row0 * 4 + b) * 1024 + n_h * 64 + col) =
                make_float2(f2tf32f(acc[mi][ni][0] * inv[mi][0]),
                            f2tf32f(acc[mi][ni][1] * inv[mi][0]));
            *(float2*)(av + ((size_t)(row0 + 8) * 4 + b) * 1024 + n_h * 64 + col) =
                make_float2(f2tf32f(acc[mi][ni][2] * inv[mi][1]),
                            f2tf32f(acc[mi][ni][3] * inv[mi][1]));
        }
}

// ---------------- weight rounding ----------------
__global__ void roundw_kernel(float4* __restrict__ dst, const float4* __restrict__ src) {
    size_t i = (size_t)blockIdx.x * 256 + threadIdx.x;
    float4 v = src[i];
    dst[i] = make_float4(f2tf32f(v.x), f2tf32f(v.y), f2tf32f(v.z), f2tf32f(v.w));
}

// ---------------- small kernels ----------------
__global__ void posemb_kernel(float* __restrict__ r) {
    int idx = blockIdx.x * 256 + threadIdx.x;
    int k = idx >> 10, d = idx & 1023;
    float pos = (float)(KLEN - 1 - k);
    int j = (d < 512) ? d : d - 512;
    float inv = expf(-((float)(2 * j) / 1024.0f) * 9.210340371976184f);
    float ang = pos * inv;
    r[idx] = f2tf32f((d < 512) ? sinf(ang) : cosf(ang));
}

__global__ void copy4_kernel(float4* __restrict__ dst, const float4* __restrict__ src) {
    size_t i = (size_t)blockIdx.x * 256 + threadIdx.x;
    dst[i] = src[i];
}

__global__ void concat_kernel(float4* __restrict__ cat, const float4* __restrict__ mem,
                              const float4* __restrict__ h) {
    size_t i = (size_t)blockIdx.x * 256 + threadIdx.x;
    const size_t half = (size_t)MLEN * BATCH * DMODEL / 4;
    float4 v = (i < half) ? mem[i] : h[i - half];
    cat[i] = make_float4(f2tf32f(v.x), f2tf32f(v.y), f2tf32f(v.z), f2tf32f(v.w));
}

// q = split-K partials q0+q1 (rows [i*4+b], 1024 cols); outputs rounded tf32
__global__ void repack_quqv(const float* __restrict__ q0, const float* __restrict__ q1,
                            const float* __restrict__ u, const float* __restrict__ v,
                            float* __restrict__ qu, float* __restrict__ qv) {
    int idx = blockIdx.x * 256 + threadIdx.x;
    int d4 = idx & 15, i = (idx >> 4) & 511, bh = idx >> 13;
    int b = bh >> 4, n = bh & 15;
    size_t qoff = ((size_t)(i * 4 + b)) * 1024 + n * 64 + d4 * 4;
    float4 qa = *(const float4*)(q0 + qoff);
    float4 qb = *(const float4*)(q1 + qoff);
    float4 uu = *(const float4*)(u + n * 64 + d4 * 4);
    float4 vv = *(const float4*)(v + n * 64 + d4 * 4);
    float qx = qa.x + qb.x, qy = qa.y + qb.y, qz = qa.z + qb.z, qw = qa.w + qb.w;
    size_t o = ((size_t)bh * 512 + i) * 64 + d4 * 4;
    *(float4*)(qu + o) = make_float4(f2tf32f(qx + uu.x), f2tf32f(qy + uu.y),
                                     f2tf32f(qz + uu.z), f2tf32f(qw + uu.w));
    *(float4*)(qv + o) = make_float4(f2tf32f(qx + vv.x), f2tf32f(qy + vv.y),
                                     f2tf32f(qz + vv.z), f2tf32f(qw + vv.w));
}

__global__ void repack_kv(const float* __restrict__ heads, float* __restrict__ kc,
                          float* __restrict__ vc) {
    int idx = blockIdx.x * 256 + threadIdx.x;
    int d4 = idx & 15, j = (idx >> 4) & 1023, bh = idx >> 14;
    int b = bh >> 4, n = bh & 15;
    const float* base = heads + ((size_t)(j * 4 + b)) * 3072 + n * 64 + d4 * 4;
    float4 kx = *(const float4*)(base + 1024);
    float4 vx = *(const float4*)(base + 2048);
    size_t o = ((size_t)bh * 1024 + j) * 64 + d4 * 4;
    *(float4*)(kc + o) = kx;
    *(float4*)(vc + o) = vx;
}

// rk = split-K partials p0+p1 ([j][1024]); output [n][j][64], rounded
__global__ void repack_rk(const float* __restrict__ p0, const float* __restrict__ p1,
                          float* __restrict__ rkc) {
    int idx = blockIdx.x * 256 + threadIdx.x;
    int d4 = idx & 15, j = (idx >> 4) & 1023, n = idx >> 14;
    size_t off = (size_t)j * 1024 + n * 64 + d4 * 4;
    float4 a = *(const float4*)(p0 + off);
    float4 b = *(const float4*)(p1 + off);
    *(float4*)(rkc + ((size_t)n * 1024 + j) * 64 + d4 * 4) =
        make_float4(f2tf32f(a.x + b.x), f2tf32f(a.y + b.y),
                    f2tf32f(a.z + b.z), f2tf32f(a.w + b.w));
}

// ---------------- residual + 2 partials + LayerNorm (output rounded) ----------------
__global__ void __launch_bounds__(256) add_ln3_kernel(
    float* __restrict__ h, const float* __restrict__ t0, const float* __restrict__ t1,
    const float* __restrict__ g, const float* __restrict__ b)
{
    int row = blockIdx.x;
    int tid = threadIdx.x;
    __shared__ float rs[256], rs2[256];
    float x[4];
    float s = 0.f, ss = 0.f;
#pragma unroll
    for (int c = 0; c < 4; c++) {
        int d = c * 256 + tid;
        size_t o = (size_t)row * 1024 + d;
        float v = h[o] + t0[o] + t1[o];
        x[c] = v; s += v; ss += v * v;
    }
    rs[tid] = s; rs2[tid] = ss; __syncthreads();
    for (int o = 128; o > 0; o >>= 1) {
        if (tid < o) { rs[tid] += rs[tid + o]; rs2[tid] += rs2[tid + o]; }
        __syncthreads();
    }
    float mu = rs[0] * (1.0f / 1024.0f);
    float var = rs2[0] * (1.0f / 1024.0f) - mu * mu;
    float inv = rsqrtf(var + 1e-5f);
#pragma unroll
    for (int c = 0; c < 4; c++) {
        int d = c * 256 + tid;
        h[(size_t)row * 1024 + d] = f2tf32f((x[c] - mu) * inv * g[d] + b[d]);
    }
}

// ---------------- launch ----------------
extern "C" void kernel_launch(void* const* d_in, const int* in_sizes, int n_in,
                              void* d_out, int out_size) {
    (void)in_sizes; (void)n_in; (void)out_size;
    const float* x     = (const float*)d_in[0];
    const float* mems  = (const float*)d_in[1];
    const float* u     = (const float*)d_in[2];
    const float* v     = (const float*)d_in[3];
    const float* W_qkv = (const float*)d_in[4];
    const float* W_o   = (const float*)d_in[5];
    const float* W_r   = (const float*)d_in[6];
    const float* ln1_g = (const float*)d_in[7];
    const float* ln1_b = (const float*)d_in[8];
    const float* W1    = (const float*)d_in[9];
    const float* b1    = (const float*)d_in[10];
    const float* W2    = (const float*)d_in[11];
    const float* b2    = (const float*)d_in[12];
    const float* ln2_g = (const float*)d_in[13];
    const float* ln2_b = (const float*)d_in[14];

    float *cat, *heads, *r, *ac, *bd, *av, *tmp, *tmp2, *h, *ff, *qu, *qv, *kc, *vc, *rkc;
    float *wqkv, *wr, *wo, *w1, *w2;
    cudaGetSymbolAddress((void**)&cat,   g_cat);
    cudaGetSymbolAddress((void**)&heads, g_heads);
    cudaGetSymbolAddress((void**)&r,     g_r);
    cudaGetSymbolAddress((void**)&ac,    g_ac);
    cudaGetSymbolAddress((void**)&bd,    g_bd);
    cudaGetSymbolAddress((void**)&av,    g_av);
    cudaGetSymbolAddress((void**)&tmp,   g_tmp);
    cudaGetSymbolAddress((void**)&tmp2,  g_tmp2);
    cudaGetSymbolAddress((void**)&h,     g_h);
    cudaGetSymbolAddress((void**)&ff,    g_ff);
    cudaGetSymbolAddress((void**)&qu,    g_qu);
    cudaGetSymbolAddress((void**)&qv,    g_qv);
    cudaGetSymbolAddress((void**)&kc,    g_kc);
    cudaGetSymbolAddress((void**)&vc,    g_vc);
    cudaGetSymbolAddress((void**)&rkc,   g_rkc);
    cudaGetSymbolAddress((void**)&wqkv,  g_wqkv);
    cudaGetSymbolAddress((void**)&wr,    g_wr);
    cudaGetSymbolAddress((void**)&wo,    g_wo);
    cudaGetSymbolAddress((void**)&w1,    g_w1);
    cudaGetSymbolAddress((void**)&w2,    g_w2);

    cudaFuncSetAttribute(gemm4<0,0,0>, cudaFuncAttributeMaxDynamicSharedMemorySize, G4_SMEM);
    cudaFuncSetAttribute(gemm4<0,0,1>, cudaFuncAttributeMaxDynamicSharedMemorySize, G4_SMEM);
    cudaFuncSetAttribute(gemm4<1,1,1>, cudaFuncAttributeMaxDynamicSharedMemorySize, G4_SMEM);
    cudaFuncSetAttribute(gemm4<0,1,0>, cudaFuncAttributeMaxDynamicSharedMemorySize, G4_SMEM);
    cudaFuncSetAttribute(score2<0>,    cudaFuncAttributeMaxDynamicSharedMemorySize, SC_SMEM);
    cudaFuncSetAttribute(score2<1>,    cudaFuncAttributeMaxDynamicSharedMemorySize, SC_SMEM);
    cudaFuncSetAttribute(flash_av,     cudaFuncAttributeMaxDynamicSharedMemorySize, FV_SMEM);

    // one-time weight rounding
    roundw_kernel<<<(NLAYER*DMODEL*3072/4)/256, 256>>>((float4*)wqkv, (const float4*)W_qkv);
    roundw_kernel<<<(NLAYER*DMODEL*DMODEL/4)/256, 256>>>((float4*)wr, (const float4*)W_r);
    roundw_kernel<<<(NLAYER*DMODEL*DMODEL/4)/256, 256>>>((float4*)wo, (const float4*)W_o);
    roundw_kernel<<<(NLAYER*DMODEL*DINNER/4)/256, 256>>>((float4*)w1, (const float4*)W1);
    roundw_kernel<<<(NLAYER*DINNER*DMODEL/4)/256, 256>>>((float4*)w2, (const float4*)W2);

    posemb_kernel<<<4096, 256>>>(r);
    copy4_kernel<<<2048, 256>>>((float4*)h, (const float4*)x);

    for (int l = 0; l < NLAYER; l++) {
        const float* Wq = wqkv + (size_t)l * DMODEL * 3072;
        concat_kernel<<<4096, 256>>>((float4*)cat,
                                     (const float4*)(mems + (size_t)l * MLEN * BATCH * DMODEL),
                                     (const float4*)h);
        // K,V: all 4096 rows, cols 1024..3071 — rounded output (feeds kc/vc)
        gemm4<0,0,1><<<dim3(16, 32, 1), 128, G4_SMEM>>>(
            cat, Wq + 1024, nullptr, heads + 1024, nullptr, 1024, 1024, 3072, 3072);
        // Q: last 2048 rows, split-K=2 into tmp/tmp2
        gemm4<0,0,0><<<dim3(8, 16, 2), 128, G4_SMEM>>>(
            cat + (size_t)2048 * 1024, Wq, nullptr, tmp, tmp2, 512, 1024, 3072, 1024);
        // rk: split-K=2 into bd scratch halves (bd free until score2<1>)
        gemm4<0,0,0><<<dim3(8, 8, 2), 128, G4_SMEM>>>(
            r, wr + (size_t)l * DMODEL * DMODEL, nullptr, bd, bd + (size_t)1024 * 1024,
            512, 1024, 1024, 1024);
        // repacks
        repack_quqv<<<2048, 256>>>(tmp, tmp2, u, v, qu, qv);
        repack_kv<<<4096, 256>>>(heads, kc, vc);
        repack_rk<<<1024, 256>>>(bd, bd + (size_t)1024 * 1024, rkc);
        // scores
        score2<0><<<dim3(8, 4, BH), 128, SC_SMEM>>>(qu, kc, ac);
        score2<1><<<dim3(8, 4, BH), 128, SC_SMEM>>>(qv, rkc, bd);
        // fused softmax + P@V
        flash_av<<<dim3(4, BH), 128, FV_SMEM>>>(ac, bd, vc, av);
        // O projection: split-K=2
        gemm4<0,0,0><<<dim3(8, 16, 2), 128, G4_SMEM>>>(
            av, wo + (size_t)l * DMODEL * DMODEL, nullptr, tmp, tmp2,
            512, 1024, 1024, 1024);
        add_ln3_kernel<<<2048, 256>>>(h, tmp, tmp2,
                                      ln1_g + (size_t)l * DMODEL, ln1_b + (size_t)l * DMODEL);
        // FFN
        gemm4<1,1,1><<<dim3(32, 16, 1), 128, G4_SMEM>>>(
            h, w1 + (size_t)l * DMODEL * DINNER, b1 + (size_t)l * DINNER, ff, nullptr,
            1024, 1024, 4096, 4096);
        gemm4<0,1,0><<<dim3(8, 16, 2), 128, G4_SMEM>>>(
            ff, w2 + (size_t)l * DINNER * DMODEL, b2 + (size_t)l * DMODEL, tmp, tmp2,
            2048, 4096, 1024, 1024);
        add_ln3_kernel<<<2048, 256>>>(h, tmp, tmp2,
                                      ln2_g + (size_t)l * DMODEL, ln2_b + (size_t)l * DMODEL);
    }

    cudaMemcpyAsync(d_out, h, (size_t)QLEN * BATCH * DMODEL * sizeof(float),
                    cudaMemcpyDeviceToDevice);
}

// round 12
// speedup vs baseline: 1.1880x; 1.1880x over previous
#include <cuda_runtime.h>
#include <math.h>
#include <stdint.h>

#define QLEN 512
#define BATCH 4
#define DMODEL 1024
#define NLAYER 4
#define NHEAD 16
#define DHEAD 64
#define DINNER 4096
#define MLEN 512
#define KLEN 1024
#define BH (BATCH*NHEAD)

// ---------------- scratch ----------------
__device__ float g_cat[(size_t)KLEN*BATCH*DMODEL];
__device__ float g_heads[(size_t)KLEN*BATCH*3*DMODEL];
__device__ float g_r[(size_t)KLEN*DMODEL];
__device__ float g_ac[(size_t)BH*QLEN*KLEN];
__device__ float g_bd[(size_t)BH*QLEN*KLEN];
__device__ float g_av[(size_t)QLEN*BATCH*DMODEL];
__device__ float g_tmp[(size_t)QLEN*BATCH*DMODEL];
__device__ float g_tmp2[(size_t)QLEN*BATCH*DMODEL];
__device__ float g_h[(size_t)QLEN*BATCH*DMODEL];
__device__ float g_ff[(size_t)QLEN*BATCH*DINNER];
__device__ float g_qu[(size_t)BH*QLEN*DHEAD];
__device__ float g_qv[(size_t)BH*QLEN*DHEAD];
__device__ float g_rkc[(size_t)NHEAD*KLEN*DHEAD];
// tf32-rounded weight copies
__device__ float g_wqkv[(size_t)NLAYER*DMODEL*3072];
__device__ float g_wr[(size_t)NLAYER*DMODEL*DMODEL];
__device__ float g_wo[(size_t)NLAYER*DMODEL*DMODEL];
__device__ float g_w1[(size_t)NLAYER*DMODEL*DINNER];
__device__ float g_w2[(size_t)NLAYER*DINNER*DMODEL];

__device__ __forceinline__ uint32_t f2tf32(float f) {
    uint32_t o;
    asm("cvt.rna.tf32.f32 %0, %1;" : "=r"(o) : "f"(f));
    return o;
}
__device__ __forceinline__ float f2tf32f(float f) {
    uint32_t o = f2tf32(f);
    return __uint_as_float(o);
}

#define MMA_TF32(d, a, b) \
    asm volatile("mma.sync.aligned.m16n8k8.row.col.f32.tf32.tf32.f32 " \
                 "{%0,%1,%2,%3}, {%4,%5,%6,%7}, {%8,%9}, {%0,%1,%2,%3};" \
                 : "+f"(d[0]), "+f"(d[1]), "+f"(d[2]), "+f"(d[3]) \
                 : "r"(a.x), "r"(a.y), "r"(a.z), "r"(a.w), "r"(b.x), "r"(b.y))

__device__ __forceinline__ void cpasync16(uint32_t dst, const void* src) {
    asm volatile("cp.async.cg.shared.global [%0], [%1], 16;" :: "r"(dst), "l"(src));
}
#define CP_COMMIT() asm volatile("cp.async.commit_group;" ::: "memory")
__device__ __forceinline__ uint32_t smem_u32(const void* p) {
    uint32_t a;
    asm("{ .reg .u64 t; cvta.to.shared.u64 t, %1; cvt.u32.u64 %0, t; }" : "=r"(a) : "l"(p));
    return a;
}
#define SW128B(o) ((o) ^ (((o) >> 3) & 0x70))

// gemm4: 3 stages x (A 4096 + B 4096) words
#define G4_STAGE_W 8192
#define G4_SMEM (3 * G4_STAGE_W * 4)

// ======== gemm4: C[M,N]=A[M,K]@B[K,N]. 128 thr, CTA 128x128, warp 64x64 ========
template<int RELU, int HASBIAS, int CVT>
__global__ void __launch_bounds__(128) gemm4(
    const float* __restrict__ A, const float* __restrict__ B,
    const float* __restrict__ bias, float* __restrict__ C0, float* __restrict__ C1,
    int K, int lda, int ldb, int ldc)
{
    extern __shared__ uint32_t dsm[];
    const uint32_t sbase = smem_u32(dsm);
    const int tid = threadIdx.x, lane = tid & 31;
    const int warp = tid >> 5, wm = warp >> 1, wn = warp & 1;
    const int bx = blockIdx.x, by = blockIdx.y, bz = blockIdx.z;

    const int koff = bz * K;
    float* C = bz ? C1 : C0;

    const int a_row0 = tid >> 3, a_ch = tid & 7;
    const float* Ag = A + (size_t)(by * 128 + a_row0) * lda + koff + a_ch * 4;
    const int b_k = tid >> 2, b_nch0 = tid & 3;
    const float* Bg = B + (size_t)(koff + b_k) * ldb + bx * 128 + b_nch0 * 4;

    float acc[4][8][4];
#pragma unroll
    for (int mi = 0; mi < 4; mi++)
#pragma unroll
        for (int ni = 0; ni < 8; ni++)
#pragma unroll
            for (int r = 0; r < 4; r++) acc[mi][ni][r] = 0.f;

    const int lr = lane >> 2, lc = lane & 3;
    const int niter = K >> 5;

#define G4_LOAD(stg, k0) do { \
    uint32_t ab_ = sbase + (stg) * (G4_STAGE_W * 4); \
    _Pragma("unroll") for (int i = 0; i < 8; i++) { \
        uint32_t so_ = SW128B((uint32_t)((a_row0 + 16 * i) * 128 + a_ch * 16)); \
        cpasync16(ab_ + so_, Ag + (size_t)(16 * i) * lda + (k0)); \
    } \
    uint32_t bb_ = ab_ + 4096 * 4; \
    _Pragma("unroll") for (int i = 0; i < 8; i++) { \
        int n_ = (b_nch0 + 4 * i) * 4; \
        uint32_t w_ = (uint32_t)(b_k * 128 + (n_ ^ ((b_k & 3) << 3))); \
        cpasync16(bb_ + w_ * 4, Bg + (size_t)(k0) * ldb + 16 * i); \
    } \
    CP_COMMIT(); \
} while (0)

    G4_LOAD(0, 0);
    if (niter > 1) G4_LOAD(1, 32);

    for (int it = 0; it < niter; it++) {
        if (it + 1 < niter) {
            asm volatile("cp.async.wait_group 1;" ::: "memory");
        } else {
            asm volatile("cp.async.wait_group 0;" ::: "memory");
        }
        __syncthreads();
        if (it + 2 < niter) G4_LOAD((it + 2) % 3, (it + 2) * 32);

        const uint32_t* Abuf = dsm + (it % 3) * G4_STAGE_W;
        const uint32_t* Bbuf = Abuf + 4096;
#pragma unroll
        for (int kk = 0; kk < 4; kk++) {
            uint4 af[4]; uint2 bf[8];
#pragma unroll
            for (int mi = 0; mi < 4; mi++) {
                int row = wm * 64 + mi * 16 + lr;
                int k = kk * 8 + lc;
                af[mi].x = Abuf[SW128B((uint32_t)(row * 128 + k * 4)) >> 2];
                af[mi].y = Abuf[SW128B((uint32_t)((row + 8) * 128 + k * 4)) >> 2];
                af[mi].z = Abuf[SW128B((uint32_t)(row * 128 + (k + 4) * 4)) >> 2];
                af[mi].w = Abuf[SW128B((uint32_t)((row + 8) * 128 + (k + 4) * 4)) >> 2];
            }
#pragma unroll
            for (int ni = 0; ni < 8; ni++) {
                int n = wn * 64 + ni * 8 + lr;
                int kb = kk * 8 + lc;
                int nsw = n ^ (lc << 3);
                bf[ni].x = Bbuf[kb * 128 + nsw];
                bf[ni].y = Bbuf[(kb + 4) * 128 + nsw];
            }
#pragma unroll
            for (int mi = 0; mi < 4; mi++)
#pragma unroll
                for (int ni = 0; ni < 8; ni++) MMA_TF32(acc[mi][ni], af[mi], bf[ni]);
        }
    }
#undef G4_LOAD

    const bool dobias = HASBIAS && (bz == 0);
#pragma unroll
    for (int mi = 0; mi < 4; mi++) {
#pragma unroll
        for (int ni = 0; ni < 8; ni++) {
            int row0 = by * 128 + wm * 64 + mi * 16 + lr;
            int col  = bx * 128 + wn * 64 + ni * 8 + lc * 2;
            float b0 = 0.f, b1 = 0.f;
            if (dobias) { b0 = bias[col]; b1 = bias[col + 1]; }
            float v0 = acc[mi][ni][0] + b0, v1 = acc[mi][ni][1] + b1;
            float v2 = acc[mi][ni][2] + b0, v3 = acc[mi][ni][3] + b1;
            if (RELU) {
                v0 = fmaxf(v0, 0.f); v1 = fmaxf(v1, 0.f);
                v2 = fmaxf(v2, 0.f); v3 = fmaxf(v3, 0.f);
            }
            if (CVT) {
                v0 = f2tf32f(v0); v1 = f2tf32f(v1);
                v2 = f2tf32f(v2); v3 = f2tf32f(v3);
            }
            *(float2*)(C + (size_t)row0 * ldc + col)       = make_float2(v0, v1);
            *(float2*)(C + (size_t)(row0 + 8) * ldc + col) = make_float2(v2, v3);
        }
    }
}

// ======== score2: out[bh,i,j] = sum_d A[i][d]*B_row(j)[d] ========
// MODE 0: B rows stream directly from heads (K part), row stride 12288.
// MODE 1: B rows from rkc [n][1024][64], row stride 64.
#define SC_SMEM (4 * 4096 * 4)
template<int MODE>
__global__ void __launch_bounds__(128) score2(
    const float* __restrict__ Qb, const float* __restrict__ KV,
    float* __restrict__ out)
{
    const int bx = blockIdx.x, by = blockIdx.y, bh = blockIdx.z;
    const int i0 = by * 128, j0 = bx * 128;
    if (MODE == 0) { if (j0 >= i0 + 640) return; }
    else           { if (i0 + j0 < 257) return; }
    const int bb = bh >> 4, nn = bh & 15;
    const float* A = Qb + (size_t)bh * QLEN * 64 + (size_t)i0 * 64;
    const float* B;
    size_t ldbB;
    if (MODE == 0) {
        // K rows in heads: row j at heads[(j*4+b)*3072 + 1024 + n*64]
        B = KV + (size_t)(j0 * 4 + bb) * 3072 + 1024 + (size_t)nn * 64;
        ldbB = 4 * 3072;
    } else {
        B = KV + (size_t)nn * KLEN * 64 + (size_t)j0 * 64;
        ldbB = 64;
    }

    extern __shared__ uint32_t dsm[];
    const uint32_t sbase = smem_u32(dsm);
    const int tid = threadIdx.x, lane = tid & 31;
    const int warp = tid >> 5, wm = warp >> 1, wn = warp & 1;

    const int a_row0 = tid >> 3, a_ch = tid & 7;
    const float* Ag = A + (size_t)a_row0 * 64 + a_ch * 4;
    const float* Bg = B + (size_t)a_row0 * ldbB + a_ch * 4;

    float acc[4][8][4];
#pragma unroll
    for (int mi = 0; mi < 4; mi++)
#pragma unroll
        for (int ni = 0; ni < 8; ni++)
#pragma unroll
            for (int r = 0; r < 4; r++) acc[mi][ni][r] = 0.f;

    const int lr = lane >> 2, lc = lane & 3;

#define SC_LOAD(stg, k0) do { \
    uint32_t ab_ = sbase + (stg) * 32768; \
    uint32_t bb_ = ab_ + 16384; \
    _Pragma("unroll") for (int i = 0; i < 8; i++) { \
        uint32_t so_ = SW128B((uint32_t)((a_row0 + 16 * i) * 128 + a_ch * 16)); \
        cpasync16(ab_ + so_, Ag + (size_t)(16 * i) * 64 + (k0)); \
        cpasync16(bb_ + so_, Bg + (size_t)(16 * i) * ldbB + (k0)); \
    } \
    CP_COMMIT(); \
} while (0)

    SC_LOAD(0, 0);
    SC_LOAD(1, 32);

#pragma unroll
    for (int it = 0; it < 2; it++) {
        if (it == 0) asm volatile("cp.async.wait_group 1;" ::: "memory");
        else         asm volatile("cp.async.wait_group 0;" ::: "memory");
        __syncthreads();
        const uint32_t* Abuf = dsm + it * 8192;
        const uint32_t* Bbuf = Abuf + 4096;
#pragma unroll
        for (int kk = 0; kk < 4; kk++) {
            uint4 af[4]; uint2 bf[8];
#pragma unroll
            for (int mi = 0; mi < 4; mi++) {
                int row = wm * 64 + mi * 16 + lr;
                int k = kk * 8 + lc;
                af[mi].x = Abuf[SW128B((uint32_t)(row * 128 + k * 4)) >> 2];
                af[mi].y = Abuf[SW128B((uint32_t)((row + 8) * 128 + k * 4)) >> 2];
                af[mi].z = Abuf[SW128B((uint32_t)(row * 128 + (k + 4) * 4)) >> 2];
                af[mi].w = Abuf[SW128B((uint32_t)((row + 8) * 128 + (k + 4) * 4)) >> 2];
            }
#pragma unroll
            for (int ni = 0; ni < 8; ni++) {
                int n = wn * 64 + ni * 8 + lr;
                int k = kk * 8 + lc;
                bf[ni].x = Bbuf[SW128B((uint32_t)(n * 128 + k * 4)) >> 2];
                bf[ni].y = Bbuf[SW128B((uint32_t)(n * 128 + (k + 4) * 4)) >> 2];
            }
#pragma unroll
            for (int mi = 0; mi < 4; mi++)
#pragma unroll
                for (int ni = 0; ni < 8; ni++) MMA_TF32(acc[mi][ni], af[mi], bf[ni]);
        }
    }
#undef SC_LOAD

    float* ob = out + (size_t)bh * QLEN * KLEN;
#pragma unroll
    for (int mi = 0; mi < 4; mi++)
#pragma unroll
        for (int ni = 0; ni < 8; ni++) {
            int row0 = i0 + wm * 64 + mi * 16 + lr;
            int col  = j0 + wn * 64 + ni * 8 + lc * 2;
            *(float2*)(ob + (size_t)row0 * KLEN + col) =
                make_float2(acc[mi][ni][0], acc[mi][ni][1]);
            *(float2*)(ob + (size_t)(row0 + 8) * KLEN + col) =
                make_float2(acc[mi][ni][2], acc[mi][ni][3]);
        }
}

// ======== av2: av = P[128, kmax] @ V[kmax, 64], V streamed from heads ========
#define AV2_STAGE_W 6144
#define AV2_SMEM (3 * AV2_STAGE_W * 4)
__global__ void __launch_bounds__(128) av2(
    const float* __restrict__ P, const float* __restrict__ heads, float* __restrict__ av)
{
    extern __shared__ uint32_t dsm[];
    const uint32_t sbase = smem_u32(dsm);
    const int by = blockIdx.x, bh = blockIdx.y;
    const int b = bh >> 4, n_h = bh & 15;
    const float* A = P + (size_t)bh * QLEN * KLEN + (size_t)by * 128 * KLEN;
    // V row j at heads[(j*4+b)*3072 + 2048 + n*64]
    const float* Vb = heads + (size_t)b * 3072 + 2048 + (size_t)n_h * 64;
    const size_t ldv = 4 * 3072;
    const int kmax = min(KLEN, by * 128 + 640);

    const int tid = threadIdx.x, lane = tid & 31;
    const int warp = tid >> 5, wm = warp >> 1, wn = warp & 1;

    const int a_row0 = tid >> 3, a_ch = tid & 7;
    const float* Ag = A + (size_t)a_row0 * KLEN + a_ch * 4;
    const int b_k = tid >> 2, b_nch0 = tid & 3;
    const float* Bg = Vb + (size_t)b_k * ldv + b_nch0 * 4;

    float acc[4][4][4];
#pragma unroll
    for (int mi = 0; mi < 4; mi++)
#pragma unroll
        for (int ni = 0; ni < 4; ni++)
#pragma unroll
            for (int r = 0; r < 4; r++) acc[mi][ni][r] = 0.f;

    const int lr = lane >> 2, lc = lane & 3;
    const int niter = kmax >> 5;

#define AV2_LOAD(stg, k0) do { \
    uint32_t ab_ = sbase + (stg) * (AV2_STAGE_W * 4); \
    _Pragma("unroll") for (int i = 0; i < 8; i++) { \
        uint32_t so_ = SW128B((uint32_t)((a_row0 + 16 * i) * 128 + a_ch * 16)); \
        cpasync16(ab_ + so_, Ag + (size_t)(16 * i) * KLEN + (k0)); \
    } \
    uint32_t bb_ = ab_ + 4096 * 4; \
    _Pragma("unroll") for (int i = 0; i < 4; i++) { \
        int n_ = (b_nch0 + 4 * i) * 4; \
        uint32_t w_ = (uint32_t)(b_k * 64 + (n_ ^ ((b_k & 3) << 3))); \
        cpasync16(bb_ + w_ * 4, Bg + (size_t)(k0) * ldv + 16 * i); \
    } \
    CP_COMMIT(); \
} while (0)

    AV2_LOAD(0, 0);
    if (niter > 1) AV2_LOAD(1, 32);

    for (int it = 0; it < niter; it++) {
        if (it + 1 < niter) {
            asm volatile("cp.async.wait_group 1;" ::: "memory");
        } else {
            asm volatile("cp.async.wait_group 0;" ::: "memory");
        }
        __syncthreads();
        if (it + 2 < niter) AV2_LOAD((it + 2) % 3, (it + 2) * 32);

        const uint32_t* Abuf = dsm + (it % 3) * AV2_STAGE_W;
        const uint32_t* Bbuf = Abuf + 4096;
#pragma unroll
        for (int kk = 0; kk < 4; kk++) {
            uint4 af[4]; uint2 bf[4];
#pragma unroll
            for (int mi = 0; mi < 4; mi++) {
                int row = wm * 64 + mi * 16 + lr;
                int k = kk * 8 + lc;
                af[mi].x = Abuf[SW128B((uint32_t)(row * 128 + k * 4)) >> 2];
                af[mi].y = Abuf[SW128B((uint32_t)((row + 8) * 128 + k * 4)) >> 2];
                af[mi].z = Abuf[SW128B((uint32_t)(row * 128 + (k + 4) * 4)) >> 2];
                af[mi].w = Abuf[SW128B((uint32_t)((row + 8) * 128 + (k + 4) * 4)) >> 2];
            }
#pragma unroll
            for (int ni = 0; ni < 4; ni++) {
                int n = wn * 32 + ni * 8 + lr;
                int kb = kk * 8 + lc;
                int nsw = n ^ (lc << 3);
                bf[ni].x = Bbuf[kb * 64 + nsw];
                bf[ni].y = Bbuf[(kb + 4) * 64 + nsw];
            }
#pragma unroll
            for (int mi = 0; mi < 4; mi++)
#pragma unroll
                for (int ni = 0; ni < 4; ni++) MMA_TF32(acc[mi][ni], af[mi], bf[ni]);
        }
    }
#undef AV2_LOAD

#pragma unroll
    for (int mi = 0; mi < 4; mi++)
#pragma unroll
        for (int ni = 0; ni < 4; ni++) {
            int row0 = by * 128 + wm * 64 + mi * 16 + lr;
            int col  = wn * 32 + ni * 8 + lc * 2;
            *(float2*)(av + ((size_t)row0 * 4 + b) * 1024 + n_h * 64 + col) =
                make_float2(f2tf32f(acc[mi][ni][0]), f2tf32f(acc[mi][ni][1]));
            *(float2*)(av + ((size_t)(row0 + 8) * 4 + b) * 1024 + n_h * 64 + col) =
                make_float2(f2tf32f(acc[mi][ni][2]), f2tf32f(acc[mi][ni][3]));
        }
}

// ---------------- weight rounding ----------------
__global__ void roundw_kernel(float4* __restrict__ dst, const float4* __restrict__ src) {
    size_t i = (size_t)blockIdx.x * 256 + threadIdx.x;
    float4 v = src[i];
    dst[i] = make_float4(f2tf32f(v.x), f2tf32f(v.y), f2tf32f(v.z), f2tf32f(v.w));
}

// ---------------- small kernels ----------------
__global__ void posemb_kernel(float* __restrict__ r) {
    int idx = blockIdx.x * 256 + threadIdx.x;
    int k = idx >> 10, d = idx & 1023;
    float pos = (float)(KLEN - 1 - k);
    int j = (d < 512) ? d : d - 512;
    float inv = expf(-((float)(2 * j) / 1024.0f) * 9.210340371976184f);
    float ang = pos * inv;
    r[idx] = f2tf32f((d < 512) ? sinf(ang) : cosf(ang));
}

__global__ void copy4_kernel(float4* __restrict__ dst, const float4* __restrict__ src) {
    size_t i = (size_t)blockIdx.x * 256 + threadIdx.x;
    dst[i] = src[i];
}

__global__ void concat_kernel(float4* __restrict__ cat, const float4* __restrict__ mem,
                              const float4* __restrict__ h) {
    size_t i = (size_t)blockIdx.x * 256 + threadIdx.x;
    const size_t half = (size_t)MLEN * BATCH * DMODEL / 4;
    float4 v = (i < half) ? mem[i] : h[i - half];
    cat[i] = make_float4(f2tf32f(v.x), f2tf32f(v.y), f2tf32f(v.z), f2tf32f(v.w));
}

// q = split-K partials q0+q1 (rows [i*4+b], 1024 cols); outputs rounded tf32
__global__ void repack_quqv(const float* __restrict__ q0, const float* __restrict__ q1,
                            const float* __restrict__ u, const float* __restrict__ v,
                            float* __restrict__ qu, float* __restrict__ qv) {
    int idx = blockIdx.x * 256 + threadIdx.x;
    int d4 = idx & 15, i = (idx >> 4) & 511, bh = idx >> 13;
    int b = bh >> 4, n = bh & 15;
    size_t qoff = ((size_t)(i * 4 + b)) * 1024 + n * 64 + d4 * 4;
    float4 qa = *(const float4*)(q0 + qoff);
    float4 qb = *(const float4*)(q1 + qoff);
    float4 uu = *(const float4*)(u + n * 64 + d4 * 4);
    float4 vv = *(const float4*)(v + n * 64 + d4 * 4);
    float qx = qa.x + qb.x, qy = qa.y + qb.y, qz = qa.z + qb.z, qw = qa.w + qb.w;
    size_t o = ((size_t)bh * 512 + i) * 64 + d4 * 4;
    *(float4*)(qu + o) = make_float4(f2tf32f(qx + uu.x), f2tf32f(qy + uu.y),
                                     f2tf32f(qz + uu.z), f2tf32f(qw + uu.w));
    *(float4*)(qv + o) = make_float4(f2tf32f(qx + vv.x), f2tf32f(qy + vv.y),
                                     f2tf32f(qz + vv.z), f2tf32f(qw + vv.w));
}

// rk = split-K partials p0+p1 ([j][1024]); output [n][j][64], rounded
__global__ void repack_rk(const float* __restrict__ p0, const float* __restrict__ p1,
                          float* __restrict__ rkc) {
    int idx = blockIdx.x * 256 + threadIdx.x;
    int d4 = idx & 15, j = (idx >> 4) & 1023, n = idx >> 14;
    size_t off = (size_t)j * 1024 + n * 64 + d4 * 4;
    float4 a = *(const float4*)(p0 + off);
    float4 b = *(const float4*)(p1 + off);
    *(float4*)(rkc + ((size_t)n * 1024 + j) * 64 + d4 * 4) =
        make_float4(f2tf32f(a.x + b.x), f2tf32f(a.y + b.y),
                    f2tf32f(a.z + b.z), f2tf32f(a.w + b.w));
}

// ---------------- softmax (shift+mask+scale fused; output rounded) ----------------
__global__ void __launch_bounds__(256) softmax_kernel(float* ac, const float* __restrict__ bd) {
    int i = blockIdx.x;
    int bh = blockIdx.y;
    float* acrow = ac + ((size_t)bh * QLEN + i) * KLEN;
    const float* bdrow = bd + ((size_t)bh * QLEN + i) * KLEN;
    int tid = threadIdx.x;
    __shared__ float red[256];
    int jmax = i + MLEN;
    int shift = QLEN - 1 - i;
    float v[4];
    float m = -1e30f;
#pragma unroll
    for (int c = 0; c < 4; c++) {
        int j = c * 256 + tid;
        float s = (j <= jmax) ? 0.125f * (acrow[j] + bdrow[j + shift]) : -1e30f;
        v[c] = s;
        m = fmaxf(m, s);
    }
    red[tid] = m; __syncthreads();
    for (int o = 128; o > 0; o >>= 1) {
        if (tid < o) red[tid] = fmaxf(red[tid], red[tid + o]);
        __syncthreads();
    }
    m = red[0]; __syncthreads();
    float sum = 0.f;
#pragma unroll
    for (int c = 0; c < 4; c++) { v[c] = expf(v[c] - m); sum += v[c]; }
    red[tid] = sum; __syncthreads();
    for (int o = 128; o > 0; o >>= 1) {
        if (tid < o) red[tid] += red[tid + o];
        __syncthreads();
    }
    float inv = 1.0f / red[0];
#pragma unroll
    for (int c = 0; c < 4; c++) acrow[c * 256 + tid] = f2tf32f(v[c] * inv);
}

// ---------------- residual + 2 partials + LayerNorm (output rounded) ----------------
__global__ void __launch_bounds__(256) add_ln3_kernel(
    float* __restrict__ h, const float* __restrict__ t0, const float* __restrict__ t1,
    const float* __restrict__ g, const float* __restrict__ b)
{
    int row = blockIdx.x;
    int tid = threadIdx.x;
    __shared__ float rs[256], rs2[256];
    float x[4];
    float s = 0.f, ss = 0.f;
#pragma unroll
    for (int c = 0; c < 4; c++) {
        int d = c * 256 + tid;
        size_t o = (size_t)row * 1024 + d;
        float v = h[o] + t0[o] + t1[o];
        x[c] = v; s += v; ss += v * v;
    }
    rs[tid] = s; rs2[tid] = ss; __syncthreads();
    for (int o = 128; o > 0; o >>= 1) {
        if (tid < o) { rs[tid] += rs[tid + o]; rs2[tid] += rs2[tid + o]; }
        __syncthreads();
    }
    float mu = rs[0] * (1.0f / 1024.0f);
    float var = rs2[0] * (1.0f / 1024.0f) - mu * mu;
    float inv = rsqrtf(var + 1e-5f);
#pragma unroll
    for (int c = 0; c < 4; c++) {
        int d = c * 256 + tid;
        h[(size_t)row * 1024 + d] = f2tf32f((x[c] - mu) * inv * g[d] + b[d]);
    }
}

// ---------------- launch ----------------
extern "C" void kernel_launch(void* const* d_in, const int* in_sizes, int n_in,
                              void* d_out, int out_size) {
    (void)in_sizes; (void)n_in; (void)out_size;
    const float* x     = (const float*)d_in[0];
    const float* mems  = (const float*)d_in[1];
    const float* u     = (const float*)d_in[2];
    const float* v     = (const float*)d_in[3];
    const float* W_qkv = (const float*)d_in[4];
    const float* W_o   = (const float*)d_in[5];
    const float* W_r   = (const float*)d_in[6];
    const float* ln1_g = (const float*)d_in[7];
    const float* ln1_b = (const float*)d_in[8];
    const float* W1    = (const float*)d_in[9];
    const float* b1    = (const float*)d_in[10];
    const float* W2    = (const float*)d_in[11];
    const float* b2    = (const float*)d_in[12];
    const float* ln2_g = (const float*)d_in[13];
    const float* ln2_b = (const float*)d_in[14];

    float *cat, *heads, *r, *ac, *bd, *av, *tmp, *tmp2, *h, *ff, *qu, *qv, *rkc;
    float *wqkv, *wr, *wo, *w1, *w2;
    cudaGetSymbolAddress((void**)&cat,   g_cat);
    cudaGetSymbolAddress((void**)&heads, g_heads);
    cudaGetSymbolAddress((void**)&r,     g_r);
    cudaGetSymbolAddress((void**)&ac,    g_ac);
    cudaGetSymbolAddress((void**)&bd,    g_bd);
    cudaGetSymbolAddress((void**)&av,    g_av);
    cudaGetSymbolAddress((void**)&tmp,   g_tmp);
    cudaGetSymbolAddress((void**)&tmp2,  g_tmp2);
    cudaGetSymbolAddress((void**)&h,     g_h);
    cudaGetSymbolAddress((void**)&ff,    g_ff);
    cudaGetSymbolAddress((void**)&qu,    g_qu);
    cudaGetSymbolAddress((void**)&qv,    g_qv);
    cudaGetSymbolAddress((void**)&rkc,   g_rkc);
    cudaGetSymbolAddress((void**)&wqkv,  g_wqkv);
    cudaGetSymbolAddress((void**)&wr,    g_wr);
    cudaGetSymbolAddress((void**)&wo,    g_wo);
    cudaGetSymbolAddress((void**)&w1,    g_w1);
    cudaGetSymbolAddress((void**)&w2,    g_w2);

    cudaFuncSetAttribute(gemm4<0,0,0>, cudaFuncAttributeMaxDynamicSharedMemorySize, G4_SMEM);
    cudaFuncSetAttribute(gemm4<0,0,1>, cudaFuncAttributeMaxDynamicSharedMemorySize, G4_SMEM);
    cudaFuncSetAttribute(gemm4<1,1,1>, cudaFuncAttributeMaxDynamicSharedMemorySize, G4_SMEM);
    cudaFuncSetAttribute(gemm4<0,1,0>, cudaFuncAttributeMaxDynamicSharedMemorySize, G4_SMEM);
    cudaFuncSetAttribute(score2<0>,    cudaFuncAttributeMaxDynamicSharedMemorySize, SC_SMEM);
    cudaFuncSetAttribute(score2<1>,    cudaFuncAttributeMaxDynamicSharedMemorySize, SC_SMEM);
    cudaFuncSetAttribute(av2,          cudaFuncAttributeMaxDynamicSharedMemorySize, AV2_SMEM);

    // one-time weight rounding
    roundw_kernel<<<(NLAYER*DMODEL*3072/4)/256, 256>>>((float4*)wqkv, (const float4*)W_qkv);
    roundw_kernel<<<(NLAYER*DMODEL*DMODEL/4)/256, 256>>>((float4*)wr, (const float4*)W_r);
    roundw_kernel<<<(NLAYER*DMODEL*DMODEL/4)/256, 256>>>((float4*)wo, (const float4*)W_o);
    roundw_kernel<<<(NLAYER*DMODEL*DINNER/4)/256, 256>>>((float4*)w1, (const float4*)W1);
    roundw_kernel<<<(NLAYER*DINNER*DMODEL/4)/256, 256>>>((float4*)w2, (const float4*)W2);

    posemb_kernel<<<4096, 256>>>(r);
    copy4_kernel<<<2048, 256>>>((float4*)h, (const float4*)x);

    for (int l = 0; l < NLAYER; l++) {
        const float* Wq = wqkv + (size_t)l * DMODEL * 3072;
        concat_kernel<<<4096, 256>>>((float4*)cat,
                                     (const float4*)(mems + (size_t)l * MLEN * BATCH * DMODEL),
                                     (const float4*)h);
        // K,V: all 4096 rows, cols 1024..3071 — rounded output (consumed in place)
        gemm4<0,0,1><<<dim3(16, 32, 1), 128, G4_SMEM>>>(
            cat, Wq + 1024, nullptr, heads + 1024, nullptr, 1024, 1024, 3072, 3072);
        // Q: last 2048 rows, split-K=2 into tmp/tmp2
        gemm4<0,0,0><<<dim3(8, 16, 2), 128, G4_SMEM>>>(
            cat + (size_t)2048 * 1024, Wq, nullptr, tmp, tmp2, 512, 1024, 3072, 1024);
        // rk: split-K=2 into bd scratch halves (bd free until score2<1>)
        gemm4<0,0,0><<<dim3(8, 8, 2), 128, G4_SMEM>>>(
            r, wr + (size_t)l * DMODEL * DMODEL, nullptr, bd, bd + (size_t)1024 * 1024,
            512, 1024, 1024, 1024);
        // repacks
        repack_quqv<<<2048, 256>>>(tmp, tmp2, u, v, qu, qv);
        repack_rk<<<1024, 256>>>(bd, bd + (size_t)1024 * 1024, rkc);
        // scores (K streamed directly from heads; rk from rkc)
        score2<0><<<dim3(8, 4, BH), 128, SC_SMEM>>>(qu, heads, ac);
        score2<1><<<dim3(8, 4, BH), 128, SC_SMEM>>>(qv, rkc, bd);
        softmax_kernel<<<dim3(QLEN, BH), 256>>>(ac, bd);
        // AV (V streamed directly from heads)
        av2<<<dim3(4, BH), 128, AV2_SMEM>>>(ac, heads, av);
        // O projection: split-K=2
        gemm4<0,0,0><<<dim3(8, 16, 2), 128, G4_SMEM>>>(
            av, wo + (size_t)l * DMODEL * DMODEL, nullptr, tmp, tmp2,
            512, 1024, 1024, 1024);
        add_ln3_kernel<<<2048, 256>>>(h, tmp, tmp2,
                                      ln1_g + (size_t)l * DMODEL, ln1_b + (size_t)l * DMODEL);
        // FFN
        gemm4<1,1,1><<<dim3(32, 16, 1), 128, G4_SMEM>>>(
            h, w1 + (size_t)l * DMODEL * DINNER, b1 + (size_t)l * DINNER, ff, nullptr,
            1024, 1024, 4096, 4096);
        gemm4<0,1,0><<<dim3(8, 16, 2), 128, G4_SMEM>>>(
            ff, w2 + (size_t)l * DINNER * DMODEL, b2 + (size_t)l * DMODEL, tmp, tmp2,
            2048, 4096, 1024, 1024);
        add_ln3_kernel<<<2048, 256>>>(h, tmp, tmp2,
                                      ln2_g + (size_t)l * DMODEL, ln2_b + (size_t)l * DMODEL);
    }

    cudaMemcpyAsync(d_out, h, (size_t)QLEN * BATCH * DMODEL * sizeof(float),
                    cudaMemcpyDeviceToDevice);
}

// round 13
// speedup vs baseline: 1.1985x; 1.0089x over previous
#include <cuda_runtime.h>
#include <math.h>
#include <stdint.h>

#define QLEN 512
#define BATCH 4
#define DMODEL 1024
#define NLAYER 4
#define NHEAD 16
#define DHEAD 64
#define DINNER 4096
#define MLEN 512
#define KLEN 1024
#define BH (BATCH*NHEAD)

// ---------------- scratch ----------------
__device__ float g_cat[(size_t)KLEN*BATCH*DMODEL];
__device__ float g_heads[(size_t)KLEN*BATCH*3*DMODEL];
__device__ float g_r[(size_t)KLEN*DMODEL];
__device__ float g_ac[(size_t)BH*QLEN*KLEN];
__device__ float g_bd[(size_t)BH*QLEN*KLEN];
__device__ float g_av[(size_t)QLEN*BATCH*DMODEL];
__device__ float g_tmp[(size_t)QLEN*BATCH*DMODEL];
__device__ float g_tmp2[(size_t)QLEN*BATCH*DMODEL];
__device__ float g_h[(size_t)QLEN*BATCH*DMODEL];
__device__ float g_ff[(size_t)QLEN*BATCH*DINNER];
__device__ float g_qu[(size_t)BH*QLEN*DHEAD];
__device__ float g_qv[(size_t)BH*QLEN*DHEAD];
__device__ float g_rkc[(size_t)NHEAD*KLEN*DHEAD];
// tf32-rounded weight copies
__device__ float g_wqkv[(size_t)NLAYER*DMODEL*3072];
__device__ float g_wr[(size_t)NLAYER*DMODEL*DMODEL];
__device__ float g_wo[(size_t)NLAYER*DMODEL*DMODEL];
__device__ float g_w1[(size_t)NLAYER*DMODEL*DINNER];
__device__ float g_w2[(size_t)NLAYER*DINNER*DMODEL];

__device__ __forceinline__ uint32_t f2tf32(float f) {
    uint32_t o;
    asm("cvt.rna.tf32.f32 %0, %1;" : "=r"(o) : "f"(f));
    return o;
}
__device__ __forceinline__ float f2tf32f(float f) {
    uint32_t o = f2tf32(f);
    return __uint_as_float(o);
}

#define MMA_TF32(d, a, b) \
    asm volatile("mma.sync.aligned.m16n8k8.row.col.f32.tf32.tf32.f32 " \
                 "{%0,%1,%2,%3}, {%4,%5,%6,%7}, {%8,%9}, {%0,%1,%2,%3};" \
                 : "+f"(d[0]), "+f"(d[1]), "+f"(d[2]), "+f"(d[3]) \
                 : "r"(a.x), "r"(a.y), "r"(a.z), "r"(a.w), "r"(b.x), "r"(b.y))

__device__ __forceinline__ void cpasync16(uint32_t dst, const void* src) {
    asm volatile("cp.async.cg.shared.global [%0], [%1], 16;" :: "r"(dst), "l"(src));
}
#define CP_COMMIT() asm volatile("cp.async.commit_group;" ::: "memory")
__device__ __forceinline__ uint32_t smem_u32(const void* p) {
    uint32_t a;
    asm("{ .reg .u64 t; cvta.to.shared.u64 t, %1; cvt.u32.u64 %0, t; }" : "=r"(a) : "l"(p));
    return a;
}
#define SW128B(o) ((o) ^ (((o) >> 3) & 0x70))

// gemm4: 3 stages x (A 4096 + B 4096) words
#define G4_STAGE_W 8192
#define G4_SMEM (3 * G4_STAGE_W * 4)

// ======== gemm4: C[M,N]=A[M,K]@B[K,N]. 128 thr, CTA 128x128, warp 64x64 ========
template<int RELU, int HASBIAS, int CVT>
__global__ void __launch_bounds__(128) gemm4(
    const float* __restrict__ A, const float* __restrict__ B,
    const float* __restrict__ bias, float* __restrict__ C0, float* __restrict__ C1,
    int K, int lda, int ldb, int ldc)
{
    extern __shared__ uint32_t dsm[];
    const uint32_t sbase = smem_u32(dsm);
    const int tid = threadIdx.x, lane = tid & 31;
    const int warp = tid >> 5, wm = warp >> 1, wn = warp & 1;
    const int bx = blockIdx.x, by = blockIdx.y, bz = blockIdx.z;

    const int koff = bz * K;
    float* C = bz ? C1 : C0;

    const int a_row0 = tid >> 3, a_ch = tid & 7;
    const float* Ag = A + (size_t)(by * 128 + a_row0) * lda + koff + a_ch * 4;
    const int b_k = tid >> 2, b_nch0 = tid & 3;
    const float* Bg = B + (size_t)(koff + b_k) * ldb + bx * 128 + b_nch0 * 4;

    float acc[4][8][4];
#pragma unroll
    for (int mi = 0; mi < 4; mi++)
#pragma unroll
        for (int ni = 0; ni < 8; ni++)
#pragma unroll
            for (int r = 0; r < 4; r++) acc[mi][ni][r] = 0.f;

    const int lr = lane >> 2, lc = lane & 3;
    const int niter = K >> 5;

#define G4_LOAD(stg, k0) do { \
    uint32_t ab_ = sbase + (stg) * (G4_STAGE_W * 4); \
    _Pragma("unroll") for (int i = 0; i < 8; i++) { \
        uint32_t so_ = SW128B((uint32_t)((a_row0 + 16 * i) * 128 + a_ch * 16)); \
        cpasync16(ab_ + so_, Ag + (size_t)(16 * i) * lda + (k0)); \
    } \
    uint32_t bb_ = ab_ + 4096 * 4; \
    _Pragma("unroll") for (int i = 0; i < 8; i++) { \
        int n_ = (b_nch0 + 4 * i) * 4; \
        uint32_t w_ = (uint32_t)(b_k * 128 + (n_ ^ ((b_k & 3) << 3))); \
        cpasync16(bb_ + w_ * 4, Bg + (size_t)(k0) * ldb + 16 * i); \
    } \
    CP_COMMIT(); \
} while (0)

    G4_LOAD(0, 0);
    if (niter > 1) G4_LOAD(1, 32);

    for (int it = 0; it < niter; it++) {
        if (it + 1 < niter) {
            asm volatile("cp.async.wait_group 1;" ::: "memory");
        } else {
            asm volatile("cp.async.wait_group 0;" ::: "memory");
        }
        __syncthreads();
        if (it + 2 < niter) G4_LOAD((it + 2) % 3, (it + 2) * 32);

        const uint32_t* Abuf = dsm + (it % 3) * G4_STAGE_W;
        const uint32_t* Bbuf = Abuf + 4096;
#pragma unroll
        for (int kk = 0; kk < 4; kk++) {
            uint4 af[4]; uint2 bf[8];
#pragma unroll
            for (int mi = 0; mi < 4; mi++) {
                int row = wm * 64 + mi * 16 + lr;
                int k = kk * 8 + lc;
                af[mi].x = Abuf[SW128B((uint32_t)(row * 128 + k * 4)) >> 2];
                af[mi].y = Abuf[SW128B((uint32_t)((row + 8) * 128 + k * 4)) >> 2];
                af[mi].z = Abuf[SW128B((uint32_t)(row * 128 + (k + 4) * 4)) >> 2];
                af[mi].w = Abuf[SW128B((uint32_t)((row + 8) * 128 + (k + 4) * 4)) >> 2];
            }
#pragma unroll
            for (int ni = 0; ni < 8; ni++) {
                int n = wn * 64 + ni * 8 + lr;
                int kb = kk * 8 + lc;
                int nsw = n ^ (lc << 3);
                bf[ni].x = Bbuf[kb * 128 + nsw];
                bf[ni].y = Bbuf[(kb + 4) * 128 + nsw];
            }
#pragma unroll
            for (int mi = 0; mi < 4; mi++)
#pragma unroll
                for (int ni = 0; ni < 8; ni++) MMA_TF32(acc[mi][ni], af[mi], bf[ni]);
        }
    }
#undef G4_LOAD

    const bool dobias = HASBIAS && (bz == 0);
#pragma unroll
    for (int mi = 0; mi < 4; mi++) {
#pragma unroll
        for (int ni = 0; ni < 8; ni++) {
            int row0 = by * 128 + wm * 64 + mi * 16 + lr;
            int col  = bx * 128 + wn * 64 + ni * 8 + lc * 2;
            float b0 = 0.f, b1 = 0.f;
            if (dobias) { b0 = bias[col]; b1 = bias[col + 1]; }
            float v0 = acc[mi][ni][0] + b0, v1 = acc[mi][ni][1] + b1;
            float v2 = acc[mi][ni][2] + b0, v3 = acc[mi][ni][3] + b1;
            if (RELU) {
                v0 = fmaxf(v0, 0.f); v1 = fmaxf(v1, 0.f);
                v2 = fmaxf(v2, 0.f); v3 = fmaxf(v3, 0.f);
            }
            if (CVT) {
                v0 = f2tf32f(v0); v1 = f2tf32f(v1);
                v2 = f2tf32f(v2); v3 = f2tf32f(v3);
            }
            *(float2*)(C + (size_t)row0 * ldc + col)       = make_float2(v0, v1);
            *(float2*)(C + (size_t)(row0 + 8) * ldc + col) = make_float2(v2, v3);
        }
    }
}

// ======== qrk_gemm: merged Q-projection + rk-projection (both split-K=2) ========
// z=0,1: Q halves (grid y 0..15); z=2,3: rk halves (grid y 0..7, else return)
__global__ void __launch_bounds__(128) qrk_gemm(
    const float* __restrict__ Aq, const float* __restrict__ Bq,
    float* __restrict__ Cq0, float* __restrict__ Cq1,
    const float* __restrict__ Ar, const float* __restrict__ Br,
    float* __restrict__ Cr0, float* __restrict__ Cr1)
{
    extern __shared__ uint32_t dsm[];
    const uint32_t sbase = smem_u32(dsm);
    const int tid = threadIdx.x, lane = tid & 31;
    const int warp = tid >> 5, wm = warp >> 1, wn = warp & 1;
    const int bx = blockIdx.x, by = blockIdx.y, bz = blockIdx.z;

    const float* A; const float* B; float* C;
    int lda, ldb, koff;
    if (bz < 2) {
        A = Aq; B = Bq; C = bz ? Cq1 : Cq0;
        lda = 1024; ldb = 3072; koff = bz * 512;
    } else {
        if (by >= 8) return;
        A = Ar; B = Br; C = (bz - 2) ? Cr1 : Cr0;
        lda = 1024; ldb = 1024; koff = (bz - 2) * 512;
    }
    const int ldc = 1024;

    const int a_row0 = tid >> 3, a_ch = tid & 7;
    const float* Ag = A + (size_t)(by * 128 + a_row0) * lda + koff + a_ch * 4;
    const int b_k = tid >> 2, b_nch0 = tid & 3;
    const float* Bg = B + (size_t)(koff + b_k) * ldb + bx * 128 + b_nch0 * 4;

    float acc[4][8][4];
#pragma unroll
    for (int mi = 0; mi < 4; mi++)
#pragma unroll
        for (int ni = 0; ni < 8; ni++)
#pragma unroll
            for (int r = 0; r < 4; r++) acc[mi][ni][r] = 0.f;

    const int lr = lane >> 2, lc = lane & 3;
    const int niter = 16;   // K=512

#define QR_LOAD(stg, k0) do { \
    uint32_t ab_ = sbase + (stg) * (G4_STAGE_W * 4); \
    _Pragma("unroll") for (int i = 0; i < 8; i++) { \
        uint32_t so_ = SW128B((uint32_t)((a_row0 + 16 * i) * 128 + a_ch * 16)); \
        cpasync16(ab_ + so_, Ag + (size_t)(16 * i) * lda + (k0)); \
    } \
    uint32_t bb_ = ab_ + 4096 * 4; \
    _Pragma("unroll") for (int i = 0; i < 8; i++) { \
        int n_ = (b_nch0 + 4 * i) * 4; \
        uint32_t w_ = (uint32_t)(b_k * 128 + (n_ ^ ((b_k & 3) << 3))); \
        cpasync16(bb_ + w_ * 4, Bg + (size_t)(k0) * ldb + 16 * i); \
    } \
    CP_COMMIT(); \
} while (0)

    QR_LOAD(0, 0);
    QR_LOAD(1, 32);

    for (int it = 0; it < niter; it++) {
        if (it + 1 < niter) {
            asm volatile("cp.async.wait_group 1;" ::: "memory");
        } else {
            asm volatile("cp.async.wait_group 0;" ::: "memory");
        }
        __syncthreads();
        if (it + 2 < niter) QR_LOAD((it + 2) % 3, (it + 2) * 32);

        const uint32_t* Abuf = dsm + (it % 3) * G4_STAGE_W;
        const uint32_t* Bbuf = Abuf + 4096;
#pragma unroll
        for (int kk = 0; kk < 4; kk++) {
            uint4 af[4]; uint2 bf[8];
#pragma unroll
            for (int mi = 0; mi < 4; mi++) {
                int row = wm * 64 + mi * 16 + lr;
                int k = kk * 8 + lc;
                af[mi].x = Abuf[SW128B((uint32_t)(row * 128 + k * 4)) >> 2];
                af[mi].y = Abuf[SW128B((uint32_t)((row + 8) * 128 + k * 4)) >> 2];
                af[mi].z = Abuf[SW128B((uint32_t)(row * 128 + (k + 4) * 4)) >> 2];
                af[mi].w = Abuf[SW128B((uint32_t)((row + 8) * 128 + (k + 4) * 4)) >> 2];
            }
#pragma unroll
            for (int ni = 0; ni < 8; ni++) {
                int n = wn * 64 + ni * 8 + lr;
                int kb = kk * 8 + lc;
                int nsw = n ^ (lc << 3);
                bf[ni].x = Bbuf[kb * 128 + nsw];
                bf[ni].y = Bbuf[(kb + 4) * 128 + nsw];
            }
#pragma unroll
            for (int mi = 0; mi < 4; mi++)
#pragma unroll
                for (int ni = 0; ni < 8; ni++) MMA_TF32(acc[mi][ni], af[mi], bf[ni]);
        }
    }
#undef QR_LOAD

#pragma unroll
    for (int mi = 0; mi < 4; mi++)
#pragma unroll
        for (int ni = 0; ni < 8; ni++) {
            int row0 = by * 128 + wm * 64 + mi * 16 + lr;
            int col  = bx * 128 + wn * 64 + ni * 8 + lc * 2;
            *(float2*)(C + (size_t)row0 * ldc + col) =
                make_float2(acc[mi][ni][0], acc[mi][ni][1]);
            *(float2*)(C + (size_t)(row0 + 8) * ldc + col) =
                make_float2(acc[mi][ni][2], acc[mi][ni][3]);
        }
}

// ======== score_both: AC (mode 0) and BD (mode 1) in one launch ========
#define SC_SMEM (4 * 4096 * 4)
__global__ void __launch_bounds__(128) score_both(
    const float* __restrict__ qu, const float* __restrict__ qv,
    const float* __restrict__ heads, const float* __restrict__ rkc,
    float* __restrict__ ac, float* __restrict__ bd)
{
    const int bx = blockIdx.x, by = blockIdx.y, z = blockIdx.z;
    const int mode = (z >= BH) ? 1 : 0;
    const int bh = mode ? z - BH : z;
    const int i0 = by * 128, j0 = bx * 128;
    if (mode == 0) { if (j0 >= i0 + 640) return; }
    else           { if (i0 + j0 < 257) return; }
    const int bb = bh >> 4, nn = bh & 15;
    const float* A = (mode ? qv : qu) + (size_t)bh * QLEN * 64 + (size_t)i0 * 64;
    const float* B;
    size_t ldbB;
    if (mode == 0) {
        B = heads + (size_t)(j0 * 4 + bb) * 3072 + 1024 + (size_t)nn * 64;
        ldbB = 4 * 3072;
    } else {
        B = rkc + (size_t)nn * KLEN * 64 + (size_t)j0 * 64;
        ldbB = 64;
    }
    float* out = mode ? bd : ac;

    extern __shared__ uint32_t dsm[];
    const uint32_t sbase = smem_u32(dsm);
    const int tid = threadIdx.x, lane = tid & 31;
    const int warp = tid >> 5, wm = warp >> 1, wn = warp & 1;

    const int a_row0 = tid >> 3, a_ch = tid & 7;
    const float* Ag = A + (size_t)a_row0 * 64 + a_ch * 4;
    const float* Bg = B + (size_t)a_row0 * ldbB + a_ch * 4;

    float acc[4][8][4];
#pragma unroll
    for (int mi = 0; mi < 4; mi++)
#pragma unroll
        for (int ni = 0; ni < 8; ni++)
#pragma unroll
            for (int r = 0; r < 4; r++) acc[mi][ni][r] = 0.f;

    const int lr = lane >> 2, lc = lane & 3;

#define SC_LOAD(stg, k0) do { \
    uint32_t ab_ = sbase + (stg) * 32768; \
    uint32_t bb_ = ab_ + 16384; \
    _Pragma("unroll") for (int i = 0; i < 8; i++) { \
        uint32_t so_ = SW128B((uint32_t)((a_row0 + 16 * i) * 128 + a_ch * 16)); \
        cpasync16(ab_ + so_, Ag + (size_t)(16 * i) * 64 + (k0)); \
        cpasync16(bb_ + so_, Bg + (size_t)(16 * i) * ldbB + (k0)); \
    } \
    CP_COMMIT(); \
} while (0)

    SC_LOAD(0, 0);
    SC_LOAD(1, 32);

#pragma unroll
    for (int it = 0; it < 2; it++) {
        if (it == 0) asm volatile("cp.async.wait_group 1;" ::: "memory");
        else         asm volatile("cp.async.wait_group 0;" ::: "memory");
        __syncthreads();
        const uint32_t* Abuf = dsm + it * 8192;
        const uint32_t* Bbuf = Abuf + 4096;
#pragma unroll
        for (int kk = 0; kk < 4; kk++) {
            uint4 af[4]; uint2 bf[8];
#pragma unroll
            for (int mi = 0; mi < 4; mi++) {
                int row = wm * 64 + mi * 16 + lr;
                int k = kk * 8 + lc;
                af[mi].x = Abuf[SW128B((uint32_t)(row * 128 + k * 4)) >> 2];
                af[mi].y = Abuf[SW128B((uint32_t)((row + 8) * 128 + k * 4)) >> 2];
                af[mi].z = Abuf[SW128B((uint32_t)(row * 128 + (k + 4) * 4)) >> 2];
                af[mi].w = Abuf[SW128B((uint32_t)((row + 8) * 128 + (k + 4) * 4)) >> 2];
            }
#pragma unroll
            for (int ni = 0; ni < 8; ni++) {
                int n = wn * 64 + ni * 8 + lr;
                int k = kk * 8 + lc;
                bf[ni].x = Bbuf[SW128B((uint32_t)(n * 128 + k * 4)) >> 2];
                bf[ni].y = Bbuf[SW128B((uint32_t)(n * 128 + (k + 4) * 4)) >> 2];
            }
#pragma unroll
            for (int mi = 0; mi < 4; mi++)
#pragma unroll
                for (int ni = 0; ni < 8; ni++) MMA_TF32(acc[mi][ni], af[mi], bf[ni]);
        }
    }
#undef SC_LOAD

    float* ob = out + (size_t)bh * QLEN * KLEN;
#pragma unroll
    for (int mi = 0; mi < 4; mi++)
#pragma unroll
        for (int ni = 0; ni < 8; ni++) {
            int row0 = i0 + wm * 64 + mi * 16 + lr;
            int col  = j0 + wn * 64 + ni * 8 + lc * 2;
            *(float2*)(ob + (size_t)row0 * KLEN + col) =
                make_float2(acc[mi][ni][0], acc[mi][ni][1]);
            *(float2*)(ob + (size_t)(row0 + 8) * KLEN + col) =
                make_float2(acc[mi][ni][2], acc[mi][ni][3]);
        }
}

// ======== av2: av = P[128, kmax] @ V[kmax, 64], V streamed from heads ========
#define AV2_STAGE_W 6144
#define AV2_SMEM (3 * AV2_STAGE_W * 4)
__global__ void __launch_bounds__(128) av2(
    const float* __restrict__ P, const float* __restrict__ heads, float* __restrict__ av)
{
    extern __shared__ uint32_t dsm[];
    const uint32_t sbase = smem_u32(dsm);
    const int by = blockIdx.x, bh = blockIdx.y;
    const int b = bh >> 4, n_h = bh & 15;
    const float* A = P + (size_t)bh * QLEN * KLEN + (size_t)by * 128 * KLEN;
    const float* Vb = heads + (size_t)b * 3072 + 2048 + (size_t)n_h * 64;
    const size_t ldv = 4 * 3072;
    const int kmax = min(KLEN, by * 128 + 640);

    const int tid = threadIdx.x, lane = tid & 31;
    const int warp = tid >> 5, wm = warp >> 1, wn = warp & 1;

    const int a_row0 = tid >> 3, a_ch = tid & 7;
    const float* Ag = A + (size_t)a_row0 * KLEN + a_ch * 4;
    const int b_k = tid >> 2, b_nch0 = tid & 3;
    const float* Bg = Vb + (size_t)b_k * ldv + b_nch0 * 4;

    float acc[4][4][4];
#pragma unroll
    for (int mi = 0; mi < 4; mi++)
#pragma unroll
        for (int ni = 0; ni < 4; ni++)
#pragma unroll
            for (int r = 0; r < 4; r++) acc[mi][ni][r] = 0.f;

    const int lr = lane >> 2, lc = lane & 3;
    const int niter = kmax >> 5;

#define AV2_LOAD(stg, k0) do { \
    uint32_t ab_ = sbase + (stg) * (AV2_STAGE_W * 4); \
    _Pragma("unroll") for (int i = 0; i < 8; i++) { \
        uint32_t so_ = SW128B((uint32_t)((a_row0 + 16 * i) * 128 + a_ch * 16)); \
        cpasync16(ab_ + so_, Ag + (size_t)(16 * i) * KLEN + (k0)); \
    } \
    uint32_t bb_ = ab_ + 4096 * 4; \
    _Pragma("unroll") for (int i = 0; i < 4; i++) { \
        int n_ = (b_nch0 + 4 * i) * 4; \
        uint32_t w_ = (uint32_t)(b_k * 64 + (n_ ^ ((b_k & 3) << 3))); \
        cpasync16(bb_ + w_ * 4, Bg + (size_t)(k0) * ldv + 16 * i); \
    } \
    CP_COMMIT(); \
} while (0)

    AV2_LOAD(0, 0);
    if (niter > 1) AV2_LOAD(1, 32);

    for (int it = 0; it < niter; it++) {
        if (it + 1 < niter) {
            asm volatile("cp.async.wait_group 1;" ::: "memory");
        } else {
            asm volatile("cp.async.wait_group 0;" ::: "memory");
        }
        __syncthreads();
        if (it + 2 < niter) AV2_LOAD((it + 2) % 3, (it + 2) * 32);

        const uint32_t* Abuf = dsm + (it % 3) * AV2_STAGE_W;
        const uint32_t* Bbuf = Abuf + 4096;
#pragma unroll
        for (int kk = 0; kk < 4; kk++) {
            uint4 af[4]; uint2 bf[4];
#pragma unroll
            for (int mi = 0; mi < 4; mi++) {
                int row = wm * 64 + mi * 16 + lr;
                int k = kk * 8 + lc;
                af[mi].x = Abuf[SW128B((uint32_t)(row * 128 + k * 4)) >> 2];
                af[mi].y = Abuf[SW128B((uint32_t)((row + 8) * 128 + k * 4)) >> 2];
                af[mi].z = Abuf[SW128B((uint32_t)(row * 128 + (k + 4) * 4)) >> 2];
                af[mi].w = Abuf[SW128B((uint32_t)((row + 8) * 128 + (k + 4) * 4)) >> 2];
            }
#pragma unroll
            for (int ni = 0; ni < 4; ni++) {
                int n = wn * 32 + ni * 8 + lr;
                int kb = kk * 8 + lc;
                int nsw = n ^ (lc << 3);
                bf[ni].x = Bbuf[kb * 64 + nsw];
                bf[ni].y = Bbuf[(kb + 4) * 64 + nsw];
            }
#pragma unroll
            for (int mi = 0; mi < 4; mi++)
#pragma unroll
                for (int ni = 0; ni < 4; ni++) MMA_TF32(acc[mi][ni], af[mi], bf[ni]);
        }
    }
#undef AV2_LOAD

#pragma unroll
    for (int mi = 0; mi < 4; mi++)
#pragma unroll
        for (int ni = 0; ni < 4; ni++) {
            int row0 = by * 128 + wm * 64 + mi * 16 + lr;
            int col  = wn * 32 + ni * 8 + lc * 2;
            *(float2*)(av + ((size_t)row0 * 4 + b) * 1024 + n_h * 64 + col) =
                make_float2(f2tf32f(acc[mi][ni][0]), f2tf32f(acc[mi][ni][1]));
            *(float2*)(av + ((size_t)(row0 + 8) * 4 + b) * 1024 + n_h * 64 + col) =
                make_float2(f2tf32f(acc[mi][ni][2]), f2tf32f(acc[mi][ni][3]));
        }
}

// ---------------- fused weight rounding (all 5 tensors, one launch) ----------------
__global__ void roundw5_kernel(
    float4* d0, const float4* s0, size_t n0,
    float4* d1, const float4* s1, size_t n1,
    float4* d2, const float4* s2, size_t n2,
    float4* d3, const float4* s3, size_t n3,
    float4* d4, const float4* s4, size_t n4)
{
    size_t i = (size_t)blockIdx.x * 256 + threadIdx.x;
    float4* d; const float4* s;
    if (i < n0) { d = d0; s = s0; }
    else { i -= n0;
    if (i < n1) { d = d1; s = s1; }
    else { i -= n1;
    if (i < n2) { d = d2; s = s2; }
    else { i -= n2;
    if (i < n3) { d = d3; s = s3; }
    else { i -= n3;
    if (i < n4) { d = d4; s = s4; }
    else return; }}}}
    float4 v = s[i];
    d[i] = make_float4(f2tf32f(v.x), f2tf32f(v.y), f2tf32f(v.z), f2tf32f(v.w));
}

// ---------------- small kernels ----------------
__global__ void posemb_kernel(float* __restrict__ r) {
    int idx = blockIdx.x * 256 + threadIdx.x;
    int k = idx >> 10, d = idx & 1023;
    float pos = (float)(KLEN - 1 - k);
    int j = (d < 512) ? d : d - 512;
    float inv = expf(-((float)(2 * j) / 1024.0f) * 9.210340371976184f);
    float ang = pos * inv;
    r[idx] = f2tf32f((d < 512) ? sinf(ang) : cosf(ang));
}

__global__ void copy4_kernel(float4* __restrict__ dst, const float4* __restrict__ src) {
    size_t i = (size_t)blockIdx.x * 256 + threadIdx.x;
    dst[i] = src[i];
}

__global__ void concat_kernel(float4* __restrict__ cat, const float4* __restrict__ mem,
                              const float4* __restrict__ h) {
    size_t i = (size_t)blockIdx.x * 256 + threadIdx.x;
    const size_t half = (size_t)MLEN * BATCH * DMODEL / 4;
    float4 v = (i < half) ? mem[i] : h[i - half];
    cat[i] = make_float4(f2tf32f(v.x), f2tf32f(v.y), f2tf32f(v.z), f2tf32f(v.w));
}

// q = split-K partials q0+q1; outputs rounded tf32
__global__ void repack_quqv(const float* __restrict__ q0, const float* __restrict__ q1,
                            const float* __restrict__ u, const float* __restrict__ v,
                            float* __restrict__ qu, float* __restrict__ qv) {
    int idx = blockIdx.x * 256 + threadIdx.x;
    int d4 = idx & 15, i = (idx >> 4) & 511, bh = idx >> 13;
    int b = bh >> 4, n = bh & 15;
    size_t qoff = ((size_t)(i * 4 + b)) * 1024 + n * 64 + d4 * 4;
    float4 qa = *(const float4*)(q0 + qoff);
    float4 qb = *(const float4*)(q1 + qoff);
    float4 uu = *(const float4*)(u + n * 64 + d4 * 4);
    float4 vv = *(const float4*)(v + n * 64 + d4 * 4);
    float qx = qa.x + qb.x, qy = qa.y + qb.y, qz = qa.z + qb.z, qw = qa.w + qb.w;
    size_t o = ((size_t)bh * 512 + i) * 64 + d4 * 4;
    *(float4*)(qu + o) = make_float4(f2tf32f(qx + uu.x), f2tf32f(qy + uu.y),
                                     f2tf32f(qz + uu.z), f2tf32f(qw + uu.w));
    *(float4*)(qv + o) = make_float4(f2tf32f(qx + vv.x), f2tf32f(qy + vv.y),
                                     f2tf32f(qz + vv.z), f2tf32f(qw + vv.w));
}

// rk = split-K partials p0+p1 ([j][1024]); output [n][j][64], rounded
__global__ void repack_rk(const float* __restrict__ p0, const float* __restrict__ p1,
                          float* __restrict__ rkc) {
    int idx = blockIdx.x * 256 + threadIdx.x;
    int d4 = idx & 15, j = (idx >> 4) & 1023, n = idx >> 14;
    size_t off = (size_t)j * 1024 + n * 64 + d4 * 4;
    float4 a = *(const float4*)(p0 + off);
    float4 b = *(const float4*)(p1 + off);
    *(float4*)(rkc + ((size_t)n * 1024 + j) * 64 + d4 * 4) =
        make_float4(f2tf32f(a.x + b.x), f2tf32f(a.y + b.y),
                    f2tf32f(a.z + b.z), f2tf32f(a.w + b.w));
}

// ---------------- softmax (shift+mask+scale fused; chunk-3 skip for i<256) -------
__global__ void __launch_bounds__(256) softmax_kernel(float* ac, const float* __restrict__ bd) {
    int i = blockIdx.x;
    int bh = blockIdx.y;
    float* acrow = ac + ((size_t)bh * QLEN + i) * KLEN;
    const float* bdrow = bd + ((size_t)bh * QLEN + i) * KLEN;
    int tid = threadIdx.x;
    __shared__ float red[256];
    int jmax = i + MLEN;
    int shift = QLEN - 1 - i;
    const bool skip3 = (i < 256);   // av2 never reads cols >=768 for these rows
    float v[4];
    float m = -1e30f;
#pragma unroll
    for (int c = 0; c < 3; c++) {
        int j = c * 256 + tid;
        float s = (j <= jmax) ? 0.125f * (acrow[j] + bdrow[j + shift]) : -1e30f;
        v[c] = s;
        m = fmaxf(m, s);
    }
    if (!skip3) {
        int j = 768 + tid;
        float s = (j <= jmax) ? 0.125f * (acrow[j] + bdrow[j + shift]) : -1e30f;
        v[3] = s;
        m = fmaxf(m, s);
    } else v[3] = -1e30f;
    red[tid] = m; __syncthreads();
    for (int o = 128; o > 0; o >>= 1) {
        if (tid < o) red[tid] = fmaxf(red[tid], red[tid + o]);
        __syncthreads();
    }
    m = red[0]; __syncthreads();
    float sum = 0.f;
#pragma unroll
    for (int c = 0; c < 4; c++) { v[c] = expf(v[c] - m); sum += v[c]; }
    red[tid] = sum; __syncthreads();
    for (int o = 128; o > 0; o >>= 1) {
        if (tid < o) red[tid] += red[tid + o];
        __syncthreads();
    }
    float inv = 1.0f / red[0];
#pragma unroll
    for (int c = 0; c < 3; c++) acrow[c * 256 + tid] = f2tf32f(v[c] * inv);
    if (!skip3) acrow[768 + tid] = f2tf32f(v[3] * inv);
}

// ---------------- residual + 2 partials + LayerNorm (output rounded) ----------------
__global__ void __launch_bounds__(256) add_ln3_kernel(
    float* __restrict__ h, const float* __restrict__ t0, const float* __restrict__ t1,
    const float* __restrict__ g, const float* __restrict__ b)
{
    int row = blockIdx.x;
    int tid = threadIdx.x;
    __shared__ float rs[256], rs2[256];
    float x[4];
    float s = 0.f, ss = 0.f;
#pragma unroll
    for (int c = 0; c < 4; c++) {
        int d = c * 256 + tid;
        size_t o = (size_t)row * 1024 + d;
        float v = h[o] + t0[o] + t1[o];
        x[c] = v; s += v; ss += v * v;
    }
    rs[tid] = s; rs2[tid] = ss; __syncthreads();
    for (int o = 128; o > 0; o >>= 1) {
        if (tid < o) { rs[tid] += rs[tid + o]; rs2[tid] += rs2[tid + o]; }
        __syncthreads();
    }
    float mu = rs[0] * (1.0f / 1024.0f);
    float var = rs2[0] * (1.0f / 1024.0f) - mu * mu;
    float inv = rsqrtf(var + 1e-5f);
#pragma unroll
    for (int c = 0; c < 4; c++) {
        int d = c * 256 + tid;
        h[(size_t)row * 1024 + d] = f2tf32f((x[c] - mu) * inv * g[d] + b[d]);
    }
}

// ---------------- launch ----------------
extern "C" void kernel_launch(void* const* d_in, const int* in_sizes, int n_in,
                              void* d_out, int out_size) {
    (void)in_sizes; (void)n_in; (void)out_size;
    const float* x     = (const float*)d_in[0];
    const float* mems  = (const float*)d_in[1];
    const float* u     = (const float*)d_in[2];
    const float* v     = (const float*)d_in[3];
    const float* W_qkv = (const float*)d_in[4];
    const float* W_o   = (const float*)d_in[5];
    const float* W_r   = (const float*)d_in[6];
    const float* ln1_g = (const float*)d_in[7];
    const float* ln1_b = (const float*)d_in[8];
    const float* W1    = (const float*)d_in[9];
    const float* b1    = (const float*)d_in[10];
    const float* W2    = (const float*)d_in[11];
    const float* b2    = (const float*)d_in[12];
    const float* ln2_g = (const float*)d_in[13];
    const float* ln2_b = (const float*)d_in[14];

    float *cat, *heads, *r, *ac, *bd, *av, *tmp, *tmp2, *h, *ff, *qu, *qv, *rkc;
    float *wqkv, *wr, *wo, *w1, *w2;
    cudaGetSymbolAddress((void**)&cat,   g_cat);
    cudaGetSymbolAddress((void**)&heads, g_heads);
    cudaGetSymbolAddress((void**)&r,     g_r);
    cudaGetSymbolAddress((void**)&ac,    g_ac);
    cudaGetSymbolAddress((void**)&bd,    g_bd);
    cudaGetSymbolAddress((void**)&av,    g_av);
    cudaGetSymbolAddress((void**)&tmp,   g_tmp);
    cudaGetSymbolAddress((void**)&tmp2,  g_tmp2);
    cudaGetSymbolAddress((void**)&h,     g_h);
    cudaGetSymbolAddress((void**)&ff,    g_ff);
    cudaGetSymbolAddress((void**)&qu,    g_qu);
    cudaGetSymbolAddress((void**)&qv,    g_qv);
    cudaGetSymbolAddress((void**)&rkc,   g_rkc);
    cudaGetSymbolAddress((void**)&wqkv,  g_wqkv);
    cudaGetSymbolAddress((void**)&wr,    g_wr);
    cudaGetSymbolAddress((void**)&wo,    g_wo);
    cudaGetSymbolAddress((void**)&w1,    g_w1);
    cudaGetSymbolAddress((void**)&w2,    g_w2);

    cudaFuncSetAttribute(gemm4<0,0,0>, cudaFuncAttributeMaxDynamicSharedMemorySize, G4_SMEM);
    cudaFuncSetAttribute(gemm4<0,0,1>, cudaFuncAttributeMaxDynamicSharedMemorySize, G4_SMEM);
    cudaFuncSetAttribute(gemm4<1,1,1>, cudaFuncAttributeMaxDynamicSharedMemorySize, G4_SMEM);
    cudaFuncSetAttribute(gemm4<0,1,0>, cudaFuncAttributeMaxDynamicSharedMemorySize, G4_SMEM);
    cudaFuncSetAttribute(qrk_gemm,     cudaFuncAttributeMaxDynamicSharedMemorySize, G4_SMEM);
    cudaFuncSetAttribute(score_both,   cudaFuncAttributeMaxDynamicSharedMemorySize, SC_SMEM);
    cudaFuncSetAttribute(av2,          cudaFuncAttributeMaxDynamicSharedMemorySize, AV2_SMEM);

    // one-time weight rounding (single fused launch)
    {
        size_t n0 = (size_t)NLAYER*DMODEL*3072/4, n1 = (size_t)NLAYER*DMODEL*DMODEL/4;
        size_t n2 = n1, n3 = (size_t)NLAYER*DMODEL*DINNER/4, n4 = n3;
        size_t ntot = n0 + n1 + n2 + n3 + n4;
        roundw5_kernel<<<(unsigned)((ntot + 255) / 256), 256>>>(
            (float4*)wqkv, (const float4*)W_qkv, n0,
            (float4*)wr,   (const float4*)W_r,   n1,
            (float4*)wo,   (const float4*)W_o,   n2,
            (float4*)w1,   (const float4*)W1,    n3,
            (float4*)w2,   (const float4*)W2,    n4);
    }

    posemb_kernel<<<4096, 256>>>(r);
    copy4_kernel<<<2048, 256>>>((float4*)h, (const float4*)x);

    for (int l = 0; l < NLAYER; l++) {
        const float* Wq = wqkv + (size_t)l * DMODEL * 3072;
        concat_kernel<<<4096, 256>>>((float4*)cat,
                                     (const float4*)(mems + (size_t)l * MLEN * BATCH * DMODEL),
                                     (const float4*)h);
        // K,V: all 4096 rows, cols 1024..3071 — rounded output (consumed in place)
        gemm4<0,0,1><<<dim3(16, 32, 1), 128, G4_SMEM>>>(
            cat, Wq + 1024, nullptr, heads + 1024, nullptr, 1024, 1024, 3072, 3072);
        // Q (split-K=2) + rk (split-K=2), one launch
        qrk_gemm<<<dim3(8, 16, 4), 128, G4_SMEM>>>(
            cat + (size_t)2048 * 1024, Wq, tmp, tmp2,
            r, wr + (size_t)l * DMODEL * DMODEL, bd, bd + (size_t)1024 * 1024);
        // repacks
        repack_quqv<<<2048, 256>>>(tmp, tmp2, u, v, qu, qv);
        repack_rk<<<1024, 256>>>(bd, bd + (size_t)1024 * 1024, rkc);
        // scores: AC + BD in one launch
        score_both<<<dim3(8, 4, 2 * BH), 128, SC_SMEM>>>(qu, qv, heads, rkc, ac, bd);
        softmax_kernel<<<dim3(QLEN, BH), 256>>>(ac, bd);
        // AV (V streamed directly from heads)
        av2<<<dim3(4, BH), 128, AV2_SMEM>>>(ac, heads, av);
        // O projection: split-K=2
        gemm4<0,0,0><<<dim3(8, 16, 2), 128, G4_SMEM>>>(
            av, wo + (size_t)l * DMODEL * DMODEL, nullptr, tmp, tmp2,
            512, 1024, 1024, 1024);
        add_ln3_kernel<<<2048, 256>>>(h, tmp, tmp2,
                                      ln1_g + (size_t)l * DMODEL, ln1_b + (size_t)l * DMODEL);
        // FFN
        gemm4<1,1,1><<<dim3(32, 16, 1), 128, G4_SMEM>>>(
            h, w1 + (size_t)l * DMODEL * DINNER, b1 + (size_t)l * DINNER, ff, nullptr,
            1024, 1024, 4096, 4096);
        gemm4<0,1,0><<<dim3(8, 16, 2), 128, G4_SMEM>>>(
            ff, w2 + (size_t)l * DINNER * DMODEL, b2 + (size_t)l * DMODEL, tmp, tmp2,
            2048, 4096, 1024, 1024);
        add_ln3_kernel<<<2048, 256>>>(h, tmp, tmp2,
                                      ln2_g + (size_t)l * DMODEL, ln2_b + (size_t)l * DMODEL);
    }

    cudaMemcpyAsync(d_out, h, (size_t)QLEN * BATCH * DMODEL * sizeof(float),
                    cudaMemcpyDeviceToDevice);
}

// round 14
// speedup vs baseline: 1.1986x; 1.0001x over previous
#include <cuda_runtime.h>
#include <math.h>
#include <stdint.h>

#define QLEN 512
#define BATCH 4
#define DMODEL 1024
#define NLAYER 4
#define NHEAD 16
#define DHEAD 64
#define DINNER 4096
#define MLEN 512
#define KLEN 1024
#define BH (BATCH*NHEAD)

// ---------------- scratch ----------------
__device__ float g_cat[(size_t)KLEN*BATCH*DMODEL];
__device__ float g_heads[(size_t)KLEN*BATCH*3*DMODEL];
__device__ float g_r[(size_t)KLEN*DMODEL];
__device__ float g_ac[(size_t)BH*QLEN*KLEN];
__device__ float g_bd[(size_t)BH*QLEN*KLEN];
__device__ float g_av[(size_t)QLEN*BATCH*DMODEL];
__device__ float g_tmp[(size_t)QLEN*BATCH*DMODEL];
__device__ float g_tmp2[(size_t)QLEN*BATCH*DMODEL];
__device__ float g_h[(size_t)QLEN*BATCH*DMODEL];
__device__ float g_ff[(size_t)QLEN*BATCH*DINNER];
__device__ float g_qu[(size_t)BH*QLEN*DHEAD];
__device__ float g_qv[(size_t)BH*QLEN*DHEAD];
__device__ float g_rkc[(size_t)NHEAD*KLEN*DHEAD];
// tf32-rounded weight copies
__device__ float g_wqkv[(size_t)NLAYER*DMODEL*3072];
__device__ float g_wr[(size_t)NLAYER*DMODEL*DMODEL];
__device__ float g_wo[(size_t)NLAYER*DMODEL*DMODEL];
__device__ float g_w1[(size_t)NLAYER*DMODEL*DINNER];
__device__ float g_w2[(size_t)NLAYER*DINNER*DMODEL];

__device__ __forceinline__ uint32_t f2tf32(float f) {
    uint32_t o;
    asm("cvt.rna.tf32.f32 %0, %1;" : "=r"(o) : "f"(f));
    return o;
}
__device__ __forceinline__ float f2tf32f(float f) {
    uint32_t o = f2tf32(f);
    return __uint_as_float(o);
}

#define MMA_TF32(d, a, b) \
    asm volatile("mma.sync.aligned.m16n8k8.row.col.f32.tf32.tf32.f32 " \
                 "{%0,%1,%2,%3}, {%4,%5,%6,%7}, {%8,%9}, {%0,%1,%2,%3};" \
                 : "+f"(d[0]), "+f"(d[1]), "+f"(d[2]), "+f"(d[3]) \
                 : "r"(a.x), "r"(a.y), "r"(a.z), "r"(a.w), "r"(b.x), "r"(b.y))

__device__ __forceinline__ void cpasync16(uint32_t dst, const void* src) {
    asm volatile("cp.async.cg.shared.global [%0], [%1], 16;" :: "r"(dst), "l"(src));
}
#define CP_COMMIT() asm volatile("cp.async.commit_group;" ::: "memory")
__device__ __forceinline__ uint32_t smem_u32(const void* p) {
    uint32_t a;
    asm("{ .reg .u64 t; cvta.to.shared.u64 t, %1; cvt.u32.u64 %0, t; }" : "=r"(a) : "l"(p));
    return a;
}
#define SW128B(o) ((o) ^ (((o) >> 3) & 0x70))

// gemm4: 3 stages x (A 4096 + B 4096) words
#define G4_STAGE_W 8192
#define G4_SMEM (3 * G4_STAGE_W * 4)

// ======== gemm4: C[M,N]=A[M,K]@B[K,N]. 128 thr, CTA 128x128, warp 64x64 ========
template<int RELU, int HASBIAS, int CVT>
__global__ void __launch_bounds__(128) gemm4(
    const float* __restrict__ A, const float* __restrict__ B,
    const float* __restrict__ bias, float* __restrict__ C0, float* __restrict__ C1,
    int K, int lda, int ldb, int ldc)
{
    extern __shared__ uint32_t dsm[];
    const uint32_t sbase = smem_u32(dsm);
    const int tid = threadIdx.x, lane = tid & 31;
    const int warp = tid >> 5, wm = warp >> 1, wn = warp & 1;
    const int bx = blockIdx.x, by = blockIdx.y, bz = blockIdx.z;

    const int koff = bz * K;
    float* C = bz ? C1 : C0;

    const int a_row0 = tid >> 3, a_ch = tid & 7;
    const float* Ag = A + (size_t)(by * 128 + a_row0) * lda + koff + a_ch * 4;
    const int b_k = tid >> 2, b_nch0 = tid & 3;
    const float* Bg = B + (size_t)(koff + b_k) * ldb + bx * 128 + b_nch0 * 4;

    float acc[4][8][4];
#pragma unroll
    for (int mi = 0; mi < 4; mi++)
#pragma unroll
        for (int ni = 0; ni < 8; ni++)
#pragma unroll
            for (int r = 0; r < 4; r++) acc[mi][ni][r] = 0.f;

    const int lr = lane >> 2, lc = lane & 3;
    const int niter = K >> 5;

#define G4_LOAD(stg, k0) do { \
    uint32_t ab_ = sbase + (stg) * (G4_STAGE_W * 4); \
    _Pragma("unroll") for (int i = 0; i < 8; i++) { \
        uint32_t so_ = SW128B((uint32_t)((a_row0 + 16 * i) * 128 + a_ch * 16)); \
        cpasync16(ab_ + so_, Ag + (size_t)(16 * i) * lda + (k0)); \
    } \
    uint32_t bb_ = ab_ + 4096 * 4; \
    _Pragma("unroll") for (int i = 0; i < 8; i++) { \
        int n_ = (b_nch0 + 4 * i) * 4; \
        uint32_t w_ = (uint32_t)(b_k * 128 + (n_ ^ ((b_k & 3) << 3))); \
        cpasync16(bb_ + w_ * 4, Bg + (size_t)(k0) * ldb + 16 * i); \
    } \
    CP_COMMIT(); \
} while (0)

    G4_LOAD(0, 0);
    if (niter > 1) G4_LOAD(1, 32);

    for (int it = 0; it < niter; it++) {
        if (it + 1 < niter) {
            asm volatile("cp.async.wait_group 1;" ::: "memory");
        } else {
            asm volatile("cp.async.wait_group 0;" ::: "memory");
        }
        __syncthreads();
        if (it + 2 < niter) G4_LOAD((it + 2) % 3, (it + 2) * 32);

        const uint32_t* Abuf = dsm + (it % 3) * G4_STAGE_W;
        const uint32_t* Bbuf = Abuf + 4096;
#pragma unroll
        for (int kk = 0; kk < 4; kk++) {
            uint4 af[4]; uint2 bf[8];
#pragma unroll
            for (int mi = 0; mi < 4; mi++) {
                int row = wm * 64 + mi * 16 + lr;
                int k = kk * 8 + lc;
                af[mi].x = Abuf[SW128B((uint32_t)(row * 128 + k * 4)) >> 2];
                af[mi].y = Abuf[SW128B((uint32_t)((row + 8) * 128 + k * 4)) >> 2];
                af[mi].z = Abuf[SW128B((uint32_t)(row * 128 + (k + 4) * 4)) >> 2];
                af[mi].w = Abuf[SW128B((uint32_t)((row + 8) * 128 + (k + 4) * 4)) >> 2];
            }
#pragma unroll
            for (int ni = 0; ni < 8; ni++) {
                int n = wn * 64 + ni * 8 + lr;
                int kb = kk * 8 + lc;
                int nsw = n ^ (lc << 3);
                bf[ni].x = Bbuf[kb * 128 + nsw];
                bf[ni].y = Bbuf[(kb + 4) * 128 + nsw];
            }
#pragma unroll
            for (int mi = 0; mi < 4; mi++)
#pragma unroll
                for (int ni = 0; ni < 8; ni++) MMA_TF32(acc[mi][ni], af[mi], bf[ni]);
        }
    }
#undef G4_LOAD

    const bool dobias = HASBIAS && (bz == 0);
#pragma unroll
    for (int mi = 0; mi < 4; mi++) {
#pragma unroll
        for (int ni = 0; ni < 8; ni++) {
            int row0 = by * 128 + wm * 64 + mi * 16 + lr;
            int col  = bx * 128 + wn * 64 + ni * 8 + lc * 2;
            float b0 = 0.f, b1 = 0.f;
            if (dobias) { b0 = bias[col]; b1 = bias[col + 1]; }
            float v0 = acc[mi][ni][0] + b0, v1 = acc[mi][ni][1] + b1;
            float v2 = acc[mi][ni][2] + b0, v3 = acc[mi][ni][3] + b1;
            if (RELU) {
                v0 = fmaxf(v0, 0.f); v1 = fmaxf(v1, 0.f);
                v2 = fmaxf(v2, 0.f); v3 = fmaxf(v3, 0.f);
            }
            if (CVT) {
                v0 = f2tf32f(v0); v1 = f2tf32f(v1);
                v2 = f2tf32f(v2); v3 = f2tf32f(v3);
            }
            *(float2*)(C + (size_t)row0 * ldc + col)       = make_float2(v0, v1);
            *(float2*)(C + (size_t)(row0 + 8) * ldc + col) = make_float2(v2, v3);
        }
    }
}

// ======== qrk_gemm: merged Q-projection + rk-projection (both split-K=2) ========
__global__ void __launch_bounds__(128) qrk_gemm(
    const float* __restrict__ Aq, const float* __restrict__ Bq,
    float* __restrict__ Cq0, float* __restrict__ Cq1,
    const float* __restrict__ Ar, const float* __restrict__ Br,
    float* __restrict__ Cr0, float* __restrict__ Cr1)
{
    extern __shared__ uint32_t dsm[];
    const uint32_t sbase = smem_u32(dsm);
    const int tid = threadIdx.x, lane = tid & 31;
    const int warp = tid >> 5, wm = warp >> 1, wn = warp & 1;
    const int bx = blockIdx.x, by = blockIdx.y, bz = blockIdx.z;

    const float* A; const float* B; float* C;
    int lda, ldb, koff;
    if (bz < 2) {
        A = Aq; B = Bq; C = bz ? Cq1 : Cq0;
        lda = 1024; ldb = 3072; koff = bz * 512;
    } else {
        if (by >= 8) return;
        A = Ar; B = Br; C = (bz - 2) ? Cr1 : Cr0;
        lda = 1024; ldb = 1024; koff = (bz - 2) * 512;
    }
    const int ldc = 1024;

    const int a_row0 = tid >> 3, a_ch = tid & 7;
    const float* Ag = A + (size_t)(by * 128 + a_row0) * lda + koff + a_ch * 4;
    const int b_k = tid >> 2, b_nch0 = tid & 3;
    const float* Bg = B + (size_t)(koff + b_k) * ldb + bx * 128 + b_nch0 * 4;

    float acc[4][8][4];
#pragma unroll
    for (int mi = 0; mi < 4; mi++)
#pragma unroll
        for (int ni = 0; ni < 8; ni++)
#pragma unroll
            for (int r = 0; r < 4; r++) acc[mi][ni][r] = 0.f;

    const int lr = lane >> 2, lc = lane & 3;
    const int niter = 16;   // K=512

#define QR_LOAD(stg, k0) do { \
    uint32_t ab_ = sbase + (stg) * (G4_STAGE_W * 4); \
    _Pragma("unroll") for (int i = 0; i < 8; i++) { \
        uint32_t so_ = SW128B((uint32_t)((a_row0 + 16 * i) * 128 + a_ch * 16)); \
        cpasync16(ab_ + so_, Ag + (size_t)(16 * i) * lda + (k0)); \
    } \
    uint32_t bb_ = ab_ + 4096 * 4; \
    _Pragma("unroll") for (int i = 0; i < 8; i++) { \
        int n_ = (b_nch0 + 4 * i) * 4; \
        uint32_t w_ = (uint32_t)(b_k * 128 + (n_ ^ ((b_k & 3) << 3))); \
        cpasync16(bb_ + w_ * 4, Bg + (size_t)(k0) * ldb + 16 * i); \
    } \
    CP_COMMIT(); \
} while (0)

    QR_LOAD(0, 0);
    QR_LOAD(1, 32);

    for (int it = 0; it < niter; it++) {
        if (it + 1 < niter) {
            asm volatile("cp.async.wait_group 1;" ::: "memory");
        } else {
            asm volatile("cp.async.wait_group 0;" ::: "memory");
        }
        __syncthreads();
        if (it + 2 < niter) QR_LOAD((it + 2) % 3, (it + 2) * 32);

        const uint32_t* Abuf = dsm + (it % 3) * G4_STAGE_W;
        const uint32_t* Bbuf = Abuf + 4096;
#pragma unroll
        for (int kk = 0; kk < 4; kk++) {
            uint4 af[4]; uint2 bf[8];
#pragma unroll
            for (int mi = 0; mi < 4; mi++) {
                int row = wm * 64 + mi * 16 + lr;
                int k = kk * 8 + lc;
                af[mi].x = Abuf[SW128B((uint32_t)(row * 128 + k * 4)) >> 2];
                af[mi].y = Abuf[SW128B((uint32_t)((row + 8) * 128 + k * 4)) >> 2];
                af[mi].z = Abuf[SW128B((uint32_t)(row * 128 + (k + 4) * 4)) >> 2];
                af[mi].w = Abuf[SW128B((uint32_t)((row + 8) * 128 + (k + 4) * 4)) >> 2];
            }
#pragma unroll
            for (int ni = 0; ni < 8; ni++) {
                int n = wn * 64 + ni * 8 + lr;
                int kb = kk * 8 + lc;
                int nsw = n ^ (lc << 3);
                bf[ni].x = Bbuf[kb * 128 + nsw];
                bf[ni].y = Bbuf[(kb + 4) * 128 + nsw];
            }
#pragma unroll
            for (int mi = 0; mi < 4; mi++)
#pragma unroll
                for (int ni = 0; ni < 8; ni++) MMA_TF32(acc[mi][ni], af[mi], bf[ni]);
        }
    }
#undef QR_LOAD

#pragma unroll
    for (int mi = 0; mi < 4; mi++)
#pragma unroll
        for (int ni = 0; ni < 8; ni++) {
            int row0 = by * 128 + wm * 64 + mi * 16 + lr;
            int col  = bx * 128 + wn * 64 + ni * 8 + lc * 2;
            *(float2*)(C + (size_t)row0 * ldc + col) =
                make_float2(acc[mi][ni][0], acc[mi][ni][1]);
            *(float2*)(C + (size_t)(row0 + 8) * ldc + col) =
                make_float2(acc[mi][ni][2], acc[mi][ni][3]);
        }
}

// ======== score_both: AC (mode 0, plain store) and BD (mode 1, SHIFTED store) ====
#define SC_SMEM (4 * 4096 * 4)
__global__ void __launch_bounds__(128) score_both(
    const float* __restrict__ qu, const float* __restrict__ qv,
    const float* __restrict__ heads, const float* __restrict__ rkc,
    float* __restrict__ ac, float* __restrict__ bd)
{
    const int bx = blockIdx.x, by = blockIdx.y, z = blockIdx.z;
    const int mode = (z >= BH) ? 1 : 0;
    const int bh = mode ? z - BH : z;
    const int i0 = by * 128, j0 = bx * 128;
    if (mode == 0) { if (j0 >= i0 + 640) return; }
    else           { if (i0 + j0 < 257) return; }
    const int bb = bh >> 4, nn = bh & 15;
    const float* A = (mode ? qv : qu) + (size_t)bh * QLEN * 64 + (size_t)i0 * 64;
    const float* B;
    size_t ldbB;
    if (mode == 0) {
        B = heads + (size_t)(j0 * 4 + bb) * 3072 + 1024 + (size_t)nn * 64;
        ldbB = 4 * 3072;
    } else {
        B = rkc + (size_t)nn * KLEN * 64 + (size_t)j0 * 64;
        ldbB = 64;
    }

    extern __shared__ uint32_t dsm[];
    const uint32_t sbase = smem_u32(dsm);
    const int tid = threadIdx.x, lane = tid & 31;
    const int warp = tid >> 5, wm = warp >> 1, wn = warp & 1;

    const int a_row0 = tid >> 3, a_ch = tid & 7;
    const float* Ag = A + (size_t)a_row0 * 64 + a_ch * 4;
    const float* Bg = B + (size_t)a_row0 * ldbB + a_ch * 4;

    float acc[4][8][4];
#pragma unroll
    for (int mi = 0; mi < 4; mi++)
#pragma unroll
        for (int ni = 0; ni < 8; ni++)
#pragma unroll
            for (int r = 0; r < 4; r++) acc[mi][ni][r] = 0.f;

    const int lr = lane >> 2, lc = lane & 3;

#define SC_LOAD(stg, k0) do { \
    uint32_t ab_ = sbase + (stg) * 32768; \
    uint32_t bb_ = ab_ + 16384; \
    _Pragma("unroll") for (int i = 0; i < 8; i++) { \
        uint32_t so_ = SW128B((uint32_t)((a_row0 + 16 * i) * 128 + a_ch * 16)); \
        cpasync16(ab_ + so_, Ag + (size_t)(16 * i) * 64 + (k0)); \
        cpasync16(bb_ + so_, Bg + (size_t)(16 * i) * ldbB + (k0)); \
    } \
    CP_COMMIT(); \
} while (0)

    SC_LOAD(0, 0);
    SC_LOAD(1, 32);

#pragma unroll
    for (int it = 0; it < 2; it++) {
        if (it == 0) asm volatile("cp.async.wait_group 1;" ::: "memory");
        else         asm volatile("cp.async.wait_group 0;" ::: "memory");
        __syncthreads();
        const uint32_t* Abuf = dsm + it * 8192;
        const uint32_t* Bbuf = Abuf + 4096;
#pragma unroll
        for (int kk = 0; kk < 4; kk++) {
            uint4 af[4]; uint2 bf[8];
#pragma unroll
            for (int mi = 0; mi < 4; mi++) {
                int row = wm * 64 + mi * 16 + lr;
                int k = kk * 8 + lc;
                af[mi].x = Abuf[SW128B((uint32_t)(row * 128 + k * 4)) >> 2];
                af[mi].y = Abuf[SW128B((uint32_t)((row + 8) * 128 + k * 4)) >> 2];
                af[mi].z = Abuf[SW128B((uint32_t)(row * 128 + (k + 4) * 4)) >> 2];
                af[mi].w = Abuf[SW128B((uint32_t)((row + 8) * 128 + (k + 4) * 4)) >> 2];
            }
#pragma unroll
            for (int ni = 0; ni < 8; ni++) {
                int n = wn * 64 + ni * 8 + lr;
                int k = kk * 8 + lc;
                bf[ni].x = Bbuf[SW128B((uint32_t)(n * 128 + k * 4)) >> 2];
                bf[ni].y = Bbuf[SW128B((uint32_t)(n * 128 + (k + 4) * 4)) >> 2];
            }
#pragma unroll
            for (int mi = 0; mi < 4; mi++)
#pragma unroll
                for (int ni = 0; ni < 8; ni++) MMA_TF32(acc[mi][ni], af[mi], bf[ni]);
        }
    }
#undef SC_LOAD

    if (mode == 0) {
        float* ob = ac + (size_t)bh * QLEN * KLEN;
#pragma unroll
        for (int mi = 0; mi < 4; mi++)
#pragma unroll
            for (int ni = 0; ni < 8; ni++) {
                int row0 = i0 + wm * 64 + mi * 16 + lr;
                int col  = j0 + wn * 64 + ni * 8 + lc * 2;
                *(float2*)(ob + (size_t)row0 * KLEN + col) =
                    make_float2(acc[mi][ni][0], acc[mi][ni][1]);
                *(float2*)(ob + (size_t)(row0 + 8) * KLEN + col) =
                    make_float2(acc[mi][ni][2], acc[mi][ni][3]);
            }
    } else {
        // shifted store: bd[i][jj + i - 511] = BDraw[i][jj]
        float* ob = bd + (size_t)bh * QLEN * KLEN;
#pragma unroll
        for (int mi = 0; mi < 4; mi++)
#pragma unroll
            for (int ni = 0; ni < 8; ni++) {
                int r0 = i0 + wm * 64 + mi * 16 + lr;
                int r1 = r0 + 8;
                int c0 = j0 + wn * 64 + ni * 8 + lc * 2;
                int jp;
                jp = c0 + r0 - 511;
                if (jp >= 0) ob[(size_t)r0 * KLEN + jp] = acc[mi][ni][0];
                jp = c0 + 1 + r0 - 511;
                if (jp >= 0) ob[(size_t)r0 * KLEN + jp] = acc[mi][ni][1];
                jp = c0 + r1 - 511;
                if (jp >= 0) ob[(size_t)r1 * KLEN + jp] = acc[mi][ni][2];
                jp = c0 + 1 + r1 - 511;
                if (jp >= 0) ob[(size_t)r1 * KLEN + jp] = acc[mi][ni][3];
            }
    }
}

// ======== av3: fused (softmax no-max) + P@V. ac/bd index-aligned, staged in smem ==
// 2-stage ring: ac 4096 + bd 4096 + V 2048 words per stage = 40KB; 2 CTA/SM.
#define AV3_STAGE_W 10240
#define AV3_SMEM (2 * AV3_STAGE_W * 4)
__global__ void __launch_bounds__(128) av3(
    const float* __restrict__ ac, const float* __restrict__ bd,
    const float* __restrict__ heads, float* __restrict__ av)
{
    extern __shared__ uint32_t dsm[];
    const uint32_t sbase = smem_u32(dsm);
    const int by = blockIdx.x, bh = blockIdx.y;
    const int b = bh >> 4, n_h = bh & 15;
    const float* acb = ac + (size_t)bh * QLEN * KLEN + (size_t)by * 128 * KLEN;
    const float* bdb = bd + (size_t)bh * QLEN * KLEN + (size_t)by * 128 * KLEN;
    const float* Vb = heads + (size_t)b * 3072 + 2048 + (size_t)n_h * 64;
    const size_t ldv = 4 * 3072;
    const int kmax = min(KLEN, by * 128 + 640);

    const int tid = threadIdx.x, lane = tid & 31;
    const int warp = tid >> 5, wm = warp >> 1, wn = warp & 1;
    const int lr = lane >> 2, lc = lane & 3;

    const int a_row0 = tid >> 3, a_ch = tid & 7;
    const float* Acg = acb + (size_t)a_row0 * KLEN + a_ch * 4;
    const float* Bdg = bdb + (size_t)a_row0 * KLEN + a_ch * 4;
    const int b_k = tid >> 2, b_nch0 = tid & 3;
    const float* Bg = Vb + (size_t)b_k * ldv + b_nch0 * 4;

    float acc[4][4][4];
#pragma unroll
    for (int mi = 0; mi < 4; mi++)
#pragma unroll
        for (int ni = 0; ni < 4; ni++)
#pragma unroll
            for (int r = 0; r < 4; r++) acc[mi][ni][r] = 0.f;
    float lsum[4][2];
#pragma unroll
    for (int mi = 0; mi < 4; mi++) { lsum[mi][0] = 0.f; lsum[mi][1] = 0.f; }

    int jm[4][2];
#pragma unroll
    for (int mi = 0; mi < 4; mi++)
#pragma unroll
        for (int h = 0; h < 2; h++)
            jm[mi][h] = by * 128 + wm * 64 + mi * 16 + lr + 8 * h + 512;

    const int niter = kmax >> 5;

#define AV3_LOAD(stg, k0) do { \
    uint32_t base_ = sbase + (stg) * (AV3_STAGE_W * 4); \
    _Pragma("unroll") for (int i = 0; i < 8; i++) { \
        uint32_t so_ = SW128B((uint32_t)((a_row0 + 16 * i) * 128 + a_ch * 16)); \
        cpasync16(base_ + so_, Acg + (size_t)(16 * i) * KLEN + (k0)); \
        cpasync16(base_ + 16384 + so_, Bdg + (size_t)(16 * i) * KLEN + (k0)); \
    } \
    _Pragma("unroll") for (int i = 0; i < 4; i++) { \
        int n_ = (b_nch0 + 4 * i) * 4; \
        uint32_t w_ = (uint32_t)(b_k * 64 + (n_ ^ ((b_k & 3) << 3))); \
        cpasync16(base_ + 32768 + w_ * 4, Bg + (size_t)(k0) * ldv + 16 * i); \
    } \
    CP_COMMIT(); \
} while (0)

    AV3_LOAD(0, 0);
    if (niter > 1) AV3_LOAD(1, 32);

    for (int it = 0; it < niter; it++) {
        if (it + 1 < niter) {
            asm volatile("cp.async.wait_group 1;" ::: "memory");
        } else {
            asm volatile("cp.async.wait_group 0;" ::: "memory");
        }
        __syncthreads();

        const uint32_t* Sac = dsm + (it & 1) * AV3_STAGE_W;
        const uint32_t* Sbd = Sac + 4096;
        const uint32_t* Sv  = Sac + 8192;
        const int jb = it * 32;
#pragma unroll
        for (int kk = 0; kk < 4; kk++) {
            const int j1 = jb + kk * 8 + lc;
            const int j2 = j1 + 4;
            uint4 af[4];
#pragma unroll
            for (int mi = 0; mi < 4; mi++) {
                int row = wm * 64 + mi * 16 + lr;
                int k = kk * 8 + lc;
                uint32_t o00 = SW128B((uint32_t)(row * 128 + k * 4)) >> 2;
                uint32_t o10 = SW128B((uint32_t)((row + 8) * 128 + k * 4)) >> 2;
                uint32_t o01 = SW128B((uint32_t)(row * 128 + (k + 4) * 4)) >> 2;
                uint32_t o11 = SW128B((uint32_t)((row + 8) * 128 + (k + 4) * 4)) >> 2;
                float sx = 0.125f * (__uint_as_float(Sac[o00]) + __uint_as_float(Sbd[o00]));
                float sy = 0.125f * (__uint_as_float(Sac[o10]) + __uint_as_float(Sbd[o10]));
                float sz = 0.125f * (__uint_as_float(Sac[o01]) + __uint_as_float(Sbd[o01]));
                float sw = 0.125f * (__uint_as_float(Sac[o11]) + __uint_as_float(Sbd[o11]));
                float px = (j1 <= jm[mi][0]) ? __expf(sx) : 0.f;
                float py = (j1 <= jm[mi][1]) ? __expf(sy) : 0.f;
                float pz = (j2 <= jm[mi][0]) ? __expf(sz) : 0.f;
                float pw = (j2 <= jm[mi][1]) ? __expf(sw) : 0.f;
                uint32_t rx = f2tf32(px), ry = f2tf32(py);
                uint32_t rz = f2tf32(pz), rw = f2tf32(pw);
                lsum[mi][0] += __uint_as_float(rx) + __uint_as_float(rz);
                lsum[mi][1] += __uint_as_float(ry) + __uint_as_float(rw);
                af[mi].x = rx; af[mi].y = ry; af[mi].z = rz; af[mi].w = rw;
            }
            uint2 bf[4];
#pragma unroll
            for (int ni = 0; ni < 4; ni++) {
                int n = wn * 32 + ni * 8 + lr;
                int kb = kk * 8 + lc;
                int nsw = n ^ (lc << 3);
                bf[ni].x = Sv[kb * 64 + nsw];
                bf[ni].y = Sv[(kb + 4) * 64 + nsw];
            }
#pragma unroll
            for (int mi = 0; mi < 4; mi++)
#pragma unroll
                for (int ni = 0; ni < 4; ni++) MMA_TF32(acc[mi][ni], af[mi], bf[ni]);
        }
        __syncthreads();
        if (it + 2 < niter) AV3_LOAD(it & 1, (it + 2) * 32);
    }
#undef AV3_LOAD

    float inv[4][2];
#pragma unroll
    for (int mi = 0; mi < 4; mi++)
#pragma unroll
        for (int h = 0; h < 2; h++) {
            float l = lsum[mi][h];
            l += __shfl_xor_sync(0xFFFFFFFF, l, 1);
            l += __shfl_xor_sync(0xFFFFFFFF, l, 2);
            inv[mi][h] = 1.0f / l;
        }

#pragma unroll
    for (int mi = 0; mi < 4; mi++)
#pragma unroll
        for (int ni = 0; ni < 4; ni++) {
            int row0 = by * 128 + wm * 64 + mi * 16 + lr;
            int col  = wn * 32 + ni * 8 + lc * 2;
            *(float2*)(av + ((size_t)row0 * 4 + b) * 1024 + n_h * 64 + col) =
                make_float2(f2tf32f(acc[mi][ni][0] * inv[mi][0]),
                            f2tf32f(acc[mi][ni][1] * inv[mi][0]));
            *(float2*)(av + ((size_t)(row0 + 8) * 4 + b) * 1024 + n_h * 64 + col) =
                make_float2(f2tf32f(acc[mi][ni][2] * inv[mi][1]),
                            f2tf32f(acc[mi][ni][3] * inv[mi][1]));
        }
}

// ---------------- fused weight rounding ----------------
__global__ void roundw5_kernel(
    float4* d0, const float4* s0, size_t n0,
    float4* d1, const float4* s1, size_t n1,
    float4* d2, const float4* s2, size_t n2,
    float4* d3, const float4* s3, size_t n3,
    float4* d4, const float4* s4, size_t n4)
{
    size_t i = (size_t)blockIdx.x * 256 + threadIdx.x;
    float4* d; const float4* s;
    if (i < n0) { d = d0; s = s0; }
    else { i -= n0;
    if (i < n1) { d = d1; s = s1; }
    else { i -= n1;
    if (i < n2) { d = d2; s = s2; }
    else { i -= n2;
    if (i < n3) { d = d3; s = s3; }
    else { i -= n3;
    if (i < n4) { d = d4; s = s4; }
    else return; }}}}
    float4 v = s[i];
    d[i] = make_float4(f2tf32f(v.x), f2tf32f(v.y), f2tf32f(v.z), f2tf32f(v.w));
}

// ---------------- small kernels ----------------
__global__ void posemb_kernel(float* __restrict__ r) {
    int idx = blockIdx.x * 256 + threadIdx.x;
    int k = idx >> 10, d = idx & 1023;
    float pos = (float)(KLEN - 1 - k);
    int j = (d < 512) ? d : d - 512;
    float inv = expf(-((float)(2 * j) / 1024.0f) * 9.210340371976184f);
    float ang = pos * inv;
    r[idx] = f2tf32f((d < 512) ? sinf(ang) : cosf(ang));
}

__global__ void copy4_kernel(float4* __restrict__ dst, const float4* __restrict__ src) {
    size_t i = (size_t)blockIdx.x * 256 + threadIdx.x;
    dst[i] = src[i];
}

__global__ void concat_kernel(float4* __restrict__ cat, const float4* __restrict__ mem,
                              const float4* __restrict__ h) {
    size_t i = (size_t)blockIdx.x * 256 + threadIdx.x;
    const size_t half = (size_t)MLEN * BATCH * DMODEL / 4;
    float4 v = (i < half) ? mem[i] : h[i - half];
    cat[i] = make_float4(f2tf32f(v.x), f2tf32f(v.y), f2tf32f(v.z), f2tf32f(v.w));
}

// q = split-K partials q0+q1; outputs rounded tf32
__global__ void repack_quqv(const float* __restrict__ q0, const float* __restrict__ q1,
                            const float* __restrict__ u, const float* __restrict__ v,
                            float* __restrict__ qu, float* __restrict__ qv) {
    int idx = blockIdx.x * 256 + threadIdx.x;
    int d4 = idx & 15, i = (idx >> 4) & 511, bh = idx >> 13;
    int b = bh >> 4, n = bh & 15;
    size_t qoff = ((size_t)(i * 4 + b)) * 1024 + n * 64 + d4 * 4;
    float4 qa = *(const float4*)(q0 + qoff);
    float4 qb = *(const float4*)(q1 + qoff);
    float4 uu = *(const float4*)(u + n * 64 + d4 * 4);
    float4 vv = *(const float4*)(v + n * 64 + d4 * 4);
    float qx = qa.x + qb.x, qy = qa.y + qb.y, qz = qa.z + qb.z, qw = qa.w + qb.w;
    size_t o = ((size_t)bh * 512 + i) * 64 + d4 * 4;
    *(float4*)(qu + o) = make_float4(f2tf32f(qx + uu.x), f2tf32f(qy + uu.y),
                                     f2tf32f(qz + uu.z), f2tf32f(qw + uu.w));
    *(float4*)(qv + o) = make_float4(f2tf32f(qx + vv.x), f2tf32f(qy + vv.y),
                                     f2tf32f(qz + vv.z), f2tf32f(qw + vv.w));
}

// rk = split-K partials p0+p1 ([j][1024]); output [n][j][64], rounded
__global__ void repack_rk(const float* __restrict__ p0, const float* __restrict__ p1,
                          float* __restrict__ rkc) {
    int idx = blockIdx.x * 256 + threadIdx.x;
    int d4 = idx & 15, j = (idx >> 4) & 1023, n = idx >> 14;
    size_t off = (size_t)j * 1024 + n * 64 + d4 * 4;
    float4 a = *(const float4*)(p0 + off);
    float4 b = *(const float4*)(p1 + off);
    *(float4*)(rkc + ((size_t)n * 1024 + j) * 64 + d4 * 4) =
        make_float4(f2tf32f(a.x + b.x), f2tf32f(a.y + b.y),
                    f2tf32f(a.z + b.z), f2tf32f(a.w + b.w));
}

// ---------------- residual + 2 partials + LayerNorm (output rounded) ----------------
__global__ void __launch_bounds__(256) add_ln3_kernel(
    float* __restrict__ h, const float* __restrict__ t0, const float* __restrict__ t1,
    const float* __restrict__ g, const float* __restrict__ b)
{
    int row = blockIdx.x;
    int tid = threadIdx.x;
    __shared__ float rs[256], rs2[256];
    float x[4];
    float s = 0.f, ss = 0.f;
#pragma unroll
    for (int c = 0; c < 4; c++) {
        int d = c * 256 + tid;
        size_t o = (size_t)row * 1024 + d;
        float v = h[o] + t0[o] + t1[o];
        x[c] = v; s += v; ss += v * v;
    }
    rs[tid] = s; rs2[tid] = ss; __syncthreads();
    for (int o = 128; o > 0; o >>= 1) {
        if (tid < o) { rs[tid] += rs[tid + o]; rs2[tid] += rs2[tid + o]; }
        __syncthreads();
    }
    float mu = rs[0] * (1.0f / 1024.0f);
    float var = rs2[0] * (1.0f / 1024.0f) - mu * mu;
    float inv = rsqrtf(var + 1e-5f);
#pragma unroll
    for (int c = 0; c < 4; c++) {
        int d = c * 256 + tid;
        h[(size_t)row * 1024 + d] = f2tf32f((x[c] - mu) * inv * g[d] + b[d]);
    }
}

// ---------------- launch ----------------
extern "C" void kernel_launch(void* const* d_in, const int* in_sizes, int n_in,
                              void* d_out, int out_size) {
    (void)in_sizes; (void)n_in; (void)out_size;
    const float* x     = (const float*)d_in[0];
    const float* mems  = (const float*)d_in[1];
    const float* u     = (const float*)d_in[2];
    const float* v     = (const float*)d_in[3];
    const float* W_qkv = (const float*)d_in[4];
    const float* W_o   = (const float*)d_in[5];
    const float* W_r   = (const float*)d_in[6];
    const float* ln1_g = (const float*)d_in[7];
    const float* ln1_b = (const float*)d_in[8];
    const float* W1    = (const float*)d_in[9];
    const float* b1    = (const float*)d_in[10];
    const float* W2    = (const float*)d_in[11];
    const float* b2    = (const float*)d_in[12];
    const float* ln2_g = (const float*)d_in[13];
    const float* ln2_b = (const float*)d_in[14];

    float *cat, *heads, *r, *ac, *bd, *av, *tmp, *tmp2, *h, *ff, *qu, *qv, *rkc;
    float *wqkv, *wr, *wo, *w1, *w2;
    cudaGetSymbolAddress((void**)&cat,   g_cat);
    cudaGetSymbolAddress((void**)&heads, g_heads);
    cudaGetSymbolAddress((void**)&r,     g_r);
    cudaGetSymbolAddress((void**)&ac,    g_ac);
    cudaGetSymbolAddress((void**)&bd,    g_bd);
    cudaGetSymbolAddress((void**)&av,    g_av);
    cudaGetSymbolAddress((void**)&tmp,   g_tmp);
    cudaGetSymbolAddress((void**)&tmp2,  g_tmp2);
    cudaGetSymbolAddress((void**)&h,     g_h);
    cudaGetSymbolAddress((void**)&ff,    g_ff);
    cudaGetSymbolAddress((void**)&qu,    g_qu);
    cudaGetSymbolAddress((void**)&qv,    g_qv);
    cudaGetSymbolAddress((void**)&rkc,   g_rkc);
    cudaGetSymbolAddress((void**)&wqkv,  g_wqkv);
    cudaGetSymbolAddress((void**)&wr,    g_wr);
    cudaGetSymbolAddress((void**)&wo,    g_wo);
    cudaGetSymbolAddress((void**)&w1,    g_w1);
    cudaGetSymbolAddress((void**)&w2,    g_w2);

    cudaFuncSetAttribute(gemm4<0,0,0>, cudaFuncAttributeMaxDynamicSharedMemorySize, G4_SMEM);
    cudaFuncSetAttribute(gemm4<0,0,1>, cudaFuncAttributeMaxDynamicSharedMemorySize, G4_SMEM);
    cudaFuncSetAttribute(gemm4<1,1,1>, cudaFuncAttributeMaxDynamicSharedMemorySize, G4_SMEM);
    cudaFuncSetAttribute(gemm4<0,1,0>, cudaFuncAttributeMaxDynamicSharedMemorySize, G4_SMEM);
    cudaFuncSetAttribute(qrk_gemm,     cudaFuncAttributeMaxDynamicSharedMemorySize, G4_SMEM);
    cudaFuncSetAttribute(score_both,   cudaFuncAttributeMaxDynamicSharedMemorySize, SC_SMEM);
    cudaFuncSetAttribute(av3,          cudaFuncAttributeMaxDynamicSharedMemorySize, AV3_SMEM);

    // one-time weight rounding (single fused launch)
    {
        size_t n0 = (size_t)NLAYER*DMODEL*3072/4, n1 = (size_t)NLAYER*DMODEL*DMODEL/4;
        size_t n2 = n1, n3 = (size_t)NLAYER*DMODEL*DINNER/4, n4 = n3;
        size_t ntot = n0 + n1 + n2 + n3 + n4;
        roundw5_kernel<<<(unsigned)((ntot + 255) / 256), 256>>>(
            (float4*)wqkv, (const float4*)W_qkv, n0,
            (float4*)wr,   (const float4*)W_r,   n1,
            (float4*)wo,   (const float4*)W_o,   n2,
            (float4*)w1,   (const float4*)W1,    n3,
            (float4*)w2,   (const float4*)W2,    n4);
    }

    posemb_kernel<<<4096, 256>>>(r);
    copy4_kernel<<<2048, 256>>>((float4*)h, (const float4*)x);

    for (int l = 0; l < NLAYER; l++) {
        const float* Wq = wqkv + (size_t)l * DMODEL * 3072;
        concat_kernel<<<4096, 256>>>((float4*)cat,
                                     (const float4*)(mems + (size_t)l * MLEN * BATCH * DMODEL),
                                     (const float4*)h);
        // K,V: all 4096 rows, cols 1024..3071 — rounded output (consumed in place)
        gemm4<0,0,1><<<dim3(16, 32, 1), 128, G4_SMEM>>>(
            cat, Wq + 1024, nullptr, heads + 1024, nullptr, 1024, 1024, 3072, 3072);
        // Q (split-K=2) + rk (split-K=2), one launch
        qrk_gemm<<<dim3(8, 16, 4), 128, G4_SMEM>>>(
            cat + (size_t)2048 * 1024, Wq, tmp, tmp2,
            r, wr + (size_t)l * DMODEL * DMODEL, bd, bd + (size_t)1024 * 1024);
        // repacks
        repack_quqv<<<2048, 256>>>(tmp, tmp2, u, v, qu, qv);
        repack_rk<<<1024, 256>>>(bd, bd + (size_t)1024 * 1024, rkc);
        // scores: AC plain + BD shifted, one launch
        score_both<<<dim3(8, 4, 2 * BH), 128, SC_SMEM>>>(qu, qv, heads, rkc, ac, bd);
        // fused softmax + P@V (V streamed from heads)
        av3<<<dim3(4, BH), 128, AV3_SMEM>>>(ac, bd, heads, av);
        // O projection: split-K=2
        gemm4<0,0,0><<<dim3(8, 16, 2), 128, G4_SMEM>>>(
            av, wo + (size_t)l * DMODEL * DMODEL, nullptr, tmp, tmp2,
            512, 1024, 1024, 1024);
        add_ln3_kernel<<<2048, 256>>>(h, tmp, tmp2,
                                      ln1_g + (size_t)l * DMODEL, ln1_b + (size_t)l * DMODEL);
        // FFN
        gemm4<1,1,1><<<dim3(32, 16, 1), 128, G4_SMEM>>>(
            h, w1 + (size_t)l * DMODEL * DINNER, b1 + (size_t)l * DINNER, ff, nullptr,
            1024, 1024, 4096, 4096);
        gemm4<0,1,0><<<dim3(8, 16, 2), 128, G4_SMEM>>>(
            ff, w2 + (size_t)l * DINNER * DMODEL, b2 + (size_t)l * DMODEL, tmp, tmp2,
            2048, 4096, 1024, 1024);
        add_ln3_kernel<<<2048, 256>>>(h, tmp, tmp2,
                                      ln2_g + (size_t)l * DMODEL, ln2_b + (size_t)l * DMODEL);
    }

    cudaMemcpyAsync(d_out, h, (size_t)QLEN * BATCH * DMODEL * sizeof(float),
                    cudaMemcpyDeviceToDevice);
}

// round 15
// speedup vs baseline: 1.2214x; 1.0190x over previous
#include <cuda_runtime.h>
#include <math.h>
#include <stdint.h>

#define QLEN 512
#define BATCH 4
#define DMODEL 1024
#define NLAYER 4
#define NHEAD 16
#define DHEAD 64
#define DINNER 4096
#define MLEN 512
#define KLEN 1024
#define BH (BATCH*NHEAD)

// ---------------- scratch ----------------
__device__ float g_memsr[(size_t)NLAYER*MLEN*BATCH*DMODEL];
__device__ float g_heads[(size_t)KLEN*BATCH*3*DMODEL];
__device__ float g_r[(size_t)KLEN*DMODEL];
__device__ float g_ac[(size_t)BH*QLEN*KLEN];
__device__ float g_bd[(size_t)BH*QLEN*KLEN];
__device__ float g_av[(size_t)QLEN*BATCH*DMODEL];
__device__ float g_tmp[(size_t)QLEN*BATCH*DMODEL];
__device__ float g_tmp2[(size_t)QLEN*BATCH*DMODEL];
__device__ float g_h[(size_t)QLEN*BATCH*DMODEL];
__device__ float g_ff[(size_t)QLEN*BATCH*DINNER];
__device__ float g_qu[(size_t)BH*QLEN*DHEAD];
__device__ float g_qv[(size_t)BH*QLEN*DHEAD];
__device__ float g_rkc[(size_t)NHEAD*KLEN*DHEAD];
// tf32-rounded weight copies
__device__ float g_wqkv[(size_t)NLAYER*DMODEL*3072];
__device__ float g_wr[(size_t)NLAYER*DMODEL*DMODEL];
__device__ float g_wo[(size_t)NLAYER*DMODEL*DMODEL];
__device__ float g_w1[(size_t)NLAYER*DMODEL*DINNER];
__device__ float g_w2[(size_t)NLAYER*DINNER*DMODEL];

__device__ __forceinline__ uint32_t f2tf32(float f) {
    uint32_t o;
    asm("cvt.rna.tf32.f32 %0, %1;" : "=r"(o) : "f"(f));
    return o;
}
__device__ __forceinline__ float f2tf32f(float f) {
    uint32_t o = f2tf32(f);
    return __uint_as_float(o);
}

#define MMA_TF32(d, a, b) \
    asm volatile("mma.sync.aligned.m16n8k8.row.col.f32.tf32.tf32.f32 " \
                 "{%0,%1,%2,%3}, {%4,%5,%6,%7}, {%8,%9}, {%0,%1,%2,%3};" \
                 : "+f"(d[0]), "+f"(d[1]), "+f"(d[2]), "+f"(d[3]) \
                 : "r"(a.x), "r"(a.y), "r"(a.z), "r"(a.w), "r"(b.x), "r"(b.y))

__device__ __forceinline__ void cpasync16(uint32_t dst, const void* src) {
    asm volatile("cp.async.cg.shared.global [%0], [%1], 16;" :: "r"(dst), "l"(src));
}
#define CP_COMMIT() asm volatile("cp.async.commit_group;" ::: "memory")
__device__ __forceinline__ uint32_t smem_u32(const void* p) {
    uint32_t a;
    asm("{ .reg .u64 t; cvta.to.shared.u64 t, %1; cvt.u32.u64 %0, t; }" : "=r"(a) : "l"(p));
    return a;
}
#define SW128B(o) ((o) ^ (((o) >> 3) & 0x70))

// gemm4: 3 stages x (A 4096 + B 4096) words
#define G4_STAGE_W 8192
#define G4_SMEM (3 * G4_STAGE_W * 4)

// ======== gemm4: C[M,N]=A[M,K]@B[K,N]. 128 thr, CTA 128x128, warp 64x64 ========
template<int RELU, int HASBIAS, int CVT>
__global__ void __launch_bounds__(128) gemm4(
    const float* __restrict__ A, const float* __restrict__ B,
    const float* __restrict__ bias, float* __restrict__ C0, float* __restrict__ C1,
    int K, int lda, int ldb, int ldc)
{
    extern __shared__ uint32_t dsm[];
    const uint32_t sbase = smem_u32(dsm);
    const int tid = threadIdx.x, lane = tid & 31;
    const int warp = tid >> 5, wm = warp >> 1, wn = warp & 1;
    const int bx = blockIdx.x, by = blockIdx.y, bz = blockIdx.z;

    const int koff = bz * K;
    float* C = bz ? C1 : C0;

    const int a_row0 = tid >> 3, a_ch = tid & 7;
    const float* Ag = A + (size_t)(by * 128 + a_row0) * lda + koff + a_ch * 4;
    const int b_k = tid >> 2, b_nch0 = tid & 3;
    const float* Bg = B + (size_t)(koff + b_k) * ldb + bx * 128 + b_nch0 * 4;

    float acc[4][8][4];
#pragma unroll
    for (int mi = 0; mi < 4; mi++)
#pragma unroll
        for (int ni = 0; ni < 8; ni++)
#pragma unroll
            for (int r = 0; r < 4; r++) acc[mi][ni][r] = 0.f;

    const int lr = lane >> 2, lc = lane & 3;
    const int niter = K >> 5;

#define G4_LOAD(stg, k0) do { \
    uint32_t ab_ = sbase + (stg) * (G4_STAGE_W * 4); \
    _Pragma("unroll") for (int i = 0; i < 8; i++) { \
        uint32_t so_ = SW128B((uint32_t)((a_row0 + 16 * i) * 128 + a_ch * 16)); \
        cpasync16(ab_ + so_, Ag + (size_t)(16 * i) * lda + (k0)); \
    } \
    uint32_t bb_ = ab_ + 4096 * 4; \
    _Pragma("unroll") for (int i = 0; i < 8; i++) { \
        int n_ = (b_nch0 + 4 * i) * 4; \
        uint32_t w_ = (uint32_t)(b_k * 128 + (n_ ^ ((b_k & 3) << 3))); \
        cpasync16(bb_ + w_ * 4, Bg + (size_t)(k0) * ldb + 16 * i); \
    } \
    CP_COMMIT(); \
} while (0)

    G4_LOAD(0, 0);
    if (niter > 1) G4_LOAD(1, 32);

    for (int it = 0; it < niter; it++) {
        if (it + 1 < niter) {
            asm volatile("cp.async.wait_group 1;" ::: "memory");
        } else {
            asm volatile("cp.async.wait_group 0;" ::: "memory");
        }
        __syncthreads();
        if (it + 2 < niter) G4_LOAD((it + 2) % 3, (it + 2) * 32);

        const uint32_t* Abuf = dsm + (it % 3) * G4_STAGE_W;
        const uint32_t* Bbuf = Abuf + 4096;
#pragma unroll
        for (int kk = 0; kk < 4; kk++) {
            uint4 af[4]; uint2 bf[8];
#pragma unroll
            for (int mi = 0; mi < 4; mi++) {
                int row = wm * 64 + mi * 16 + lr;
                int k = kk * 8 + lc;
                af[mi].x = Abuf[SW128B((uint32_t)(row * 128 + k * 4)) >> 2];
                af[mi].y = Abuf[SW128B((uint32_t)((row + 8) * 128 + k * 4)) >> 2];
                af[mi].z = Abuf[SW128B((uint32_t)(row * 128 + (k + 4) * 4)) >> 2];
                af[mi].w = Abuf[SW128B((uint32_t)((row + 8) * 128 + (k + 4) * 4)) >> 2];
            }
#pragma unroll
            for (int ni = 0; ni < 8; ni++) {
                int n = wn * 64 + ni * 8 + lr;
                int kb = kk * 8 + lc;
                int nsw = n ^ (lc << 3);
                bf[ni].x = Bbuf[kb * 128 + nsw];
                bf[ni].y = Bbuf[(kb + 4) * 128 + nsw];
            }
#pragma unroll
            for (int mi = 0; mi < 4; mi++)
#pragma unroll
                for (int ni = 0; ni < 8; ni++) MMA_TF32(acc[mi][ni], af[mi], bf[ni]);
        }
    }
#undef G4_LOAD

    const bool dobias = HASBIAS && (bz == 0);
#pragma unroll
    for (int mi = 0; mi < 4; mi++) {
#pragma unroll
        for (int ni = 0; ni < 8; ni++) {
            int row0 = by * 128 + wm * 64 + mi * 16 + lr;
            int col  = bx * 128 + wn * 64 + ni * 8 + lc * 2;
            float b0 = 0.f, b1 = 0.f;
            if (dobias) { b0 = bias[col]; b1 = bias[col + 1]; }
            float v0 = acc[mi][ni][0] + b0, v1 = acc[mi][ni][1] + b1;
            float v2 = acc[mi][ni][2] + b0, v3 = acc[mi][ni][3] + b1;
            if (RELU) {
                v0 = fmaxf(v0, 0.f); v1 = fmaxf(v1, 0.f);
                v2 = fmaxf(v2, 0.f); v3 = fmaxf(v3, 0.f);
            }
            if (CVT) {
                v0 = f2tf32f(v0); v1 = f2tf32f(v1);
                v2 = f2tf32f(v2); v3 = f2tf32f(v3);
            }
            *(float2*)(C + (size_t)row0 * ldc + col)       = make_float2(v0, v1);
            *(float2*)(C + (size_t)(row0 + 8) * ldc + col) = make_float2(v2, v3);
        }
    }
}

// ======== mega_qkv: KV-proj + Q-proj(2 halves) + rk-proj(2 halves), one launch ====
// grid (16, 56): by<32 KV; 32<=by<48 Q (bx>>3 = half); 48<=by<56 rk (bx>>3 = half).
__global__ void __launch_bounds__(128) mega_qkv(
    const float* __restrict__ memsl, const float* __restrict__ h,
    const float* __restrict__ r,
    const float* __restrict__ Wq, const float* __restrict__ Wr,
    float* __restrict__ heads, float* __restrict__ q0, float* __restrict__ q1,
    float* __restrict__ rk0, float* __restrict__ rk1)
{
    extern __shared__ uint32_t dsm[];
    const uint32_t sbase = smem_u32(dsm);
    const int tid = threadIdx.x, lane = tid & 31;
    const int warp = tid >> 5, wm = warp >> 1, wn = warp & 1;
    const int bx = blockIdx.x, by = blockIdx.y;

    const float* Ablk; const float* B; float* C;
    int ldb, ldc, koff, niter, colbase, rowbase;
    bool cvt;
    if (by < 32) {
        Ablk = (by < 16) ? memsl + (size_t)by * 128 * 1024
                         : h + (size_t)(by - 16) * 128 * 1024;
        B = Wq + 1024; ldb = 3072;
        C = heads + 1024; ldc = 3072;
        koff = 0; niter = 32; cvt = true;
        colbase = bx * 128; rowbase = by * 128;
    } else if (by < 48) {
        int half = bx >> 3, bxe = bx & 7;
        Ablk = h + (size_t)(by - 32) * 128 * 1024;
        B = Wq; ldb = 3072;
        C = half ? q1 : q0; ldc = 1024;
        koff = half * 512; niter = 16; cvt = false;
        colbase = bxe * 128; rowbase = (by - 32) * 128;
    } else {
        int half = bx >> 3, bxe = bx & 7;
        Ablk = r + (size_t)(by - 48) * 128 * 1024;
        B = Wr; ldb = 1024;
        C = half ? rk1 : rk0; ldc = 1024;
        koff = half * 512; niter = 16; cvt = false;
        colbase = bxe * 128; rowbase = (by - 48) * 128;
    }

    const int a_row0 = tid >> 3, a_ch = tid & 7;
    const float* Ag = Ablk + (size_t)a_row0 * 1024 + koff + a_ch * 4;
    const int b_k = tid >> 2, b_nch0 = tid & 3;
    const float* Bg = B + (size_t)(koff + b_k) * ldb + colbase + b_nch0 * 4;

    float acc[4][8][4];
#pragma unroll
    for (int mi = 0; mi < 4; mi++)
#pragma unroll
        for (int ni = 0; ni < 8; ni++)
#pragma unroll
            for (int rr = 0; rr < 4; rr++) acc[mi][ni][rr] = 0.f;

    const int lr = lane >> 2, lc = lane & 3;

#define MQ_LOAD(stg, k0) do { \
    uint32_t ab_ = sbase + (stg) * (G4_STAGE_W * 4); \
    _Pragma("unroll") for (int i = 0; i < 8; i++) { \
        uint32_t so_ = SW128B((uint32_t)((a_row0 + 16 * i) * 128 + a_ch * 16)); \
        cpasync16(ab_ + so_, Ag + (size_t)(16 * i) * 1024 + (k0)); \
    } \
    uint32_t bb_ = ab_ + 4096 * 4; \
    _Pragma("unroll") for (int i = 0; i < 8; i++) { \
        int n_ = (b_nch0 + 4 * i) * 4; \
        uint32_t w_ = (uint32_t)(b_k * 128 + (n_ ^ ((b_k & 3) << 3))); \
        cpasync16(bb_ + w_ * 4, Bg + (size_t)(k0) * ldb + 16 * i); \
    } \
    CP_COMMIT(); \
} while (0)

    MQ_LOAD(0, 0);
    if (niter > 1) MQ_LOAD(1, 32);

    for (int it = 0; it < niter; it++) {
        if (it + 1 < niter) {
            asm volatile("cp.async.wait_group 1;" ::: "memory");
        } else {
            asm volatile("cp.async.wait_group 0;" ::: "memory");
        }
        __syncthreads();
        if (it + 2 < niter) MQ_LOAD((it + 2) % 3, (it + 2) * 32);

        const uint32_t* Abuf = dsm + (it % 3) * G4_STAGE_W;
        const uint32_t* Bbuf = Abuf + 4096;
#pragma unroll
        for (int kk = 0; kk < 4; kk++) {
            uint4 af[4]; uint2 bf[8];
#pragma unroll
            for (int mi = 0; mi < 4; mi++) {
                int row = wm * 64 + mi * 16 + lr;
                int k = kk * 8 + lc;
                af[mi].x = Abuf[SW128B((uint32_t)(row * 128 + k * 4)) >> 2];
                af[mi].y = Abuf[SW128B((uint32_t)((row + 8) * 128 + k * 4)) >> 2];
                af[mi].z = Abuf[SW128B((uint32_t)(row * 128 + (k + 4) * 4)) >> 2];
                af[mi].w = Abuf[SW128B((uint32_t)((row + 8) * 128 + (k + 4) * 4)) >> 2];
            }
#pragma unroll
            for (int ni = 0; ni < 8; ni++) {
                int n = wn * 64 + ni * 8 + lr;
                int kb = kk * 8 + lc;
                int nsw = n ^ (lc << 3);
                bf[ni].x = Bbuf[kb * 128 + nsw];
                bf[ni].y = Bbuf[(kb + 4) * 128 + nsw];
            }
#pragma unroll
            for (int mi = 0; mi < 4; mi++)
#pragma unroll
                for (int ni = 0; ni < 8; ni++) MMA_TF32(acc[mi][ni], af[mi], bf[ni]);
        }
    }
#undef MQ_LOAD

#pragma unroll
    for (int mi = 0; mi < 4; mi++) {
#pragma unroll
        for (int ni = 0; ni < 8; ni++) {
            int row0 = rowbase + wm * 64 + mi * 16 + lr;
            int col  = colbase + wn * 64 + ni * 8 + lc * 2;
            float v0 = acc[mi][ni][0], v1 = acc[mi][ni][1];
            float v2 = acc[mi][ni][2], v3 = acc[mi][ni][3];
            if (cvt) {
                v0 = f2tf32f(v0); v1 = f2tf32f(v1);
                v2 = f2tf32f(v2); v3 = f2tf32f(v3);
            }
            *(float2*)(C + (size_t)row0 * ldc + col)       = make_float2(v0, v1);
            *(float2*)(C + (size_t)(row0 + 8) * ldc + col) = make_float2(v2, v3);
        }
    }
}

// ======== score_both: AC (mode 0, plain store) and BD (mode 1, SHIFTED store) ====
#define SC_SMEM (4 * 4096 * 4)
__global__ void __launch_bounds__(128) score_both(
    const float* __restrict__ qu, const float* __restrict__ qv,
    const float* __restrict__ heads, const float* __restrict__ rkc,
    float* __restrict__ ac, float* __restrict__ bd)
{
    const int bx = blockIdx.x, by = blockIdx.y, z = blockIdx.z;
    const int mode = (z >= BH) ? 1 : 0;
    const int bh = mode ? z - BH : z;
    const int i0 = by * 128, j0 = bx * 128;
    if (mode == 0) { if (j0 >= i0 + 640) return; }
    else           { if (i0 + j0 < 257) return; }
    const int bb = bh >> 4, nn = bh & 15;
    const float* A = (mode ? qv : qu) + (size_t)bh * QLEN * 64 + (size_t)i0 * 64;
    const float* B;
    size_t ldbB;
    if (mode == 0) {
        B = heads + (size_t)(j0 * 4 + bb) * 3072 + 1024 + (size_t)nn * 64;
        ldbB = 4 * 3072;
    } else {
        B = rkc + (size_t)nn * KLEN * 64 + (size_t)j0 * 64;
        ldbB = 64;
    }

    extern __shared__ uint32_t dsm[];
    const uint32_t sbase = smem_u32(dsm);
    const int tid = threadIdx.x, lane = tid & 31;
    const int warp = tid >> 5, wm = warp >> 1, wn = warp & 1;

    const int a_row0 = tid >> 3, a_ch = tid & 7;
    const float* Ag = A + (size_t)a_row0 * 64 + a_ch * 4;
    const float* Bg = B + (size_t)a_row0 * ldbB + a_ch * 4;

    float acc[4][8][4];
#pragma unroll
    for (int mi = 0; mi < 4; mi++)
#pragma unroll
        for (int ni = 0; ni < 8; ni++)
#pragma unroll
            for (int r = 0; r < 4; r++) acc[mi][ni][r] = 0.f;

    const int lr = lane >> 2, lc = lane & 3;

#define SC_LOAD(stg, k0) do { \
    uint32_t ab_ = sbase + (stg) * 32768; \
    uint32_t bb_ = ab_ + 16384; \
    _Pragma("unroll") for (int i = 0; i < 8; i++) { \
        uint32_t so_ = SW128B((uint32_t)((a_row0 + 16 * i) * 128 + a_ch * 16)); \
        cpasync16(ab_ + so_, Ag + (size_t)(16 * i) * 64 + (k0)); \
        cpasync16(bb_ + so_, Bg + (size_t)(16 * i) * ldbB + (k0)); \
    } \
    CP_COMMIT(); \
} while (0)

    SC_LOAD(0, 0);
    SC_LOAD(1, 32);

#pragma unroll
    for (int it = 0; it < 2; it++) {
        if (it == 0) asm volatile("cp.async.wait_group 1;" ::: "memory");
        else         asm volatile("cp.async.wait_group 0;" ::: "memory");
        __syncthreads();
        const uint32_t* Abuf = dsm + it * 8192;
        const uint32_t* Bbuf = Abuf + 4096;
#pragma unroll
        for (int kk = 0; kk < 4; kk++) {
            uint4 af[4]; uint2 bf[8];
#pragma unroll
            for (int mi = 0; mi < 4; mi++) {
                int row = wm * 64 + mi * 16 + lr;
                int k = kk * 8 + lc;
                af[mi].x = Abuf[SW128B((uint32_t)(row * 128 + k * 4)) >> 2];
                af[mi].y = Abuf[SW128B((uint32_t)((row + 8) * 128 + k * 4)) >> 2];
                af[mi].z = Abuf[SW128B((uint32_t)(row * 128 + (k + 4) * 4)) >> 2];
                af[mi].w = Abuf[SW128B((uint32_t)((row + 8) * 128 + (k + 4) * 4)) >> 2];
            }
#pragma unroll
            for (int ni = 0; ni < 8; ni++) {
                int n = wn * 64 + ni * 8 + lr;
                int k = kk * 8 + lc;
                bf[ni].x = Bbuf[SW128B((uint32_t)(n * 128 + k * 4)) >> 2];
                bf[ni].y = Bbuf[SW128B((uint32_t)(n * 128 + (k + 4) * 4)) >> 2];
            }
#pragma unroll
            for (int mi = 0; mi < 4; mi++)
#pragma unroll
                for (int ni = 0; ni < 8; ni++) MMA_TF32(acc[mi][ni], af[mi], bf[ni]);
        }
    }
#undef SC_LOAD

    if (mode == 0) {
        float* ob = ac + (size_t)bh * QLEN * KLEN;
#pragma unroll
        for (int mi = 0; mi < 4; mi++)
#pragma unroll
            for (int ni = 0; ni < 8; ni++) {
                int row0 = i0 + wm * 64 + mi * 16 + lr;
                int col  = j0 + wn * 64 + ni * 8 + lc * 2;
                *(float2*)(ob + (size_t)row0 * KLEN + col) =
                    make_float2(acc[mi][ni][0], acc[mi][ni][1]);
                *(float2*)(ob + (size_t)(row0 + 8) * KLEN + col) =
                    make_float2(acc[mi][ni][2], acc[mi][ni][3]);
            }
    } else {
        float* ob = bd + (size_t)bh * QLEN * KLEN;
#pragma unroll
        for (int mi = 0; mi < 4; mi++)
#pragma unroll
            for (int ni = 0; ni < 8; ni++) {
                int r0 = i0 + wm * 64 + mi * 16 + lr;
                int r1 = r0 + 8;
                int c0 = j0 + wn * 64 + ni * 8 + lc * 2;
                int jp;
                jp = c0 + r0 - 511;
                if (jp >= 0) ob[(size_t)r0 * KLEN + jp] = acc[mi][ni][0];
                jp = c0 + 1 + r0 - 511;
                if (jp >= 0) ob[(size_t)r0 * KLEN + jp] = acc[mi][ni][1];
                jp = c0 + r1 - 511;
                if (jp >= 0) ob[(size_t)r1 * KLEN + jp] = acc[mi][ni][2];
                jp = c0 + 1 + r1 - 511;
                if (jp >= 0) ob[(size_t)r1 * KLEN + jp] = acc[mi][ni][3];
            }
    }
}

// ======== av3: fused (softmax no-max) + P@V ========
#define AV3_STAGE_W 10240
#define AV3_SMEM (2 * AV3_STAGE_W * 4)
__global__ void __launch_bounds__(128) av3(
    const float* __restrict__ ac, const float* __restrict__ bd,
    const float* __restrict__ heads, float* __restrict__ av)
{
    extern __shared__ uint32_t dsm[];
    const uint32_t sbase = smem_u32(dsm);
    const int by = blockIdx.x, bh = blockIdx.y;
    const int b = bh >> 4, n_h = bh & 15;
    const float* acb = ac + (size_t)bh * QLEN * KLEN + (size_t)by * 128 * KLEN;
    const float* bdb = bd + (size_t)bh * QLEN * KLEN + (size_t)by * 128 * KLEN;
    const float* Vb = heads + (size_t)b * 3072 + 2048 + (size_t)n_h * 64;
    const size_t ldv = 4 * 3072;
    const int kmax = min(KLEN, by * 128 + 640);

    const int tid = threadIdx.x, lane = tid & 31;
    const int warp = tid >> 5, wm = warp >> 1, wn = warp & 1;
    const int lr = lane >> 2, lc = lane & 3;

    const int a_row0 = tid >> 3, a_ch = tid & 7;
    const float* Acg = acb + (size_t)a_row0 * KLEN + a_ch * 4;
    const float* Bdg = bdb + (size_t)a_row0 * KLEN + a_ch * 4;
    const int b_k = tid >> 2, b_nch0 = tid & 3;
    const float* Bg = Vb + (size_t)b_k * ldv + b_nch0 * 4;

    float acc[4][4][4];
#pragma unroll
    for (int mi = 0; mi < 4; mi++)
#pragma unroll
        for (int ni = 0; ni < 4; ni++)
#pragma unroll
            for (int r = 0; r < 4; r++) acc[mi][ni][r] = 0.f;
    float lsum[4][2];
#pragma unroll
    for (int mi = 0; mi < 4; mi++) { lsum[mi][0] = 0.f; lsum[mi][1] = 0.f; }

    int jm[4][2];
#pragma unroll
    for (int mi = 0; mi < 4; mi++)
#pragma unroll
        for (int h = 0; h < 2; h++)
            jm[mi][h] = by * 128 + wm * 64 + mi * 16 + lr + 8 * h + 512;

    const int niter = kmax >> 5;

#define AV3_LOAD(stg, k0) do { \
    uint32_t base_ = sbase + (stg) * (AV3_STAGE_W * 4); \
    _Pragma("unroll") for (int i = 0; i < 8; i++) { \
        uint32_t so_ = SW128B((uint32_t)((a_row0 + 16 * i) * 128 + a_ch * 16)); \
        cpasync16(base_ + so_, Acg + (size_t)(16 * i) * KLEN + (k0)); \
        cpasync16(base_ + 16384 + so_, Bdg + (size_t)(16 * i) * KLEN + (k0)); \
    } \
    _Pragma("unroll") for (int i = 0; i < 4; i++) { \
        int n_ = (b_nch0 + 4 * i) * 4; \
        uint32_t w_ = (uint32_t)(b_k * 64 + (n_ ^ ((b_k & 3) << 3))); \
        cpasync16(base_ + 32768 + w_ * 4, Bg + (size_t)(k0) * ldv + 16 * i); \
    } \
    CP_COMMIT(); \
} while (0)

    AV3_LOAD(0, 0);
    if (niter > 1) AV3_LOAD(1, 32);

    for (int it = 0; it < niter; it++) {
        if (it + 1 < niter) {
            asm volatile("cp.async.wait_group 1;" ::: "memory");
        } else {
            asm volatile("cp.async.wait_group 0;" ::: "memory");
        }
        __syncthreads();

        const uint32_t* Sac = dsm + (it & 1) * AV3_STAGE_W;
        const uint32_t* Sbd = Sac + 4096;
        const uint32_t* Sv  = Sac + 8192;
        const int jb = it * 32;
#pragma unroll
        for (int kk = 0; kk < 4; kk++) {
            const int j1 = jb + kk * 8 + lc;
            const int j2 = j1 + 4;
            uint4 af[4];
#pragma unroll
            for (int mi = 0; mi < 4; mi++) {
                int row = wm * 64 + mi * 16 + lr;
                int k = kk * 8 + lc;
                uint32_t o00 = SW128B((uint32_t)(row * 128 + k * 4)) >> 2;
                uint32_t o10 = SW128B((uint32_t)((row + 8) * 128 + k * 4)) >> 2;
                uint32_t o01 = SW128B((uint32_t)(row * 128 + (k + 4) * 4)) >> 2;
                uint32_t o11 = SW128B((uint32_t)((row + 8) * 128 + (k + 4) * 4)) >> 2;
                float sx = 0.125f * (__uint_as_float(Sac[o00]) + __uint_as_float(Sbd[o00]));
                float sy = 0.125f * (__uint_as_float(Sac[o10]) + __uint_as_float(Sbd[o10]));
                float sz = 0.125f * (__uint_as_float(Sac[o01]) + __uint_as_float(Sbd[o01]));
                float sw = 0.125f * (__uint_as_float(Sac[o11]) + __uint_as_float(Sbd[o11]));
                float px = (j1 <= jm[mi][0]) ? __expf(sx) : 0.f;
                float py = (j1 <= jm[mi][1]) ? __expf(sy) : 0.f;
                float pz = (j2 <= jm[mi][0]) ? __expf(sz) : 0.f;
                float pw = (j2 <= jm[mi][1]) ? __expf(sw) : 0.f;
                uint32_t rx = f2tf32(px), ry = f2tf32(py);
                uint32_t rz = f2tf32(pz), rw = f2tf32(pw);
                lsum[mi][0] += __uint_as_float(rx) + __uint_as_float(rz);
                lsum[mi][1] += __uint_as_float(ry) + __uint_as_float(rw);
                af[mi].x = rx; af[mi].y = ry; af[mi].z = rz; af[mi].w = rw;
            }
            uint2 bf[4];
#pragma unroll
            for (int ni = 0; ni < 4; ni++) {
                int n = wn * 32 + ni * 8 + lr;
                int kb = kk * 8 + lc;
                int nsw = n ^ (lc << 3);
                bf[ni].x = Sv[kb * 64 + nsw];
                bf[ni].y = Sv[(kb + 4) * 64 + nsw];
            }
#pragma unroll
            for (int mi = 0; mi < 4; mi++)
#pragma unroll
                for (int ni = 0; ni < 4; ni++) MMA_TF32(acc[mi][ni], af[mi], bf[ni]);
        }
        __syncthreads();
        if (it + 2 < niter) AV3_LOAD(it & 1, (it + 2) * 32);
    }
#undef AV3_LOAD

    float inv[4][2];
#pragma unroll
    for (int mi = 0; mi < 4; mi++)
#pragma unroll
        for (int h = 0; h < 2; h++) {
            float l = lsum[mi][h];
            l += __shfl_xor_sync(0xFFFFFFFF, l, 1);
            l += __shfl_xor_sync(0xFFFFFFFF, l, 2);
            inv[mi][h] = 1.0f / l;
        }

#pragma unroll
    for (int mi = 0; mi < 4; mi++)
#pragma unroll
        for (int ni = 0; ni < 4; ni++) {
            int row0 = by * 128 + wm * 64 + mi * 16 + lr;
            int col  = wn * 32 + ni * 8 + lc * 2;
            *(float2*)(av + ((size_t)row0 * 4 + b) * 1024 + n_h * 64 + col) =
                make_float2(f2tf32f(acc[mi][ni][0] * inv[mi][0]),
                            f2tf32f(acc[mi][ni][1] * inv[mi][0]));
            *(float2*)(av + ((size_t)(row0 + 8) * 4 + b) * 1024 + n_h * 64 + col) =
                make_float2(f2tf32f(acc[mi][ni][2] * inv[mi][1]),
                            f2tf32f(acc[mi][ni][3] * inv[mi][1]));
        }
}

// ---------------- fused weight rounding ----------------
__global__ void roundw5_kernel(
    float4* d0, const float4* s0, size_t n0,
    float4* d1, const float4* s1, size_t n1,
    float4* d2, const float4* s2, size_t n2,
    float4* d3, const float4* s3, size_t n3,
    float4* d4, const float4* s4, size_t n4)
{
    size_t i = (size_t)blockIdx.x * 256 + threadIdx.x;
    float4* d; const float4* s;
    if (i < n0) { d = d0; s = s0; }
    else { i -= n0;
    if (i < n1) { d = d1; s = s1; }
    else { i -= n1;
    if (i < n2) { d = d2; s = s2; }
    else { i -= n2;
    if (i < n3) { d = d3; s = s3; }
    else { i -= n3;
    if (i < n4) { d = d4; s = s4; }
    else return; }}}}
    float4 v = s[i];
    d[i] = make_float4(f2tf32f(v.x), f2tf32f(v.y), f2tf32f(v.z), f2tf32f(v.w));
}

// generic rounding copy (used for mems and x->h)
__global__ void roundcp_kernel(float4* __restrict__ dst, const float4* __restrict__ src) {
    size_t i = (size_t)blockIdx.x * 256 + threadIdx.x;
    float4 v = src[i];
    dst[i] = make_float4(f2tf32f(v.x), f2tf32f(v.y), f2tf32f(v.z), f2tf32f(v.w));
}

// ---------------- small kernels ----------------
__global__ void posemb_kernel(float* __restrict__ r) {
    int idx = blockIdx.x * 256 + threadIdx.x;
    int k = idx >> 10, d = idx & 1023;
    float pos = (float)(KLEN - 1 - k);
    int j = (d < 512) ? d : d - 512;
    float inv = expf(-((float)(2 * j) / 1024.0f) * 9.210340371976184f);
    float ang = pos * inv;
    r[idx] = f2tf32f((d < 512) ? sinf(ang) : cosf(ang));
}

// merged repacks: blocks [0,2048) -> quqv, [2048,3072) -> rk
__global__ void repack_both(const float* __restrict__ q0, const float* __restrict__ q1,
                            const float* __restrict__ u, const float* __restrict__ v,
                            float* __restrict__ qu, float* __restrict__ qv,
                            const float* __restrict__ p0, const float* __restrict__ p1,
                            float* __restrict__ rkc) {
    int blk = blockIdx.x;
    int tid = threadIdx.x;
    if (blk < 2048) {
        int idx = blk * 256 + tid;
        int d4 = idx & 15, i = (idx >> 4) & 511, bh = idx >> 13;
        int b = bh >> 4, n = bh & 15;
        size_t qoff = ((size_t)(i * 4 + b)) * 1024 + n * 64 + d4 * 4;
        float4 qa = *(const float4*)(q0 + qoff);
        float4 qb = *(const float4*)(q1 + qoff);
        float4 uu = *(const float4*)(u + n * 64 + d4 * 4);
        float4 vv = *(const float4*)(v + n * 64 + d4 * 4);
        float qx = qa.x + qb.x, qy = qa.y + qb.y, qz = qa.z + qb.z, qw = qa.w + qb.w;
        size_t o = ((size_t)bh * 512 + i) * 64 + d4 * 4;
        *(float4*)(qu + o) = make_float4(f2tf32f(qx + uu.x), f2tf32f(qy + uu.y),
                                         f2tf32f(qz + uu.z), f2tf32f(qw + uu.w));
        *(float4*)(qv + o) = make_float4(f2tf32f(qx + vv.x), f2tf32f(qy + vv.y),
                                         f2tf32f(qz + vv.z), f2tf32f(qw + vv.w));
    } else {
        int idx = (blk - 2048) * 256 + tid;
        int d4 = idx & 15, j = (idx >> 4) & 1023, n = idx >> 14;
        size_t off = (size_t)j * 1024 + n * 64 + d4 * 4;
        float4 a = *(const float4*)(p0 + off);
        float4 b = *(const float4*)(p1 + off);
        *(float4*)(rkc + ((size_t)n * 1024 + j) * 64 + d4 * 4) =
            make_float4(f2tf32f(a.x + b.x), f2tf32f(a.y + b.y),
                        f2tf32f(a.z + b.z), f2tf32f(a.w + b.w));
    }
}

// ---------------- residual + 2 partials + LayerNorm (output rounded) ----------------
__global__ void __launch_bounds__(256) add_ln3_kernel(
    float* __restrict__ h, const float* __restrict__ t0, const float* __restrict__ t1,
    const float* __restrict__ g, const float* __restrict__ b)
{
    int row = blockIdx.x;
    int tid = threadIdx.x;
    __shared__ float rs[256], rs2[256];
    float x[4];
    float s = 0.f, ss = 0.f;
#pragma unroll
    for (int c = 0; c < 4; c++) {
        int d = c * 256 + tid;
        size_t o = (size_t)row * 1024 + d;
        float v = h[o] + t0[o] + t1[o];
        x[c] = v; s += v; ss += v * v;
    }
    rs[tid] = s; rs2[tid] = ss; __syncthreads();
    for (int o = 128; o > 0; o >>= 1) {
        if (tid < o) { rs[tid] += rs[tid + o]; rs2[tid] += rs2[tid + o]; }
        __syncthreads();
    }
    float mu = rs[0] * (1.0f / 1024.0f);
    float var = rs2[0] * (1.0f / 1024.0f) - mu * mu;
    float inv = rsqrtf(var + 1e-5f);
#pragma unroll
    for (int c = 0; c < 4; c++) {
        int d = c * 256 + tid;
        h[(size_t)row * 1024 + d] = f2tf32f((x[c] - mu) * inv * g[d] + b[d]);
    }
}

// ---------------- launch ----------------
extern "C" void kernel_launch(void* const* d_in, const int* in_sizes, int n_in,
                              void* d_out, int out_size) {
    (void)in_sizes; (void)n_in; (void)out_size;
    const float* x     = (const float*)d_in[0];
    const float* mems  = (const float*)d_in[1];
    const float* u     = (const float*)d_in[2];
    const float* v     = (const float*)d_in[3];
    const float* W_qkv = (const float*)d_in[4];
    const float* W_o   = (const float*)d_in[5];
    const float* W_r   = (const float*)d_in[6];
    const float* ln1_g = (const float*)d_in[7];
    const float* ln1_b = (const float*)d_in[8];
    const float* W1    = (const float*)d_in[9];
    const float* b1    = (const float*)d_in[10];
    const float* W2    = (const float*)d_in[11];
    const float* b2    = (const float*)d_in[12];
    const float* ln2_g = (const float*)d_in[13];
    const float* ln2_b = (const float*)d_in[14];

    float *memsr, *heads, *r, *ac, *bd, *av, *tmp, *tmp2, *h, *ff, *qu, *qv, *rkc;
    float *wqkv, *wr, *wo, *w1, *w2;
    cudaGetSymbolAddress((void**)&memsr, g_memsr);
    cudaGetSymbolAddress((void**)&heads, g_heads);
    cudaGetSymbolAddress((void**)&r,     g_r);
    cudaGetSymbolAddress((void**)&ac,    g_ac);
    cudaGetSymbolAddress((void**)&bd,    g_bd);
    cudaGetSymbolAddress((void**)&av,    g_av);
    cudaGetSymbolAddress((void**)&tmp,   g_tmp);
    cudaGetSymbolAddress((void**)&tmp2,  g_tmp2);
    cudaGetSymbolAddress((void**)&h,     g_h);
    cudaGetSymbolAddress((void**)&ff,    g_ff);
    cudaGetSymbolAddress((void**)&qu,    g_qu);
    cudaGetSymbolAddress((void**)&qv,    g_qv);
    cudaGetSymbolAddress((void**)&rkc,   g_rkc);
    cudaGetSymbolAddress((void**)&wqkv,  g_wqkv);
    cudaGetSymbolAddress((void**)&wr,    g_wr);
    cudaGetSymbolAddress((void**)&wo,    g_wo);
    cudaGetSymbolAddress((void**)&w1,    g_w1);
    cudaGetSymbolAddress((void**)&w2,    g_w2);

    cudaFuncSetAttribute(gemm4<0,0,0>, cudaFuncAttributeMaxDynamicSharedMemorySize, G4_SMEM);
    cudaFuncSetAttribute(gemm4<1,1,1>, cudaFuncAttributeMaxDynamicSharedMemorySize, G4_SMEM);
    cudaFuncSetAttribute(gemm4<0,1,0>, cudaFuncAttributeMaxDynamicSharedMemorySize, G4_SMEM);
    cudaFuncSetAttribute(mega_qkv,     cudaFuncAttributeMaxDynamicSharedMemorySize, G4_SMEM);
    cudaFuncSetAttribute(score_both,   cudaFuncAttributeMaxDynamicSharedMemorySize, SC_SMEM);
    cudaFuncSetAttribute(av3,          cudaFuncAttributeMaxDynamicSharedMemorySize, AV3_SMEM);

    // one-time weight rounding (single fused launch) + mems rounding + x->h
    {
        size_t n0 = (size_t)NLAYER*DMODEL*3072/4, n1 = (size_t)NLAYER*DMODEL*DMODEL/4;
        size_t n2 = n1, n3 = (size_t)NLAYER*DMODEL*DINNER/4, n4 = n3;
        size_t ntot = n0 + n1 + n2 + n3 + n4;
        roundw5_kernel<<<(unsigned)((ntot + 255) / 256), 256>>>(
            (float4*)wqkv, (const float4*)W_qkv, n0,
            (float4*)wr,   (const float4*)W_r,   n1,
            (float4*)wo,   (const float4*)W_o,   n2,
            (float4*)w1,   (const float4*)W1,    n3,
            (float4*)w2,   (const float4*)W2,    n4);
    }
    roundcp_kernel<<<(NLAYER*MLEN*BATCH*DMODEL/4)/256, 256>>>(
        (float4*)memsr, (const float4*)mems);
    roundcp_kernel<<<(QLEN*BATCH*DMODEL/4)/256, 256>>>((float4*)h, (const float4*)x);
    posemb_kernel<<<4096, 256>>>(r);

    for (int l = 0; l < NLAYER; l++) {
        const float* Wq = wqkv + (size_t)l * DMODEL * 3072;
        // KV + Q(2 halves) + rk(2 halves), one dense launch
        mega_qkv<<<dim3(16, 56), 128, G4_SMEM>>>(
            memsr + (size_t)l * MLEN * BATCH * DMODEL, h, r,
            Wq, wr + (size_t)l * DMODEL * DMODEL,
            heads, tmp, tmp2, bd, bd + (size_t)1024 * 1024);
        // merged repacks
        repack_both<<<3072, 256>>>(tmp, tmp2, u, v, qu, qv,
                                   bd, bd + (size_t)1024 * 1024, rkc);
        // scores: AC plain + BD shifted, one launch
        score_both<<<dim3(8, 4, 2 * BH), 128, SC_SMEM>>>(qu, qv, heads, rkc, ac, bd);
        // fused softmax + P@V
        av3<<<dim3(4, BH), 128, AV3_SMEM>>>(ac, bd, heads, av);
        // O projection: split-K=2
        gemm4<0,0,0><<<dim3(8, 16, 2), 128, G4_SMEM>>>(
            av, wo + (size_t)l * DMODEL * DMODEL, nullptr, tmp, tmp2,
            512, 1024, 1024, 1024);
        add_ln3_kernel<<<2048, 256>>>(h, tmp, tmp2,
                                      ln1_g + (size_t)l * DMODEL, ln1_b + (size_t)l * DMODEL);
        // FFN
        gemm4<1,1,1><<<dim3(32, 16, 1), 128, G4_SMEM>>>(
            h, w1 + (size_t)l * DMODEL * DINNER, b1 + (size_t)l * DINNER, ff, nullptr,
            1024, 1024, 4096, 4096);
        gemm4<0,1,0><<<dim3(8, 16, 2), 128, G4_SMEM>>>(
            ff, w2 + (size_t)l * DINNER * DMODEL, b2 + (size_t)l * DMODEL, tmp, tmp2,
            2048, 4096, 1024, 1024);
        add_ln3_kernel<<<2048, 256>>>(h, tmp, tmp2,
                                      ln2_g + (size_t)l * DMODEL, ln2_b + (size_t)l * DMODEL);
    }

    cudaMemcpyAsync(d_out, h, (size_t)QLEN * BATCH * DMODEL * sizeof(float),
                    cudaMemcpyDeviceToDevice);
}

// round 17
// speedup vs baseline: 1.2492x; 1.0227x over previous
#include <cuda_runtime.h>
#include <math.h>
#include <stdint.h>

#define QLEN 512
#define BATCH 4
#define DMODEL 1024
#define NLAYER 4
#define NHEAD 16
#define DHEAD 64
#define DINNER 4096
#define MLEN 512
#define KLEN 1024
#define BH (BATCH*NHEAD)

// ---------------- scratch ----------------
__device__ float g_memsr[(size_t)NLAYER*MLEN*BATCH*DMODEL];
__device__ float g_heads[(size_t)KLEN*BATCH*3*DMODEL];
__device__ float g_r[(size_t)KLEN*DMODEL];
__device__ float g_ac[(size_t)BH*QLEN*KLEN];
__device__ float g_bd[(size_t)BH*QLEN*KLEN];
__device__ float g_av[(size_t)QLEN*BATCH*DMODEL];
__device__ float g_tmp[(size_t)QLEN*BATCH*DMODEL];
__device__ float g_tmp2[(size_t)QLEN*BATCH*DMODEL];
__device__ float g_h[(size_t)QLEN*BATCH*DMODEL];
__device__ float g_ff[(size_t)QLEN*BATCH*DINNER];
__device__ float g_qu[(size_t)BH*QLEN*DHEAD];
__device__ float g_qv[(size_t)BH*QLEN*DHEAD];
__device__ float g_rkc[(size_t)NHEAD*KLEN*DHEAD];
// tf32-rounded weight copies
__device__ float g_wqkv[(size_t)NLAYER*DMODEL*3072];
__device__ float g_wr[(size_t)NLAYER*DMODEL*DMODEL];
__device__ float g_wo[(size_t)NLAYER*DMODEL*DMODEL];
__device__ float g_w1[(size_t)NLAYER*DMODEL*DINNER];
__device__ float g_w2[(size_t)NLAYER*DINNER*DMODEL];

__device__ __forceinline__ uint32_t f2tf32(float f) {
    uint32_t o;
    asm("cvt.rna.tf32.f32 %0, %1;" : "=r"(o) : "f"(f));
    return o;
}
__device__ __forceinline__ float f2tf32f(float f) {
    uint32_t o = f2tf32(f);
    return __uint_as_float(o);
}

#define MMA_TF32(d, a, b) \
    asm volatile("mma.sync.aligned.m16n8k8.row.col.f32.tf32.tf32.f32 " \
                 "{%0,%1,%2,%3}, {%4,%5,%6,%7}, {%8,%9}, {%0,%1,%2,%3};" \
                 : "+f"(d[0]), "+f"(d[1]), "+f"(d[2]), "+f"(d[3]) \
                 : "r"(a.x), "r"(a.y), "r"(a.z), "r"(a.w), "r"(b.x), "r"(b.y))

__device__ __forceinline__ void cpasync16(uint32_t dst, const void* src) {
    asm volatile("cp.async.cg.shared.global [%0], [%1], 16;" :: "r"(dst), "l"(src));
}
#define CP_COMMIT() asm volatile("cp.async.commit_group;" ::: "memory")
__device__ __forceinline__ uint32_t smem_u32(const void* p) {
    uint32_t a;
    asm("{ .reg .u64 t; cvta.to.shared.u64 t, %1; cvt.u32.u64 %0, t; }" : "=r"(a) : "l"(p));
    return a;
}
#define SW128B(o) ((o) ^ (((o) >> 3) & 0x70))

// gemm4: 3 stages x (A 4096 + B 4096) words
#define G4_STAGE_W 8192
#define G4_SMEM (3 * G4_STAGE_W * 4)

// ======== gemm4: C[M,N]=A[M,K]@B[K,N]. 128 thr, CTA 128x128, warp 64x64 ========
template<int RELU, int HASBIAS, int CVT>
__global__ void __launch_bounds__(128) gemm4(
    const float* __restrict__ A, const float* __restrict__ B,
    const float* __restrict__ bias, float* __restrict__ C0, float* __restrict__ C1,
    int K, int lda, int ldb, int ldc)
{
    extern __shared__ uint32_t dsm[];
    const uint32_t sbase = smem_u32(dsm);
    const int tid = threadIdx.x, lane = tid & 31;
    const int warp = tid >> 5, wm = warp >> 1, wn = warp & 1;
    const int bx = blockIdx.x, by = blockIdx.y, bz = blockIdx.z;

    const int koff = bz * K;
    float* C = bz ? C1 : C0;

    const int a_row0 = tid >> 3, a_ch = tid & 7;
    const float* Ag = A + (size_t)(by * 128 + a_row0) * lda + koff + a_ch * 4;
    const int b_k = tid >> 2, b_nch0 = tid & 3;
    const float* Bg = B + (size_t)(koff + b_k) * ldb + bx * 128 + b_nch0 * 4;

    float acc[4][8][4];
#pragma unroll
    for (int mi = 0; mi < 4; mi++)
#pragma unroll
        for (int ni = 0; ni < 8; ni++)
#pragma unroll
            for (int r = 0; r < 4; r++) acc[mi][ni][r] = 0.f;

    const int lr = lane >> 2, lc = lane & 3;
    const int niter = K >> 5;

#define G4_LOAD(stg, k0) do { \
    uint32_t ab_ = sbase + (stg) * (G4_STAGE_W * 4); \
    _Pragma("unroll") for (int i = 0; i < 8; i++) { \
        uint32_t so_ = SW128B((uint32_t)((a_row0 + 16 * i) * 128 + a_ch * 16)); \
        cpasync16(ab_ + so_, Ag + (size_t)(16 * i) * lda + (k0)); \
    } \
    uint32_t bb_ = ab_ + 4096 * 4; \
    _Pragma("unroll") for (int i = 0; i < 8; i++) { \
        int n_ = (b_nch0 + 4 * i) * 4; \
        uint32_t w_ = (uint32_t)(b_k * 128 + (n_ ^ ((b_k & 3) << 3))); \
        cpasync16(bb_ + w_ * 4, Bg + (size_t)(k0) * ldb + 16 * i); \
    } \
    CP_COMMIT(); \
} while (0)

    G4_LOAD(0, 0);
    if (niter > 1) G4_LOAD(1, 32);

    for (int it = 0; it < niter; it++) {
        if (it + 1 < niter) {
            asm volatile("cp.async.wait_group 1;" ::: "memory");
        } else {
            asm volatile("cp.async.wait_group 0;" ::: "memory");
        }
        __syncthreads();
        if (it + 2 < niter) G4_LOAD((it + 2) % 3, (it + 2) * 32);

        const uint32_t* Abuf = dsm + (it % 3) * G4_STAGE_W;
        const uint32_t* Bbuf = Abuf + 4096;
#pragma unroll
        for (int kk = 0; kk < 4; kk++) {
            uint4 af[4]; uint2 bf[8];
#pragma unroll
            for (int mi = 0; mi < 4; mi++) {
                int row = wm * 64 + mi * 16 + lr;
                int k = kk * 8 + lc;
                af[mi].x = Abuf[SW128B((uint32_t)(row * 128 + k * 4)) >> 2];
                af[mi].y = Abuf[SW128B((uint32_t)((row + 8) * 128 + k * 4)) >> 2];
                af[mi].z = Abuf[SW128B((uint32_t)(row * 128 + (k + 4) * 4)) >> 2];
                af[mi].w = Abuf[SW128B((uint32_t)((row + 8) * 128 + (k + 4) * 4)) >> 2];
            }
#pragma unroll
            for (int ni = 0; ni < 8; ni++) {
                int n = wn * 64 + ni * 8 + lr;
                int kb = kk * 8 + lc;
                int nsw = n ^ (lc << 3);
                bf[ni].x = Bbuf[kb * 128 + nsw];
                bf[ni].y = Bbuf[(kb + 4) * 128 + nsw];
            }
#pragma unroll
            for (int mi = 0; mi < 4; mi++)
#pragma unroll
                for (int ni = 0; ni < 8; ni++) MMA_TF32(acc[mi][ni], af[mi], bf[ni]);
        }
    }
#undef G4_LOAD

    const bool dobias = HASBIAS && (bz == 0);
#pragma unroll
    for (int mi = 0; mi < 4; mi++) {
#pragma unroll
        for (int ni = 0; ni < 8; ni++) {
            int row0 = by * 128 + wm * 64 + mi * 16 + lr;
            int col  = bx * 128 + wn * 64 + ni * 8 + lc * 2;
            float b0 = 0.f, b1 = 0.f;
            if (dobias) { b0 = bias[col]; b1 = bias[col + 1]; }
            float v0 = acc[mi][ni][0] + b0, v1 = acc[mi][ni][1] + b1;
            float v2 = acc[mi][ni][2] + b0, v3 = acc[mi][ni][3] + b1;
            if (RELU) {
                v0 = fmaxf(v0, 0.f); v1 = fmaxf(v1, 0.f);
                v2 = fmaxf(v2, 0.f); v3 = fmaxf(v3, 0.f);
            }
            if (CVT) {
                v0 = f2tf32f(v0); v1 = f2tf32f(v1);
                v2 = f2tf32f(v2); v3 = f2tf32f(v3);
            }
            *(float2*)(C + (size_t)row0 * ldc + col)       = make_float2(v0, v1);
            *(float2*)(C + (size_t)(row0 + 8) * ldc + col) = make_float2(v2, v3);
        }
    }
}

// ======== mega_qkv2: KV-proj + Q-proj (direct qu/qv) + rk-proj (direct rkc) =====
// grid (16, 44): by<32 KV; 32<=by<40 Q (id=(by-32)*16+bx); 40<=by<44 rk.
__global__ void __launch_bounds__(128) mega_qkv2(
    const float* __restrict__ memsl, const float* __restrict__ h,
    const float* __restrict__ r,
    const float* __restrict__ Wq, const float* __restrict__ Wr,
    const float* __restrict__ u, const float* __restrict__ v,
    float* __restrict__ heads, float* __restrict__ qu, float* __restrict__ qv,
    float* __restrict__ rkc)
{
    extern __shared__ uint32_t dsm[];
    const uint32_t sbase = smem_u32(dsm);
    const int tid = threadIdx.x, lane = tid & 31;
    const int warp = tid >> 5, wm = warp >> 1, wn = warp & 1;
    const int bx = blockIdx.x, by = blockIdx.y;

    // section: 0 = KV, 1 = Q, 2 = rk
    int section;
    const float* Ablk; const float* B;
    int ldb, colbase, rowbase;
    if (by < 32) {
        section = 0;
        Ablk = (by < 16) ? memsl + (size_t)by * 128 * 1024
                         : h + (size_t)(by - 16) * 128 * 1024;
        B = Wq + 1024; ldb = 3072;
        colbase = bx * 128; rowbase = by * 128;
    } else if (by < 40) {
        section = 1;
        int id = (by - 32) * 16 + bx;
        int qby = id >> 3, qbx = id & 7;
        Ablk = h + (size_t)qby * 128 * 1024;
        B = Wq; ldb = 3072;
        colbase = qbx * 128; rowbase = qby * 128;
    } else {
        section = 2;
        int id = (by - 40) * 16 + bx;
        int rby = id >> 3, rbx = id & 7;
        Ablk = r + (size_t)rby * 128 * 1024;
        B = Wr; ldb = 1024;
        colbase = rbx * 128; rowbase = rby * 128;
    }

    const int a_row0 = tid >> 3, a_ch = tid & 7;
    const float* Ag = Ablk + (size_t)a_row0 * 1024 + a_ch * 4;
    const int b_k = tid >> 2, b_nch0 = tid & 3;
    const float* Bg = B + (size_t)b_k * ldb + colbase + b_nch0 * 4;

    float acc[4][8][4];
#pragma unroll
    for (int mi = 0; mi < 4; mi++)
#pragma unroll
        for (int ni = 0; ni < 8; ni++)
#pragma unroll
            for (int rr = 0; rr < 4; rr++) acc[mi][ni][rr] = 0.f;

    const int lr = lane >> 2, lc = lane & 3;
    const int niter = 32;   // K=1024 for all sections

#define MQ_LOAD(stg, k0) do { \
    uint32_t ab_ = sbase + (stg) * (G4_STAGE_W * 4); \
    _Pragma("unroll") for (int i = 0; i < 8; i++) { \
        uint32_t so_ = SW128B((uint32_t)((a_row0 + 16 * i) * 128 + a_ch * 16)); \
        cpasync16(ab_ + so_, Ag + (size_t)(16 * i) * 1024 + (k0)); \
    } \
    uint32_t bb_ = ab_ + 4096 * 4; \
    _Pragma("unroll") for (int i = 0; i < 8; i++) { \
        int n_ = (b_nch0 + 4 * i) * 4; \
        uint32_t w_ = (uint32_t)(b_k * 128 + (n_ ^ ((b_k & 3) << 3))); \
        cpasync16(bb_ + w_ * 4, Bg + (size_t)(k0) * ldb + 16 * i); \
    } \
    CP_COMMIT(); \
} while (0)

    MQ_LOAD(0, 0);
    MQ_LOAD(1, 32);

    for (int it = 0; it < niter; it++) {
        if (it + 1 < niter) {
            asm volatile("cp.async.wait_group 1;" ::: "memory");
        } else {
            asm volatile("cp.async.wait_group 0;" ::: "memory");
        }
        __syncthreads();
        if (it + 2 < niter) MQ_LOAD((it + 2) % 3, (it + 2) * 32);

        const uint32_t* Abuf = dsm + (it % 3) * G4_STAGE_W;
        const uint32_t* Bbuf = Abuf + 4096;
#pragma unroll
        for (int kk = 0; kk < 4; kk++) {
            uint4 af[4]; uint2 bf[8];
#pragma unroll
            for (int mi = 0; mi < 4; mi++) {
                int row = wm * 64 + mi * 16 + lr;
                int k = kk * 8 + lc;
                af[mi].x = Abuf[SW128B((uint32_t)(row * 128 + k * 4)) >> 2];
                af[mi].y = Abuf[SW128B((uint32_t)((row + 8) * 128 + k * 4)) >> 2];
                af[mi].z = Abuf[SW128B((uint32_t)(row * 128 + (k + 4) * 4)) >> 2];
                af[mi].w = Abuf[SW128B((uint32_t)((row + 8) * 128 + (k + 4) * 4)) >> 2];
            }
#pragma unroll
            for (int ni = 0; ni < 8; ni++) {
                int n = wn * 64 + ni * 8 + lr;
                int kb = kk * 8 + lc;
                int nsw = n ^ (lc << 3);
                bf[ni].x = Bbuf[kb * 128 + nsw];
                bf[ni].y = Bbuf[(kb + 4) * 128 + nsw];
            }
#pragma unroll
            for (int mi = 0; mi < 4; mi++)
#pragma unroll
                for (int ni = 0; ni < 8; ni++) MMA_TF32(acc[mi][ni], af[mi], bf[ni]);
        }
    }
#undef MQ_LOAD

    if (section == 0) {
#pragma unroll
        for (int mi = 0; mi < 4; mi++)
#pragma unroll
            for (int ni = 0; ni < 8; ni++) {
                int row0 = rowbase + wm * 64 + mi * 16 + lr;
                int col  = colbase + wn * 64 + ni * 8 + lc * 2;
                *(float2*)(heads + 1024 + (size_t)row0 * 3072 + col) =
                    make_float2(f2tf32f(acc[mi][ni][0]), f2tf32f(acc[mi][ni][1]));
                *(float2*)(heads + 1024 + (size_t)(row0 + 8) * 3072 + col) =
                    make_float2(f2tf32f(acc[mi][ni][2]), f2tf32f(acc[mi][ni][3]));
            }
    } else if (section == 1) {
        // q -> qu/qv: row=(i*4+b), col=n*64+d; qu[((b*16+n)*512+i)*64+d]
#pragma unroll
        for (int mi = 0; mi < 4; mi++)
#pragma unroll
            for (int ni = 0; ni < 8; ni++) {
                int col = colbase + wn * 64 + ni * 8 + lc * 2;
                float uu0 = u[col], uu1 = u[col + 1];
                float vv0 = v[col], vv1 = v[col + 1];
                int n = col >> 6, d = col & 63;
#pragma unroll
                for (int hh = 0; hh < 2; hh++) {
                    int row = rowbase + wm * 64 + mi * 16 + lr + 8 * hh;
                    int i = row >> 2, b = row & 3;
                    size_t o = ((size_t)(b * 16 + n) * 512 + i) * 64 + d;
                    float a0 = acc[mi][ni][2 * hh], a1 = acc[mi][ni][2 * hh + 1];
                    *(float2*)(qu + o) = make_float2(f2tf32f(a0 + uu0), f2tf32f(a1 + uu1));
                    *(float2*)(qv + o) = make_float2(f2tf32f(a0 + vv0), f2tf32f(a1 + vv1));
                }
            }
    } else {
        // rk -> rkc[n][j][64]
#pragma unroll
        for (int mi = 0; mi < 4; mi++)
#pragma unroll
            for (int ni = 0; ni < 8; ni++) {
                int col = colbase + wn * 64 + ni * 8 + lc * 2;
                int n = col >> 6, d = col & 63;
#pragma unroll
                for (int hh = 0; hh < 2; hh++) {
                    int j = rowbase + wm * 64 + mi * 16 + lr + 8 * hh;
                    size_t o = ((size_t)n * KLEN + j) * 64 + d;
                    *(float2*)(rkc + o) =
                        make_float2(f2tf32f(acc[mi][ni][2 * hh]),
                                    f2tf32f(acc[mi][ni][2 * hh + 1]));
                }
            }
    }
}

// ======== score_both: AC (mode 0, plain store) and BD (mode 1, SHIFTED store) ====
#define SC_SMEM (4 * 4096 * 4)
__global__ void __launch_bounds__(128) score_both(
    const float* __restrict__ qu, const float* __restrict__ qv,
    const float* __restrict__ heads, const float* __restrict__ rkc,
    float* __restrict__ ac, float* __restrict__ bd)
{
    const int bx = blockIdx.x, by = blockIdx.y, z = blockIdx.z;
    const int mode = (z >= BH) ? 1 : 0;
    const int bh = mode ? z - BH : z;
    const int i0 = by * 128, j0 = bx * 128;
    if (mode == 0) { if (j0 >= i0 + 640) return; }
    else           { if (i0 + j0 < 257) return; }
    const int bb = bh >> 4, nn = bh & 15;
    const float* A = (mode ? qv : qu) + (size_t)bh * QLEN * 64 + (size_t)i0 * 64;
    const float* B;
    size_t ldbB;
    if (mode == 0) {
        B = heads + (size_t)(j0 * 4 + bb) * 3072 + 1024 + (size_t)nn * 64;
        ldbB = 4 * 3072;
    } else {
        B = rkc + (size_t)nn * KLEN * 64 + (size_t)j0 * 64;
        ldbB = 64;
    }

    extern __shared__ uint32_t dsm[];
    const uint32_t sbase = smem_u32(dsm);
    const int tid = threadIdx.x, lane = tid & 31;
    const int warp = tid >> 5, wm = warp >> 1, wn = warp & 1;

    const int a_row0 = tid >> 3, a_ch = tid & 7;
    const float* Ag = A + (size_t)a_row0 * 64 + a_ch * 4;
    const float* Bg = B + (size_t)a_row0 * ldbB + a_ch * 4;

    float acc[4][8][4];
#pragma unroll
    for (int mi = 0; mi < 4; mi++)
#pragma unroll
        for (int ni = 0; ni < 8; ni++)
#pragma unroll
            for (int r = 0; r < 4; r++) acc[mi][ni][r] = 0.f;

    const int lr = lane >> 2, lc = lane & 3;

#define SC_LOAD(stg, k0) do { \
    uint32_t ab_ = sbase + (stg) * 32768; \
    uint32_t bb_ = ab_ + 16384; \
    _Pragma("unroll") for (int i = 0; i < 8; i++) { \
        uint32_t so_ = SW128B((uint32_t)((a_row0 + 16 * i) * 128 + a_ch * 16)); \
        cpasync16(ab_ + so_, Ag + (size_t)(16 * i) * 64 + (k0)); \
        cpasync16(bb_ + so_, Bg + (size_t)(16 * i) * ldbB + (k0)); \
    } \
    CP_COMMIT(); \
} while (0)

    SC_LOAD(0, 0);
    SC_LOAD(1, 32);

#pragma unroll
    for (int it = 0; it < 2; it++) {
        if (it == 0) asm volatile("cp.async.wait_group 1;" ::: "memory");
        else         asm volatile("cp.async.wait_group 0;" ::: "memory");
        __syncthreads();
        const uint32_t* Abuf = dsm + it * 8192;
        const uint32_t* Bbuf = Abuf + 4096;
#pragma unroll
        for (int kk = 0; kk < 4; kk++) {
            uint4 af[4]; uint2 bf[8];
#pragma unroll
            for (int mi = 0; mi < 4; mi++) {
                int row = wm * 64 + mi * 16 + lr;
                int k = kk * 8 + lc;
                af[mi].x = Abuf[SW128B((uint32_t)(row * 128 + k * 4)) >> 2];
                af[mi].y = Abuf[SW128B((uint32_t)((row + 8) * 128 + k * 4)) >> 2];
                af[mi].z = Abuf[SW128B((uint32_t)(row * 128 + (k + 4) * 4)) >> 2];
                af[mi].w = Abuf[SW128B((uint32_t)((row + 8) * 128 + (k + 4) * 4)) >> 2];
            }
#pragma unroll
            for (int ni = 0; ni < 8; ni++) {
                int n = wn * 64 + ni * 8 + lr;
                int k = kk * 8 + lc;
                bf[ni].x = Bbuf[SW128B((uint32_t)(n * 128 + k * 4)) >> 2];
                bf[ni].y = Bbuf[SW128B((uint32_t)(n * 128 + (k + 4) * 4)) >> 2];
            }
#pragma unroll
            for (int mi = 0; mi < 4; mi++)
#pragma unroll
                for (int ni = 0; ni < 8; ni++) MMA_TF32(acc[mi][ni], af[mi], bf[ni]);
        }
    }
#undef SC_LOAD

    if (mode == 0) {
        float* ob = ac + (size_t)bh * QLEN * KLEN;
#pragma unroll
        for (int mi = 0; mi < 4; mi++)
#pragma unroll
            for (int ni = 0; ni < 8; ni++) {
                int row0 = i0 + wm * 64 + mi * 16 + lr;
                int col  = j0 + wn * 64 + ni * 8 + lc * 2;
                *(float2*)(ob + (size_t)row0 * KLEN + col) =
                    make_float2(acc[mi][ni][0], acc[mi][ni][1]);
                *(float2*)(ob + (size_t)(row0 + 8) * KLEN + col) =
                    make_float2(acc[mi][ni][2], acc[mi][ni][3]);
            }
    } else {
        float* ob = bd + (size_t)bh * QLEN * KLEN;
#pragma unroll
        for (int mi = 0; mi < 4; mi++)
#pragma unroll
            for (int ni = 0; ni < 8; ni++) {
                int r0 = i0 + wm * 64 + mi * 16 + lr;
                int r1 = r0 + 8;
                int c0 = j0 + wn * 64 + ni * 8 + lc * 2;
                int jp;
                jp = c0 + r0 - 511;
                if (jp >= 0) ob[(size_t)r0 * KLEN + jp] = acc[mi][ni][0];
                jp = c0 + 1 + r0 - 511;
                if (jp >= 0) ob[(size_t)r0 * KLEN + jp] = acc[mi][ni][1];
                jp = c0 + r1 - 511;
                if (jp >= 0) ob[(size_t)r1 * KLEN + jp] = acc[mi][ni][2];
                jp = c0 + 1 + r1 - 511;
                if (jp >= 0) ob[(size_t)r1 * KLEN + jp] = acc[mi][ni][3];
            }
    }
}

// ======== av3: fused (softmax no-max) + P@V ========
#define AV3_STAGE_W 10240
#define AV3_SMEM (2 * AV3_STAGE_W * 4)
__global__ void __launch_bounds__(128) av3(
    const float* __restrict__ ac, const float* __restrict__ bd,
    const float* __restrict__ heads, float* __restrict__ av)
{
    extern __shared__ uint32_t dsm[];
    const uint32_t sbase = smem_u32(dsm);
    const int by = blockIdx.x, bh = blockIdx.y;
    const int b = bh >> 4, n_h = bh & 15;
    const float* acb = ac + (size_t)bh * QLEN * KLEN + (size_t)by * 128 * KLEN;
    const float* bdb = bd + (size_t)bh * QLEN * KLEN + (size_t)by * 128 * KLEN;
    const float* Vb = heads + (size_t)b * 3072 + 2048 + (size_t)n_h * 64;
    const size_t ldv = 4 * 3072;
    const int kmax = min(KLEN, by * 128 + 640);

    const int tid = threadIdx.x, lane = tid & 31;
    const int warp = tid >> 5, wm = warp >> 1, wn = warp & 1;
    const int lr = lane >> 2, lc = lane & 3;

    const int a_row0 = tid >> 3, a_ch = tid & 7;
    const float* Acg = acb + (size_t)a_row0 * KLEN + a_ch * 4;
    const float* Bdg = bdb + (size_t)a_row0 * KLEN + a_ch * 4;
    const int b_k = tid >> 2, b_nch0 = tid & 3;
    const float* Bg = Vb + (size_t)b_k * ldv + b_nch0 * 4;

    float acc[4][4][4];
#pragma unroll
    for (int mi = 0; mi < 4; mi++)
#pragma unroll
        for (int ni = 0; ni < 4; ni++)
#pragma unroll
            for (int r = 0; r < 4; r++) acc[mi][ni][r] = 0.f;
    float lsum[4][2];
#pragma unroll
    for (int mi = 0; mi < 4; mi++) { lsum[mi][0] = 0.f; lsum[mi][1] = 0.f; }

    int jm[4][2];
#pragma unroll
    for (int mi = 0; mi < 4; mi++)
#pragma unroll
        for (int h = 0; h < 2; h++)
            jm[mi][h] = by * 128 + wm * 64 + mi * 16 + lr + 8 * h + 512;

    const int niter = kmax >> 5;

#define AV3_LOAD(stg, k0) do { \
    uint32_t base_ = sbase + (stg) * (AV3_STAGE_W * 4); \
    _Pragma("unroll") for (int i = 0; i < 8; i++) { \
        uint32_t so_ = SW128B((uint32_t)((a_row0 + 16 * i) * 128 + a_ch * 16)); \
        cpasync16(base_ + so_, Acg + (size_t)(16 * i) * KLEN + (k0)); \
        cpasync16(base_ + 16384 + so_, Bdg + (size_t)(16 * i) * KLEN + (k0)); \
    } \
    _Pragma("unroll") for (int i = 0; i < 4; i++) { \
        int n_ = (b_nch0 + 4 * i) * 4; \
        uint32_t w_ = (uint32_t)(b_k * 64 + (n_ ^ ((b_k & 3) << 3))); \
        cpasync16(base_ + 32768 + w_ * 4, Bg + (size_t)(k0) * ldv + 16 * i); \
    } \
    CP_COMMIT(); \
} while (0)

    AV3_LOAD(0, 0);
    if (niter > 1) AV3_LOAD(1, 32);

    for (int it = 0; it < niter; it++) {
        if (it + 1 < niter) {
            asm volatile("cp.async.wait_group 1;" ::: "memory");
        } else {
            asm volatile("cp.async.wait_group 0;" ::: "memory");
        }
        __syncthreads();

        const uint32_t* Sac = dsm + (it & 1) * AV3_STAGE_W;
        const uint32_t* Sbd = Sac + 4096;
        const uint32_t* Sv  = Sac + 8192;
        const int jb = it * 32;
#pragma unroll
        for (int kk = 0; kk < 4; kk++) {
            const int j1 = jb + kk * 8 + lc;
            const int j2 = j1 + 4;
            uint4 af[4];
#pragma unroll
            for (int mi = 0; mi < 4; mi++) {
                int row = wm * 64 + mi * 16 + lr;
                int k = kk * 8 + lc;
                uint32_t o00 = SW128B((uint32_t)(row * 128 + k * 4)) >> 2;
                uint32_t o10 = SW128B((uint32_t)((row + 8) * 128 + k * 4)) >> 2;
                uint32_t o01 = SW128B((uint32_t)(row * 128 + (k + 4) * 4)) >> 2;
                uint32_t o11 = SW128B((uint32_t)((row + 8) * 128 + (k + 4) * 4)) >> 2;
                float sx = 0.125f * (__uint_as_float(Sac[o00]) + __uint_as_float(Sbd[o00]));
                float sy = 0.125f * (__uint_as_float(Sac[o10]) + __uint_as_float(Sbd[o10]));
                float sz = 0.125f * (__uint_as_float(Sac[o01]) + __uint_as_float(Sbd[o01]));
                float sw = 0.125f * (__uint_as_float(Sac[o11]) + __uint_as_float(Sbd[o11]));
                float px = (j1 <= jm[mi][0]) ? __expf(sx) : 0.f;
                float py = (j1 <= jm[mi][1]) ? __expf(sy) : 0.f;
                float pz = (j2 <= jm[mi][0]) ? __expf(sz) : 0.f;
                float pw = (j2 <= jm[mi][1]) ? __expf(sw) : 0.f;
                uint32_t rx = f2tf32(px), ry = f2tf32(py);
                uint32_t rz = f2tf32(pz), rw = f2tf32(pw);
                lsum[mi][0] += __uint_as_float(rx) + __uint_as_float(rz);
                lsum[mi][1] += __uint_as_float(ry) + __uint_as_float(rw);
                af[mi].x = rx; af[mi].y = ry; af[mi].z = rz; af[mi].w = rw;
            }
            uint2 bf[4];
#pragma unroll
            for (int ni = 0; ni < 4; ni++) {
                int n = wn * 32 + ni * 8 + lr;
                int kb = kk * 8 + lc;
                int nsw = n ^ (lc << 3);
                bf[ni].x = Sv[kb * 64 + nsw];
                bf[ni].y = Sv[(kb + 4) * 64 + nsw];
            }
#pragma unroll
            for (int mi = 0; mi < 4; mi++)
#pragma unroll
                for (int ni = 0; ni < 4; ni++) MMA_TF32(acc[mi][ni], af[mi], bf[ni]);
        }
        __syncthreads();
        if (it + 2 < niter) AV3_LOAD(it & 1, (it + 2) * 32);
    }
#undef AV3_LOAD

    float inv[4][2];
#pragma unroll
    for (int mi = 0; mi < 4; mi++)
#pragma unroll
        for (int h = 0; h < 2; h++) {
            float l = lsum[mi][h];
            l += __shfl_xor_sync(0xFFFFFFFF, l, 1);
            l += __shfl_xor_sync(0xFFFFFFFF, l, 2);
            inv[mi][h] = 1.0f / l;
        }

#pragma unroll
    for (int mi = 0; mi < 4; mi++)
#pragma unroll
        for (int ni = 0; ni < 4; ni++) {
            int row0 = by * 128 + wm * 64 + mi * 16 + lr;
            int col  = wn * 32 + ni * 8 + lc * 2;
            *(float2*)(av + ((size_t)row0 * 4 + b) * 1024 + n_h * 64 + col) =
                make_float2(f2tf32f(acc[mi][ni][0] * inv[mi][0]),
                            f2tf32f(acc[mi][ni][1] * inv[mi][0]));
            *(float2*)(av + ((size_t)(row0 + 8) * 4 + b) * 1024 + n_h * 64 + col) =
                make_float2(f2tf32f(acc[mi][ni][2] * inv[mi][1]),
                            f2tf32f(acc[mi][ni][3] * inv[mi][1]));
        }
}

// ---------------- fused weight rounding ----------------
__global__ void roundw5_kernel(
    float4* d0, const float4* s0, size_t n0,
    float4* d1, const float4* s1, size_t n1,
    float4* d2, const float4* s2, size_t n2,
    float4* d3, const float4* s3, size_t n3,
    float4* d4, const float4* s4, size_t n4)
{
    size_t i = (size_t)blockIdx.x * 256 + threadIdx.x;
    float4* d; const float4* s;
    if (i < n0) { d = d0; s = s0; }
    else { i -= n0;
    if (i < n1) { d = d1; s = s1; }
    else { i -= n1;
    if (i < n2) { d = d2; s = s2; }
    else { i -= n2;
    if (i < n3) { d = d3; s = s3; }
    else { i -= n3;
    if (i < n4) { d = d4; s = s4; }
    else return; }}}}
    float4 v = s[i];
    d[i] = make_float4(f2tf32f(v.x), f2tf32f(v.y), f2tf32f(v.z), f2tf32f(v.w));
}

__global__ void roundcp_kernel(float4* __restrict__ dst, const float4* __restrict__ src) {
    size_t i = (size_t)blockIdx.x * 256 + threadIdx.x;
    float4 v = src[i];
    dst[i] = make_float4(f2tf32f(v.x), f2tf32f(v.y), f2tf32f(v.z), f2tf32f(v.w));
}

// ---------------- small kernels ----------------
__global__ void posemb_kernel(float* __restrict__ r) {
    int idx = blockIdx.x * 256 + threadIdx.x;
    int k = idx >> 10, d = idx & 1023;
    float pos = (float)(KLEN - 1 - k);
    int j = (d < 512) ? d : d - 512;
    float inv = expf(-((float)(2 * j) / 1024.0f) * 9.210340371976184f);
    float ang = pos * inv;
    r[idx] = f2tf32f((d < 512) ? sinf(ang) : cosf(ang));
}

// ---------------- residual + 2 partials + LayerNorm (output rounded) ----------------
__global__ void __launch_bounds__(256) add_ln3_kernel(
    float* __restrict__ h, const float* __restrict__ t0, const float* __restrict__ t1,
    const float* __restrict__ g, const float* __restrict__ b)
{
    int row = blockIdx.x;
    int tid = threadIdx.x;
    __shared__ float rs[256], rs2[256];
    float x[4];
    float s = 0.f, ss = 0.f;
#pragma unroll
    for (int c = 0; c < 4; c++) {
        int d = c * 256 + tid;
        size_t o = (size_t)row * 1024 + d;
        float v = h[o] + t0[o] + t1[o];
        x[c] = v; s += v; ss += v * v;
    }
    rs[tid] = s; rs2[tid] = ss; __syncthreads();
    for (int o = 128; o > 0; o >>= 1) {
        if (tid < o) { rs[tid] += rs[tid + o]; rs2[tid] += rs2[tid + o]; }
        __syncthreads();
    }
    float mu = rs[0] * (1.0f / 1024.0f);
    float var = rs2[0] * (1.0f / 1024.0f) - mu * mu;
    float inv = rsqrtf(var + 1e-5f);
#pragma unroll
    for (int c = 0; c < 4; c++) {
        int d = c * 256 + tid;
        h[(size_t)row * 1024 + d] = f2tf32f((x[c] - mu) * inv * g[d] + b[d]);
    }
}

// ---------------- launch ----------------
extern "C" void kernel_launch(void* const* d_in, const int* in_sizes, int n_in,
                              void* d_out, int out_size) {
    (void)in_sizes; (void)n_in; (void)out_size;
    const float* x     = (const float*)d_in[0];
    const float* mems  = (const float*)d_in[1];
    const float* u     = (const float*)d_in[2];
    const float* v     = (const float*)d_in[3];
    const float* W_qkv = (const float*)d_in[4];
    const float* W_o   = (const float*)d_in[5];
    const float* W_r   = (const float*)d_in[6];
    const float* ln1_g = (const float*)d_in[7];
    const float* ln1_b = (const float*)d_in[8];
    const float* W1    = (const float*)d_in[9];
    const float* b1    = (const float*)d_in[10];
    const float* W2    = (const float*)d_in[11];
    const float* b2    = (const float*)d_in[12];
    const float* ln2_g = (const float*)d_in[13];
    const float* ln2_b = (const float*)d_in[14];

    float *memsr, *heads, *r, *ac, *bd, *av, *tmp, *tmp2, *h, *ff, *qu, *qv, *rkc;
    float *wqkv, *wr, *wo, *w1, *w2;
    cudaGetSymbolAddress((void**)&memsr, g_memsr);
    cudaGetSymbolAddress((void**)&heads, g_heads);
    cudaGetSymbolAddress((void**)&r,     g_r);
    cudaGetSymbolAddress((void**)&ac,    g_ac);
    cudaGetSymbolAddress((void**)&bd,    g_bd);
    cudaGetSymbolAddress((void**)&av,    g_av);
    cudaGetSymbolAddress((void**)&tmp,   g_tmp);
    cudaGetSymbolAddress((void**)&tmp2,  g_tmp2);
    cudaGetSymbolAddress((void**)&h,     g_h);
    cudaGetSymbolAddress((void**)&ff,    g_ff);
    cudaGetSymbolAddress((void**)&qu,    g_qu);
    cudaGetSymbolAddress((void**)&qv,    g_qv);
    cudaGetSymbolAddress((void**)&rkc,   g_rkc);
    cudaGetSymbolAddress((void**)&wqkv,  g_wqkv);
    cudaGetSymbolAddress((void**)&wr,    g_wr);
    cudaGetSymbolAddress((void**)&wo,    g_wo);
    cudaGetSymbolAddress((void**)&w1,    g_w1);
    cudaGetSymbolAddress((void**)&w2,    g_w2);

    cudaFuncSetAttribute(gemm4<0,0,0>, cudaFuncAttributeMaxDynamicSharedMemorySize, G4_SMEM);
    cudaFuncSetAttribute(gemm4<1,1,1>, cudaFuncAttributeMaxDynamicSharedMemorySize, G4_SMEM);
    cudaFuncSetAttribute(gemm4<0,1,0>, cudaFuncAttributeMaxDynamicSharedMemorySize, G4_SMEM);
    cudaFuncSetAttribute(mega_qkv2,    cudaFuncAttributeMaxDynamicSharedMemorySize, G4_SMEM);
    cudaFuncSetAttribute(score_both,   cudaFuncAttributeMaxDynamicSharedMemorySize, SC_SMEM);
    cudaFuncSetAttribute(av3,          cudaFuncAttributeMaxDynamicSharedMemorySize, AV3_SMEM);

    // one-time weight rounding + mems rounding + x->h
    {
        size_t n0 = (size_t)NLAYER*DMODEL*3072/4, n1 = (size_t)NLAYER*DMODEL*DMODEL/4;
        size_t n2 = n1, n3 = (size_t)NLAYER*DMODEL*DINNER/4, n4 = n3;
        size_t ntot = n0 + n1 + n2 + n3 + n4;
        roundw5_kernel<<<(unsigned)((ntot + 255) / 256), 256>>>(
            (float4*)wqkv, (const float4*)W_qkv, n0,
            (float4*)wr,   (const float4*)W_r,   n1,
            (float4*)wo,   (const float4*)W_o,   n2,
            (float4*)w1,   (const float4*)W1,    n3,
            (float4*)w2,   (const float4*)W2,    n4);
    }
    roundcp_kernel<<<(NLAYER*MLEN*BATCH*DMODEL/4)/256, 256>>>(
        (float4*)memsr, (const float4*)mems);
    roundcp_kernel<<<(QLEN*BATCH*DMODEL/4)/256, 256>>>((float4*)h, (const float4*)x);
    posemb_kernel<<<4096, 256>>>(r);

    for (int l = 0; l < NLAYER; l++) {
        const float* Wq = wqkv + (size_t)l * DMODEL * 3072;
        // KV + Q (direct qu/qv) + rk (direct rkc), one dense launch
        mega_qkv2<<<dim3(16, 44), 128, G4_SMEM>>>(
            memsr + (size_t)l * MLEN * BATCH * DMODEL, h, r,
            Wq, wr + (size_t)l * DMODEL * DMODEL, u, v,
            heads, qu, qv, rkc);
        // scores: AC plain + BD shifted, one launch
        score_both<<<dim3(8, 4, 2 * BH), 128, SC_SMEM>>>(qu, qv, heads, rkc, ac, bd);
        // fused softmax + P@V
        av3<<<dim3(4, BH), 128, AV3_SMEM>>>(ac, bd, heads, av);
        // O projection: split-K=2
        gemm4<0,0,0><<<dim3(8, 16, 2), 128, G4_SMEM>>>(
            av, wo + (size_t)l * DMODEL * DMODEL, nullptr, tmp, tmp2,
            512, 1024, 1024, 1024);
        add_ln3_kernel<<<2048, 256>>>(h, tmp, tmp2,
                                      ln1_g + (size_t)l * DMODEL, ln1_b + (size_t)l * DMODEL);
        // FFN
        gemm4<1,1,1><<<dim3(32, 16, 1), 128, G4_SMEM>>>(
            h, w1 + (size_t)l * DMODEL * DINNER, b1 + (size_t)l * DINNER, ff, nullptr,
            1024, 1024, 4096, 4096);
        gemm4<0,1,0><<<dim3(8, 16, 2), 128, G4_SMEM>>>(
            ff, w2 + (size_t)l * DINNER * DMODEL, b2 + (size_t)l * DMODEL, tmp, tmp2,
            2048, 4096, 1024, 1024);
        add_ln3_kernel<<<2048, 256>>>(h, tmp, tmp2,
                                      ln2_g + (size_t)l * DMODEL, ln2_b + (size_t)l * DMODEL);
    }

    cudaMemcpyAsync(d_out, h, (size_t)QLEN * BATCH * DMODEL * sizeof(float),
                    cudaMemcpyDeviceToDevice);
}